// round 3
// baseline (speedup 1.0000x reference)
#include <cuda_runtime.h>
#include <math.h>
#include <stdint.h>

#define SEQ 2048
#define BATCH 2
#define ROWS (BATCH*SEQ)   // 4096
#define NHEADS 16
#define QHD 192
#define NOPE 128
#define ROPE_D 64
#define VHD 128

// ---------------- scratch (device globals; no allocation allowed) ----------------
__device__ float g_qlora[(size_t)ROWS*1536];
__device__ float g_q[(size_t)ROWS*3072];
__device__ float g_ckv[(size_t)ROWS*576];
__device__ float g_cnorm[(size_t)ROWS*512];
__device__ float g_kv[(size_t)ROWS*4096];
__device__ float g_kpe[(size_t)ROWS*64];
__device__ float g_attn[(size_t)ROWS*2048];

// ==================================================================
// TF32 tensor-core GEMM: C[M,N] = A[M,K] @ B[N,K]^T
// Block tile 128x128, BK=16, 256 threads (8 warps as 4x2),
// warp tile 32x64 (2 m16-tiles x 8 n8-tiles), mma.m16n8k8.tf32.
// A,B fp32 in gmem; converted to tf32 (cvt.rna) at smem staging.
// M must be a multiple of 128 and K a multiple of 16 (true for all
// calls here); N is handled with guards (for N=576).
// ==================================================================
#define GBM 128
#define GBN 128
#define GBK 16
#define GP 132   // smem pitch (k-major: [16][132])

__device__ __forceinline__ uint32_t f2tf32(float f) {
    uint32_t u;
    asm("cvt.rna.tf32.f32 %0, %1;" : "=r"(u) : "f"(f));
    return u;
}

__device__ __forceinline__ void mma_tf32(float d[4], const uint32_t a[4],
                                         const uint32_t b[2]) {
    asm volatile(
        "mma.sync.aligned.m16n8k8.row.col.f32.tf32.tf32.f32 "
        "{%0,%1,%2,%3}, {%4,%5,%6,%7}, {%8,%9}, {%0,%1,%2,%3};"
        : "+f"(d[0]), "+f"(d[1]), "+f"(d[2]), "+f"(d[3])
        : "r"(a[0]), "r"(a[1]), "r"(a[2]), "r"(a[3]), "r"(b[0]), "r"(b[1]));
}

__global__ __launch_bounds__(256) void gemm_tf32(const float* __restrict__ A,
                                                 const float* __restrict__ B,
                                                 float* __restrict__ C,
                                                 int M, int N, int K) {
    __shared__ uint32_t As[2][GBK][GP];
    __shared__ uint32_t Bs[2][GBK][GP];
    const int tid = threadIdx.x;
    const int warp = tid >> 5, lane = tid & 31;
    const int wm = (warp & 3) * 32;      // warp row base within block tile
    const int wn = (warp >> 2) * 64;     // warp col base within block tile
    const int g  = lane >> 2;            // groupID 0..7
    const int tl = lane & 3;             // thread-in-group 0..3
    const int m0 = blockIdx.y * GBM, n0 = blockIdx.x * GBN;
    // global->smem staging mapping: each thread loads 2 float4 of A and B
    const int ar  = tid >> 2;            // row within tile 0..63 (and +64)
    const int akq = (tid & 3) * 4;       // k offset 0,4,8,12

    float4 ra0, ra1, rb0, rb1;
    float acc[2][8][4];
    #pragma unroll
    for (int i = 0; i < 2; i++)
        #pragma unroll
        for (int j = 0; j < 8; j++)
            #pragma unroll
            for (int v = 0; v < 4; v++) acc[i][j][v] = 0.f;

    const float4 z4 = make_float4(0.f, 0.f, 0.f, 0.f);

    // ---- prologue: tile 0 ----
    {
        ra0 = *(const float4*)&A[(size_t)(m0 + ar) * K + akq];
        ra1 = *(const float4*)&A[(size_t)(m0 + ar + 64) * K + akq];
        int nr0 = n0 + ar, nr1 = n0 + ar + 64;
        rb0 = (nr0 < N) ? *(const float4*)&B[(size_t)nr0 * K + akq] : z4;
        rb1 = (nr1 < N) ? *(const float4*)&B[(size_t)nr1 * K + akq] : z4;
        float av0[4] = {ra0.x, ra0.y, ra0.z, ra0.w};
        float av1[4] = {ra1.x, ra1.y, ra1.z, ra1.w};
        float bv0[4] = {rb0.x, rb0.y, rb0.z, rb0.w};
        float bv1[4] = {rb1.x, rb1.y, rb1.z, rb1.w};
        #pragma unroll
        for (int j = 0; j < 4; j++) {
            As[0][akq + j][ar]      = f2tf32(av0[j]);
            As[0][akq + j][ar + 64] = f2tf32(av1[j]);
            Bs[0][akq + j][ar]      = f2tf32(bv0[j]);
            Bs[0][akq + j][ar + 64] = f2tf32(bv1[j]);
        }
    }
    __syncthreads();

    const int T = K / GBK;
    for (int t = 0; t < T; t++) {
        const int buf = t & 1;
        // prefetch next tile into registers
        if (t + 1 < T) {
            int k0 = (t + 1) * GBK;
            ra0 = *(const float4*)&A[(size_t)(m0 + ar) * K + k0 + akq];
            ra1 = *(const float4*)&A[(size_t)(m0 + ar + 64) * K + k0 + akq];
            int nr0 = n0 + ar, nr1 = n0 + ar + 64;
            rb0 = (nr0 < N) ? *(const float4*)&B[(size_t)nr0 * K + k0 + akq] : z4;
            rb1 = (nr1 < N) ? *(const float4*)&B[(size_t)nr1 * K + k0 + akq] : z4;
        }
        // compute 2 k-steps of 8
        #pragma unroll
        for (int ks = 0; ks < 2; ks++) {
            const int kb = ks * 8;
            uint32_t afr[2][4], bfr[8][2];
            #pragma unroll
            for (int mt = 0; mt < 2; mt++) {
                int rb_ = wm + mt * 16 + g;
                afr[mt][0] = As[buf][kb + tl][rb_];
                afr[mt][1] = As[buf][kb + tl][rb_ + 8];
                afr[mt][2] = As[buf][kb + tl + 4][rb_];
                afr[mt][3] = As[buf][kb + tl + 4][rb_ + 8];
            }
            #pragma unroll
            for (int nt = 0; nt < 8; nt++) {
                int cb = wn + nt * 8 + g;
                bfr[nt][0] = Bs[buf][kb + tl][cb];
                bfr[nt][1] = Bs[buf][kb + tl + 4][cb];
            }
            #pragma unroll
            for (int mt = 0; mt < 2; mt++)
                #pragma unroll
                for (int nt = 0; nt < 8; nt++)
                    mma_tf32(acc[mt][nt], afr[mt], bfr[nt]);
        }
        // stage next tile
        if (t + 1 < T) {
            const int nb = (t + 1) & 1;
            float av0[4] = {ra0.x, ra0.y, ra0.z, ra0.w};
            float av1[4] = {ra1.x, ra1.y, ra1.z, ra1.w};
            float bv0[4] = {rb0.x, rb0.y, rb0.z, rb0.w};
            float bv1[4] = {rb1.x, rb1.y, rb1.z, rb1.w};
            #pragma unroll
            for (int j = 0; j < 4; j++) {
                As[nb][akq + j][ar]      = f2tf32(av0[j]);
                As[nb][akq + j][ar + 64] = f2tf32(av1[j]);
                Bs[nb][akq + j][ar]      = f2tf32(bv0[j]);
                Bs[nb][akq + j][ar + 64] = f2tf32(bv1[j]);
            }
        }
        __syncthreads();
    }

    // ---- epilogue ----
    #pragma unroll
    for (int mt = 0; mt < 2; mt++) {
        int r0 = m0 + wm + mt * 16 + g;
        #pragma unroll
        for (int nt = 0; nt < 8; nt++) {
            int cn = n0 + wn + nt * 8 + 2 * tl;
            if (cn < N) {
                float2 v0 = make_float2(acc[mt][nt][0], acc[mt][nt][1]);
                float2 v1 = make_float2(acc[mt][nt][2], acc[mt][nt][3]);
                *(float2*)&C[(size_t)r0 * N + cn]       = v0;
                *(float2*)&C[(size_t)(r0 + 8) * N + cn] = v1;
            }
        }
    }
}

// ---------------- RMSNorm: one block per row ----------------
__global__ __launch_bounds__(256) void rmsnorm_k(const float* __restrict__ X,
                                                 const float* __restrict__ w,
                                                 float* __restrict__ Y,
                                                 int W, int ldx, int ldy) {
    int row = blockIdx.x;
    const float* x = X + (size_t)row * ldx;
    float ss = 0.f;
    for (int i = threadIdx.x; i < W; i += 256) { float v = x[i]; ss += v * v; }
    __shared__ float red[256];
    red[threadIdx.x] = ss;
    __syncthreads();
    for (int s = 128; s > 0; s >>= 1) {
        if (threadIdx.x < s) red[threadIdx.x] += red[threadIdx.x + s];
        __syncthreads();
    }
    float inv = rsqrtf(red[0] / (float)W + 1e-6f);
    float* y = Y + (size_t)row * ldy;
    for (int i = threadIdx.x; i < W; i += 256) y[i] = w[i] * (x[i] * inv);
}

// ---------------- YaRN RoPE ----------------
__global__ __launch_bounds__(544) void rope_k(const int* __restrict__ pos_ids) {
    int row = blockIdx.x;
    int t = threadIdx.x;
    int h = t >> 5, j = t & 31;
    float pos = (float)pos_ids[row];
    float fe = powf(10000.0f, -(float)j / 32.0f);       // freq_extra
    float ramp = fminf(fmaxf(((float)j - 10.0f) / 13.0f, 0.f), 1.f);
    float invf = (fe / 40.0f) * ramp + fe * (1.0f - ramp);
    float ang = pos * invf;
    float s, c;
    sincosf(ang, &s, &c);
    if (h < NHEADS) {
        float* base = g_q + (size_t)row * 3072 + h * QHD + NOPE;
        float x0 = base[2 * j], x1 = base[2 * j + 1];
        __syncwarp();
        base[j]      = x0 * c - x1 * s;
        base[32 + j] = x1 * c + x0 * s;
    } else {
        const float* src = g_ckv + (size_t)row * 576 + 512;
        float x0 = src[2 * j], x1 = src[2 * j + 1];
        float* dst = g_kpe + (size_t)row * 64;
        dst[j]      = x0 * c - x1 * s;
        dst[32 + j] = x1 * c + x0 * s;
    }
}

// ---------------- Flash attention (causal, online softmax, fp32) ----------------
#define QP 193
#define VP 132
#define PP 68
#define FLASH_SMEM ((64*QP*2 + 64*VP + 64*PP) * 4)

__global__ __launch_bounds__(256) void flash_k(float scale) {
    extern __shared__ float sm[];
    float* Qs = sm;                    // [64][QP]
    float* Ks = Qs + 64 * QP;          // [64][QP]
    float* Vs = Ks + 64 * QP;          // [64][VP]
    float* Ps = Vs + 64 * VP;          // [64][PP]
    const int qb = blockIdx.x, h = blockIdx.y, b = blockIdx.z;
    const int tid = threadIdx.x;
    const int tx = tid & 15, ty = tid >> 4;
    const size_t bs0 = (size_t)b * SEQ;

    for (int idx = tid; idx < 64 * 192; idx += 256) {
        int r = idx / 192, c = idx - r * 192;
        Qs[r * QP + c] = g_q[(bs0 + qb * 64 + r) * 3072 + h * QHD + c];
    }
    float m_i[4], l_i[4], o[4][8];
    #pragma unroll
    for (int i = 0; i < 4; i++) {
        m_i[i] = -1e30f; l_i[i] = 0.f;
        #pragma unroll
        for (int j = 0; j < 8; j++) o[i][j] = 0.f;
    }
    __syncthreads();

    for (int kb = 0; kb <= qb; kb++) {
        for (int idx = tid; idx < 64 * 192; idx += 256) {
            int r = idx / 192, c = idx - r * 192;
            int sk = kb * 64 + r;
            float v;
            if (c < NOPE) v = g_kv[(bs0 + sk) * 4096 + h * 256 + c];
            else          v = g_kpe[(bs0 + sk) * 64 + (c - NOPE)];
            Ks[r * QP + c] = v;
        }
        for (int idx = tid; idx < 64 * 128; idx += 256) {
            int r = idx >> 7, c = idx & 127;
            Vs[r * VP + c] = g_kv[(bs0 + kb * 64 + r) * 4096 + h * 256 + NOPE + c];
        }
        __syncthreads();

        float acc[4][4] = {};
        for (int kk = 0; kk < 192; kk++) {
            float av[4], bv[4];
            #pragma unroll
            for (int i = 0; i < 4; i++) av[i] = Qs[(ty * 4 + i) * QP + kk];
            #pragma unroll
            for (int j = 0; j < 4; j++) bv[j] = Ks[(tx * 4 + j) * QP + kk];
            #pragma unroll
            for (int i = 0; i < 4; i++)
                #pragma unroll
                for (int j = 0; j < 4; j++)
                    acc[i][j] += av[i] * bv[j];
        }

        bool diag = (kb == qb);
        #pragma unroll
        for (int i = 0; i < 4; i++) {
            int qi = qb * 64 + ty * 4 + i;
            float rm = -1e30f;
            #pragma unroll
            for (int j = 0; j < 4; j++) {
                float sv = acc[i][j] * scale;
                if (diag && (kb * 64 + tx * 4 + j > qi)) sv = -1e30f;
                acc[i][j] = sv;
                rm = fmaxf(rm, sv);
            }
            #pragma unroll
            for (int off = 8; off > 0; off >>= 1)
                rm = fmaxf(rm, __shfl_xor_sync(0xffffffffu, rm, off));
            float mnew = fmaxf(m_i[i], rm);
            float alpha = __expf(m_i[i] - mnew);
            float rs = 0.f;
            #pragma unroll
            for (int j = 0; j < 4; j++) {
                float p = __expf(acc[i][j] - mnew);
                Ps[(ty * 4 + i) * PP + tx * 4 + j] = p;
                rs += p;
            }
            #pragma unroll
            for (int off = 8; off > 0; off >>= 1)
                rs += __shfl_xor_sync(0xffffffffu, rs, off);
            l_i[i] = l_i[i] * alpha + rs;
            m_i[i] = mnew;
            #pragma unroll
            for (int j = 0; j < 8; j++) o[i][j] *= alpha;
        }
        __syncthreads();

        for (int kk = 0; kk < 64; kk++) {
            float pv[4];
            #pragma unroll
            for (int i = 0; i < 4; i++) pv[i] = Ps[(ty * 4 + i) * PP + kk];
            float4 v0 = *(const float4*)&Vs[kk * VP + tx * 8];
            float4 v1 = *(const float4*)&Vs[kk * VP + tx * 8 + 4];
            float vv[8] = {v0.x, v0.y, v0.z, v0.w, v1.x, v1.y, v1.z, v1.w};
            #pragma unroll
            for (int i = 0; i < 4; i++)
                #pragma unroll
                for (int j = 0; j < 8; j++)
                    o[i][j] += pv[i] * vv[j];
        }
        __syncthreads();
    }

    #pragma unroll
    for (int i = 0; i < 4; i++) {
        float invl = 1.0f / l_i[i];
        #pragma unroll
        for (int j = 0; j < 8; j++)
            g_attn[(bs0 + qb * 64 + ty * 4 + i) * 2048 + h * VHD + tx * 8 + j] =
                o[i][j] * invl;
    }
}

// ---------------- launch ----------------
extern "C" void kernel_launch(void* const* d_in, const int* in_sizes, int n_in,
                              void* d_out, int out_size) {
    const float* hs      = (const float*)d_in[0];
    const int*   pos     = (const int*)  d_in[1];
    const float* wq_a    = (const float*)d_in[2];
    const float* q_a_ln  = (const float*)d_in[3];
    const float* wq_b    = (const float*)d_in[4];
    const float* wkv_a   = (const float*)d_in[5];
    const float* kv_a_ln = (const float*)d_in[6];
    const float* wkv_b   = (const float*)d_in[7];
    const float* wo      = (const float*)d_in[8];
    float* out = (float*)d_out;

    float *qlora, *q, *ckv, *cnorm, *kv, *kpe, *attn;
    cudaGetSymbolAddress((void**)&qlora, g_qlora);
    cudaGetSymbolAddress((void**)&q,     g_q);
    cudaGetSymbolAddress((void**)&ckv,   g_ckv);
    cudaGetSymbolAddress((void**)&cnorm, g_cnorm);
    cudaGetSymbolAddress((void**)&kv,    g_kv);
    cudaGetSymbolAddress((void**)&kpe,   g_kpe);
    cudaGetSymbolAddress((void**)&attn,  g_attn);

    // softmax scale: 192^-0.5 * m^2, m = 0.1*ln(40) + 1
    double m = 0.1 * log(40.0) + 1.0;
    float scale = (float)((1.0 / sqrt(192.0)) * m * m);

    cudaFuncSetAttribute(flash_k, cudaFuncAttributeMaxDynamicSharedMemorySize,
                         FLASH_SMEM);

    dim3 blk(256);
    // q_lora = hs @ wq_a^T            [4096,1536] = [4096,2048]x[1536,2048]^T
    gemm_tf32<<<dim3(1536 / 128, ROWS / 128), blk>>>(hs, wq_a, qlora, ROWS, 1536, 2048);
    // rmsnorm in-place over 1536
    rmsnorm_k<<<ROWS, 256>>>(qlora, q_a_ln, qlora, 1536, 1536, 1536);
    // q = qlora_n @ wq_b^T            [4096,3072]
    gemm_tf32<<<dim3(3072 / 128, ROWS / 128), blk>>>(qlora, wq_b, q, ROWS, 3072, 1536);
    // ckv = hs @ wkv_a^T              [4096,576] (N not mult of 128 -> guarded)
    gemm_tf32<<<dim3((576 + 127) / 128, ROWS / 128), blk>>>(hs, wkv_a, ckv, ROWS, 576, 2048);
    // rmsnorm(compressed[...,:512]) -> cnorm
    rmsnorm_k<<<ROWS, 256>>>(ckv, kv_a_ln, cnorm, 512, 576, 512);
    // kv = cnorm @ wkv_b^T            [4096,4096]
    gemm_tf32<<<dim3(4096 / 128, ROWS / 128), blk>>>(cnorm, wkv_b, kv, ROWS, 4096, 512);
    // rope: q_pe in place, k_pe -> g_kpe
    rope_k<<<ROWS, 544>>>(pos);
    // causal flash attention -> g_attn [rows, heads*128]
    flash_k<<<dim3(SEQ / 64, NHEADS, BATCH), 256, FLASH_SMEM>>>(scale);
    // out = attn @ wo^T               [4096,2048]
    gemm_tf32<<<dim3(2048 / 128, ROWS / 128), blk>>>(attn, wo, out, ROWS, 2048, 2048);
}

// round 4
// speedup vs baseline: 1.6840x; 1.6840x over previous
#include <cuda_runtime.h>
#include <math.h>
#include <stdint.h>

#define SEQ 2048
#define BATCH 2
#define ROWS (BATCH*SEQ)   // 4096
#define NHEADS 16
#define QHD 192
#define NOPE 128
#define VHD 128

// ---------------- scratch (device globals; no allocation allowed) ----------------
__device__ float g_qlora[(size_t)ROWS*1536];
__device__ float g_q[(size_t)ROWS*3072];
__device__ float g_ckv[(size_t)ROWS*576];
__device__ float g_cnorm[(size_t)ROWS*512];
__device__ float g_kv[(size_t)ROWS*4096];
__device__ float g_kpe[(size_t)ROWS*64];
__device__ float g_attn[(size_t)ROWS*2048];
// tf32-rounded copies (inputs to tensor-core GEMMs)
__device__ float g_hs_t [(size_t)ROWS*2048];
__device__ float g_wqa_t[(size_t)1536*2048];
__device__ float g_wqb_t[(size_t)3072*1536];
__device__ float g_wkva_t[(size_t)576*2048];
__device__ float g_wkvb_t[(size_t)4096*512];
__device__ float g_wo_t [(size_t)2048*2048];

__device__ __forceinline__ uint32_t f2tf32(float f) {
    uint32_t u;
    asm("cvt.rna.tf32.f32 %0, %1;" : "=r"(u) : "f"(f));
    return u;
}
__device__ __forceinline__ float rtf(float f) { return __uint_as_float(f2tf32(f)); }

__device__ __forceinline__ void mma_tf32(float d[4], const uint32_t a[4],
                                         const uint32_t b[2]) {
    asm volatile(
        "mma.sync.aligned.m16n8k8.row.col.f32.tf32.tf32.f32 "
        "{%0,%1,%2,%3}, {%4,%5,%6,%7}, {%8,%9}, {%0,%1,%2,%3};"
        : "+f"(d[0]), "+f"(d[1]), "+f"(d[2]), "+f"(d[3])
        : "r"(a[0]), "r"(a[1]), "r"(a[2]), "r"(a[3]), "r"(b[0]), "r"(b[1]));
}

__device__ __forceinline__ void cp_async16(uint32_t saddr, const void* gptr, bool pred) {
    int sz = pred ? 16 : 0;
    asm volatile("cp.async.cg.shared.global [%0], [%1], 16, %2;\n"
                 :: "r"(saddr), "l"(gptr), "r"(sz));
}

// ---------------- elementwise tf32 rounding copy ----------------
__global__ __launch_bounds__(256) void cvt_tf32_k(const float* __restrict__ x,
                                                  float* __restrict__ y, int n) {
    int i = (blockIdx.x * 256 + threadIdx.x) * 4;
    if (i < n) {
        float4 v = *(const float4*)(x + i);
        v.x = rtf(v.x); v.y = rtf(v.y); v.z = rtf(v.z); v.w = rtf(v.w);
        *(float4*)(y + i) = v;
    }
}

// ==================================================================
// TF32 GEMM: C[M,N] = A[M,K] @ B[N,K]^T
// 128x128 tile, BK=32, 3-stage cp.async pipeline, 256 threads
// (8 warps 4x2), warp tile 32x64. A,B already tf32-rounded fp32.
// M % 128 == 0, K % 32 == 0; N guarded.
// ==================================================================
#define APITCH 36
#define TILE_F (128*APITCH)
#define GEMM_SMEM (6*TILE_F*4)   // 3 stages x 2 operands

__global__ __launch_bounds__(256, 2) void gemm_tf32(const float* __restrict__ A,
                                                    const float* __restrict__ B,
                                                    float* __restrict__ C,
                                                    int M, int N, int K) {
    extern __shared__ float sm_[];
    float* As = sm_;
    float* Bs = sm_ + 3 * TILE_F;
    const int tid = threadIdx.x;
    const int warp = tid >> 5, lane = tid & 31;
    const int wm = (warp & 3) * 32, wn = (warp >> 2) * 64;
    const int g = lane >> 2, tl = lane & 3;
    const int m0 = blockIdx.y * 128, n0 = blockIdx.x * 128;

    float acc[2][8][4];
    #pragma unroll
    for (int i = 0; i < 2; i++)
        #pragma unroll
        for (int j = 0; j < 8; j++)
            #pragma unroll
            for (int v = 0; v < 4; v++) acc[i][j][v] = 0.f;

    const int T = K / 32;

    auto issue = [&](int stage, int t) {
        const int k0 = t * 32;
        uint32_t ab = (uint32_t)__cvta_generic_to_shared(As + stage * TILE_F);
        uint32_t bb = (uint32_t)__cvta_generic_to_shared(Bs + stage * TILE_F);
        #pragma unroll
        for (int u = 0; u < 4; u++) {
            int seg = tid + u * 256;
            int row = seg >> 3, kq = (seg & 7) * 4;
            cp_async16(ab + (row * APITCH + kq) * 4,
                       A + (size_t)(m0 + row) * K + k0 + kq, true);
            int nr = n0 + row;
            cp_async16(bb + (row * APITCH + kq) * 4,
                       B + (size_t)(nr < N ? nr : 0) * K + k0 + kq, nr < N);
        }
        asm volatile("cp.async.commit_group;");
    };

    issue(0, 0);
    if (T > 1) issue(1, 1); else asm volatile("cp.async.commit_group;");

    for (int t = 0; t < T; t++) {
        asm volatile("cp.async.wait_group 1;");
        __syncthreads();
        if (t + 2 < T) issue((t + 2) % 3, t + 2);
        else asm volatile("cp.async.commit_group;");

        const float* Ab = As + (t % 3) * TILE_F;
        const float* Bb = Bs + (t % 3) * TILE_F;
        #pragma unroll
        for (int ks = 0; ks < 4; ks++) {
            const int kb = ks * 8;
            uint32_t afr[2][4], bfr[8][2];
            #pragma unroll
            for (int mt = 0; mt < 2; mt++) {
                int rb = wm + mt * 16 + g;
                afr[mt][0] = __float_as_uint(Ab[rb * APITCH + kb + tl]);
                afr[mt][1] = __float_as_uint(Ab[(rb + 8) * APITCH + kb + tl]);
                afr[mt][2] = __float_as_uint(Ab[rb * APITCH + kb + tl + 4]);
                afr[mt][3] = __float_as_uint(Ab[(rb + 8) * APITCH + kb + tl + 4]);
            }
            #pragma unroll
            for (int nt = 0; nt < 8; nt++) {
                int cb = wn + nt * 8 + g;
                bfr[nt][0] = __float_as_uint(Bb[cb * APITCH + kb + tl]);
                bfr[nt][1] = __float_as_uint(Bb[cb * APITCH + kb + tl + 4]);
            }
            #pragma unroll
            for (int mt = 0; mt < 2; mt++)
                #pragma unroll
                for (int nt = 0; nt < 8; nt++)
                    mma_tf32(acc[mt][nt], afr[mt], bfr[nt]);
        }
        __syncthreads();
    }

    #pragma unroll
    for (int mt = 0; mt < 2; mt++) {
        int r0 = m0 + wm + mt * 16 + g;
        #pragma unroll
        for (int nt = 0; nt < 8; nt++) {
            int cn = n0 + wn + nt * 8 + 2 * tl;
            if (cn < N) {
                *(float2*)&C[(size_t)r0 * N + cn] =
                    make_float2(acc[mt][nt][0], acc[mt][nt][1]);
                *(float2*)&C[(size_t)(r0 + 8) * N + cn] =
                    make_float2(acc[mt][nt][2], acc[mt][nt][3]);
            }
        }
    }
}

// ---------------- RMSNorm (writes tf32-rounded output) ----------------
__global__ __launch_bounds__(256) void rmsnorm_k(const float* __restrict__ X,
                                                 const float* __restrict__ w,
                                                 float* __restrict__ Y,
                                                 int W, int ldx, int ldy) {
    int row = blockIdx.x;
    const float* x = X + (size_t)row * ldx;
    float ss = 0.f;
    for (int i = threadIdx.x; i < W; i += 256) { float v = x[i]; ss += v * v; }
    __shared__ float red[256];
    red[threadIdx.x] = ss;
    __syncthreads();
    for (int s = 128; s > 0; s >>= 1) {
        if (threadIdx.x < s) red[threadIdx.x] += red[threadIdx.x + s];
        __syncthreads();
    }
    float inv = rsqrtf(red[0] / (float)W + 1e-6f);
    float* y = Y + (size_t)row * ldy;
    for (int i = threadIdx.x; i < W; i += 256) y[i] = rtf(w[i] * (x[i] * inv));
}

// ---------------- YaRN RoPE ----------------
__global__ __launch_bounds__(544) void rope_k(const int* __restrict__ pos_ids) {
    int row = blockIdx.x;
    int t = threadIdx.x;
    int h = t >> 5, j = t & 31;
    float pos = (float)pos_ids[row];
    float fe = powf(10000.0f, -(float)j / 32.0f);
    float ramp = fminf(fmaxf(((float)j - 10.0f) / 13.0f, 0.f), 1.f);
    float invf = (fe / 40.0f) * ramp + fe * (1.0f - ramp);
    float ang = pos * invf;
    float s, c;
    sincosf(ang, &s, &c);
    if (h < NHEADS) {
        float* base = g_q + (size_t)row * 3072 + h * QHD + NOPE;
        float x0 = base[2 * j], x1 = base[2 * j + 1];
        __syncwarp();
        base[j]      = x0 * c - x1 * s;
        base[32 + j] = x1 * c + x0 * s;
    } else {
        const float* src = g_ckv + (size_t)row * 576 + 512;
        float x0 = src[2 * j], x1 = src[2 * j + 1];
        float* dst = g_kpe + (size_t)row * 64;
        dst[j]      = x0 * c - x1 * s;
        dst[32 + j] = x1 * c + x0 * s;
    }
}

// ---------------- Flash attention (causal, online softmax, fp32) ----------------
#define QP 193
#define VP 132
#define PP 68
#define FLASH_SMEM ((64*QP*2 + 64*VP + 64*PP) * 4)

__global__ __launch_bounds__(256) void flash_k(float scale) {
    extern __shared__ float sm[];
    float* Qs = sm;
    float* Ks = Qs + 64 * QP;
    float* Vs = Ks + 64 * QP;
    float* Ps = Vs + 64 * VP;
    const int qb = blockIdx.x, h = blockIdx.y, b = blockIdx.z;
    const int tid = threadIdx.x;
    const int tx = tid & 15, ty = tid >> 4;
    const size_t bs0 = (size_t)b * SEQ;

    for (int idx = tid; idx < 64 * 192; idx += 256) {
        int r = idx / 192, c = idx - r * 192;
        Qs[r * QP + c] = g_q[(bs0 + qb * 64 + r) * 3072 + h * QHD + c];
    }
    float m_i[4], l_i[4], o[4][8];
    #pragma unroll
    for (int i = 0; i < 4; i++) {
        m_i[i] = -1e30f; l_i[i] = 0.f;
        #pragma unroll
        for (int j = 0; j < 8; j++) o[i][j] = 0.f;
    }
    __syncthreads();

    for (int kb = 0; kb <= qb; kb++) {
        for (int idx = tid; idx < 64 * 192; idx += 256) {
            int r = idx / 192, c = idx - r * 192;
            int sk = kb * 64 + r;
            float v;
            if (c < NOPE) v = g_kv[(bs0 + sk) * 4096 + h * 256 + c];
            else          v = g_kpe[(bs0 + sk) * 64 + (c - NOPE)];
            Ks[r * QP + c] = v;
        }
        for (int idx = tid; idx < 64 * 128; idx += 256) {
            int r = idx >> 7, c = idx & 127;
            Vs[r * VP + c] = g_kv[(bs0 + kb * 64 + r) * 4096 + h * 256 + NOPE + c];
        }
        __syncthreads();

        float acc[4][4] = {};
        for (int kk = 0; kk < 192; kk++) {
            float av[4], bv[4];
            #pragma unroll
            for (int i = 0; i < 4; i++) av[i] = Qs[(ty * 4 + i) * QP + kk];
            #pragma unroll
            for (int j = 0; j < 4; j++) bv[j] = Ks[(tx * 4 + j) * QP + kk];
            #pragma unroll
            for (int i = 0; i < 4; i++)
                #pragma unroll
                for (int j = 0; j < 4; j++)
                    acc[i][j] += av[i] * bv[j];
        }

        bool diag = (kb == qb);
        #pragma unroll
        for (int i = 0; i < 4; i++) {
            int qi = qb * 64 + ty * 4 + i;
            float rm = -1e30f;
            #pragma unroll
            for (int j = 0; j < 4; j++) {
                float sv = acc[i][j] * scale;
                if (diag && (kb * 64 + tx * 4 + j > qi)) sv = -1e30f;
                acc[i][j] = sv;
                rm = fmaxf(rm, sv);
            }
            #pragma unroll
            for (int off = 8; off > 0; off >>= 1)
                rm = fmaxf(rm, __shfl_xor_sync(0xffffffffu, rm, off));
            float mnew = fmaxf(m_i[i], rm);
            float alpha = __expf(m_i[i] - mnew);
            float rs = 0.f;
            #pragma unroll
            for (int j = 0; j < 4; j++) {
                float p = __expf(acc[i][j] - mnew);
                Ps[(ty * 4 + i) * PP + tx * 4 + j] = p;
                rs += p;
            }
            #pragma unroll
            for (int off = 8; off > 0; off >>= 1)
                rs += __shfl_xor_sync(0xffffffffu, rs, off);
            l_i[i] = l_i[i] * alpha + rs;
            m_i[i] = mnew;
            #pragma unroll
            for (int j = 0; j < 8; j++) o[i][j] *= alpha;
        }
        __syncthreads();

        for (int kk = 0; kk < 64; kk++) {
            float pv[4];
            #pragma unroll
            for (int i = 0; i < 4; i++) pv[i] = Ps[(ty * 4 + i) * PP + kk];
            float4 v0 = *(const float4*)&Vs[kk * VP + tx * 8];
            float4 v1 = *(const float4*)&Vs[kk * VP + tx * 8 + 4];
            float vv[8] = {v0.x, v0.y, v0.z, v0.w, v1.x, v1.y, v1.z, v1.w};
            #pragma unroll
            for (int i = 0; i < 4; i++)
                #pragma unroll
                for (int j = 0; j < 8; j++)
                    o[i][j] += pv[i] * vv[j];
        }
        __syncthreads();
    }

    #pragma unroll
    for (int i = 0; i < 4; i++) {
        float invl = 1.0f / l_i[i];
        #pragma unroll
        for (int j = 0; j < 8; j++)
            g_attn[(bs0 + qb * 64 + ty * 4 + i) * 2048 + h * VHD + tx * 8 + j] =
                rtf(o[i][j] * invl);
    }
}

// ---------------- launch ----------------
extern "C" void kernel_launch(void* const* d_in, const int* in_sizes, int n_in,
                              void* d_out, int out_size) {
    const float* hs      = (const float*)d_in[0];
    const int*   pos     = (const int*)  d_in[1];
    const float* wq_a    = (const float*)d_in[2];
    const float* q_a_ln  = (const float*)d_in[3];
    const float* wq_b    = (const float*)d_in[4];
    const float* wkv_a   = (const float*)d_in[5];
    const float* kv_a_ln = (const float*)d_in[6];
    const float* wkv_b   = (const float*)d_in[7];
    const float* wo      = (const float*)d_in[8];
    float* out = (float*)d_out;

    float *qlora, *q, *ckv, *cnorm, *kv, *kpe, *attn;
    float *hs_t, *wqa_t, *wqb_t, *wkva_t, *wkvb_t, *wo_t;
    cudaGetSymbolAddress((void**)&qlora, g_qlora);
    cudaGetSymbolAddress((void**)&q,     g_q);
    cudaGetSymbolAddress((void**)&ckv,   g_ckv);
    cudaGetSymbolAddress((void**)&cnorm, g_cnorm);
    cudaGetSymbolAddress((void**)&kv,    g_kv);
    cudaGetSymbolAddress((void**)&kpe,   g_kpe);
    cudaGetSymbolAddress((void**)&attn,  g_attn);
    cudaGetSymbolAddress((void**)&hs_t,  g_hs_t);
    cudaGetSymbolAddress((void**)&wqa_t, g_wqa_t);
    cudaGetSymbolAddress((void**)&wqb_t, g_wqb_t);
    cudaGetSymbolAddress((void**)&wkva_t,g_wkva_t);
    cudaGetSymbolAddress((void**)&wkvb_t,g_wkvb_t);
    cudaGetSymbolAddress((void**)&wo_t,  g_wo_t);

    double m = 0.1 * log(40.0) + 1.0;
    float scale = (float)((1.0 / sqrt(192.0)) * m * m);

    cudaFuncSetAttribute(flash_k, cudaFuncAttributeMaxDynamicSharedMemorySize,
                         FLASH_SMEM);
    cudaFuncSetAttribute(gemm_tf32, cudaFuncAttributeMaxDynamicSharedMemorySize,
                         GEMM_SMEM);

    dim3 blk(256);
    // tf32-round inputs
    auto cvtn = [&](const float* x, float* y, size_t n) {
        cvt_tf32_k<<<(int)((n / 4 + 255) / 256), 256>>>(x, y, (int)n);
    };
    cvtn(hs,    hs_t,   (size_t)ROWS * 2048);
    cvtn(wq_a,  wqa_t,  (size_t)1536 * 2048);
    cvtn(wq_b,  wqb_t,  (size_t)3072 * 1536);
    cvtn(wkv_a, wkva_t, (size_t)576 * 2048);
    cvtn(wkv_b, wkvb_t, (size_t)4096 * 512);
    cvtn(wo,    wo_t,   (size_t)2048 * 2048);

    gemm_tf32<<<dim3(1536 / 128, ROWS / 128), blk, GEMM_SMEM>>>(hs_t, wqa_t, qlora, ROWS, 1536, 2048);
    rmsnorm_k<<<ROWS, 256>>>(qlora, q_a_ln, qlora, 1536, 1536, 1536);
    gemm_tf32<<<dim3(3072 / 128, ROWS / 128), blk, GEMM_SMEM>>>(qlora, wqb_t, q, ROWS, 3072, 1536);
    gemm_tf32<<<dim3((576 + 127) / 128, ROWS / 128), blk, GEMM_SMEM>>>(hs_t, wkva_t, ckv, ROWS, 576, 2048);
    rmsnorm_k<<<ROWS, 256>>>(ckv, kv_a_ln, cnorm, 512, 576, 512);
    gemm_tf32<<<dim3(4096 / 128, ROWS / 128), blk, GEMM_SMEM>>>(cnorm, wkvb_t, kv, ROWS, 4096, 512);
    rope_k<<<ROWS, 544>>>(pos);
    flash_k<<<dim3(SEQ / 64, NHEADS, BATCH), 256, FLASH_SMEM>>>(scale);
    gemm_tf32<<<dim3(2048 / 128, ROWS / 128), blk, GEMM_SMEM>>>(attn, wo_t, out, ROWS, 2048, 2048);
}

// round 5
// speedup vs baseline: 3.4148x; 2.0278x over previous
#include <cuda_runtime.h>
#include <math.h>
#include <stdint.h>

#define SEQ 2048
#define BATCH 2
#define ROWS (BATCH*SEQ)   // 4096
#define NHEADS 16
#define QHD 192
#define NOPE 128
#define VHD 128

// ---------------- scratch (device globals; no allocation allowed) ----------------
__device__ float g_qlora[(size_t)ROWS*1536];
__device__ float g_q[(size_t)ROWS*3072];
__device__ float g_ckv[(size_t)ROWS*576];
__device__ float g_cnorm[(size_t)ROWS*512];
__device__ float g_kv[(size_t)ROWS*4096];
__device__ float g_kpe[(size_t)ROWS*64];
__device__ float g_attn[(size_t)ROWS*2048];
// tf32-rounded copies (inputs to tensor-core GEMMs)
__device__ float g_hs_t [(size_t)ROWS*2048];
__device__ float g_wqa_t[(size_t)1536*2048];
__device__ float g_wqb_t[(size_t)3072*1536];
__device__ float g_wkva_t[(size_t)576*2048];
__device__ float g_wkvb_t[(size_t)4096*512];
__device__ float g_wo_t [(size_t)2048*2048];

__device__ __forceinline__ uint32_t f2tf32(float f) {
    uint32_t u;
    asm("cvt.rna.tf32.f32 %0, %1;" : "=r"(u) : "f"(f));
    return u;
}
__device__ __forceinline__ float rtf(float f) { return __uint_as_float(f2tf32(f)); }

__device__ __forceinline__ void mma_tf32(float d[4], const uint32_t a[4],
                                         const uint32_t b[2]) {
    asm volatile(
        "mma.sync.aligned.m16n8k8.row.col.f32.tf32.tf32.f32 "
        "{%0,%1,%2,%3}, {%4,%5,%6,%7}, {%8,%9}, {%0,%1,%2,%3};"
        : "+f"(d[0]), "+f"(d[1]), "+f"(d[2]), "+f"(d[3])
        : "r"(a[0]), "r"(a[1]), "r"(a[2]), "r"(a[3]), "r"(b[0]), "r"(b[1]));
}

__device__ __forceinline__ void cp_async16(uint32_t saddr, const void* gptr, bool pred) {
    int sz = pred ? 16 : 0;
    asm volatile("cp.async.cg.shared.global [%0], [%1], 16, %2;\n"
                 :: "r"(saddr), "l"(gptr), "r"(sz));
}

// ---------------- elementwise tf32 rounding copy ----------------
__global__ __launch_bounds__(256) void cvt_tf32_k(const float* __restrict__ x,
                                                  float* __restrict__ y, int n) {
    int i = (blockIdx.x * 256 + threadIdx.x) * 4;
    if (i < n) {
        float4 v = *(const float4*)(x + i);
        v.x = rtf(v.x); v.y = rtf(v.y); v.z = rtf(v.z); v.w = rtf(v.w);
        *(float4*)(y + i) = v;
    }
}

// ==================================================================
// TF32 GEMM: C[M,N] = A[M,K] @ B[N,K]^T  (same as R4)
// ==================================================================
#define APITCH 36
#define TILE_F (128*APITCH)
#define GEMM_SMEM (6*TILE_F*4)

__global__ __launch_bounds__(256, 2) void gemm_tf32(const float* __restrict__ A,
                                                    const float* __restrict__ B,
                                                    float* __restrict__ C,
                                                    int M, int N, int K) {
    extern __shared__ float sm_[];
    float* As = sm_;
    float* Bs = sm_ + 3 * TILE_F;
    const int tid = threadIdx.x;
    const int warp = tid >> 5, lane = tid & 31;
    const int wm = (warp & 3) * 32, wn = (warp >> 2) * 64;
    const int g = lane >> 2, tl = lane & 3;
    const int m0 = blockIdx.y * 128, n0 = blockIdx.x * 128;

    float acc[2][8][4];
    #pragma unroll
    for (int i = 0; i < 2; i++)
        #pragma unroll
        for (int j = 0; j < 8; j++)
            #pragma unroll
            for (int v = 0; v < 4; v++) acc[i][j][v] = 0.f;

    const int T = K / 32;

    auto issue = [&](int stage, int t) {
        const int k0 = t * 32;
        uint32_t ab = (uint32_t)__cvta_generic_to_shared(As + stage * TILE_F);
        uint32_t bb = (uint32_t)__cvta_generic_to_shared(Bs + stage * TILE_F);
        #pragma unroll
        for (int u = 0; u < 4; u++) {
            int seg = tid + u * 256;
            int row = seg >> 3, kq = (seg & 7) * 4;
            cp_async16(ab + (row * APITCH + kq) * 4,
                       A + (size_t)(m0 + row) * K + k0 + kq, true);
            int nr = n0 + row;
            cp_async16(bb + (row * APITCH + kq) * 4,
                       B + (size_t)(nr < N ? nr : 0) * K + k0 + kq, nr < N);
        }
        asm volatile("cp.async.commit_group;");
    };

    issue(0, 0);
    if (T > 1) issue(1, 1); else asm volatile("cp.async.commit_group;");

    for (int t = 0; t < T; t++) {
        asm volatile("cp.async.wait_group 1;");
        __syncthreads();
        if (t + 2 < T) issue((t + 2) % 3, t + 2);
        else asm volatile("cp.async.commit_group;");

        const float* Ab = As + (t % 3) * TILE_F;
        const float* Bb = Bs + (t % 3) * TILE_F;
        #pragma unroll
        for (int ks = 0; ks < 4; ks++) {
            const int kb = ks * 8;
            uint32_t afr[2][4], bfr[8][2];
            #pragma unroll
            for (int mt = 0; mt < 2; mt++) {
                int rb = wm + mt * 16 + g;
                afr[mt][0] = __float_as_uint(Ab[rb * APITCH + kb + tl]);
                afr[mt][1] = __float_as_uint(Ab[(rb + 8) * APITCH + kb + tl]);
                afr[mt][2] = __float_as_uint(Ab[rb * APITCH + kb + tl + 4]);
                afr[mt][3] = __float_as_uint(Ab[(rb + 8) * APITCH + kb + tl + 4]);
            }
            #pragma unroll
            for (int nt = 0; nt < 8; nt++) {
                int cb = wn + nt * 8 + g;
                bfr[nt][0] = __float_as_uint(Bb[cb * APITCH + kb + tl]);
                bfr[nt][1] = __float_as_uint(Bb[cb * APITCH + kb + tl + 4]);
            }
            #pragma unroll
            for (int mt = 0; mt < 2; mt++)
                #pragma unroll
                for (int nt = 0; nt < 8; nt++)
                    mma_tf32(acc[mt][nt], afr[mt], bfr[nt]);
        }
        __syncthreads();
    }

    #pragma unroll
    for (int mt = 0; mt < 2; mt++) {
        int r0 = m0 + wm + mt * 16 + g;
        #pragma unroll
        for (int nt = 0; nt < 8; nt++) {
            int cn = n0 + wn + nt * 8 + 2 * tl;
            if (cn < N) {
                *(float2*)&C[(size_t)r0 * N + cn] =
                    make_float2(acc[mt][nt][0], acc[mt][nt][1]);
                *(float2*)&C[(size_t)(r0 + 8) * N + cn] =
                    make_float2(acc[mt][nt][2], acc[mt][nt][3]);
            }
        }
    }
}

// ---------------- RMSNorm (writes tf32-rounded output) ----------------
__global__ __launch_bounds__(256) void rmsnorm_k(const float* __restrict__ X,
                                                 const float* __restrict__ w,
                                                 float* __restrict__ Y,
                                                 int W, int ldx, int ldy) {
    int row = blockIdx.x;
    const float* x = X + (size_t)row * ldx;
    float ss = 0.f;
    for (int i = threadIdx.x; i < W; i += 256) { float v = x[i]; ss += v * v; }
    __shared__ float red[256];
    red[threadIdx.x] = ss;
    __syncthreads();
    for (int s = 128; s > 0; s >>= 1) {
        if (threadIdx.x < s) red[threadIdx.x] += red[threadIdx.x + s];
        __syncthreads();
    }
    float inv = rsqrtf(red[0] / (float)W + 1e-6f);
    float* y = Y + (size_t)row * ldy;
    for (int i = threadIdx.x; i < W; i += 256) y[i] = rtf(w[i] * (x[i] * inv));
}

// ---------------- YaRN RoPE ----------------
__global__ __launch_bounds__(544) void rope_k(const int* __restrict__ pos_ids) {
    int row = blockIdx.x;
    int t = threadIdx.x;
    int h = t >> 5, j = t & 31;
    float pos = (float)pos_ids[row];
    float fe = powf(10000.0f, -(float)j / 32.0f);
    float ramp = fminf(fmaxf(((float)j - 10.0f) / 13.0f, 0.f), 1.f);
    float invf = (fe / 40.0f) * ramp + fe * (1.0f - ramp);
    float ang = pos * invf;
    float s, c;
    sincosf(ang, &s, &c);
    if (h < NHEADS) {
        float* base = g_q + (size_t)row * 3072 + h * QHD + NOPE;
        float x0 = base[2 * j], x1 = base[2 * j + 1];
        __syncwarp();
        base[j]      = x0 * c - x1 * s;
        base[32 + j] = x1 * c + x0 * s;
    } else {
        const float* src = g_ckv + (size_t)row * 576 + 512;
        float x0 = src[2 * j], x1 = src[2 * j + 1];
        float* dst = g_kpe + (size_t)row * 64;
        dst[j]      = x0 * c - x1 * s;
        dst[32 + j] = x1 * c + x0 * s;
    }
}

// ==================================================================
// Flash attention, tf32 tensor cores.
// 128 threads / 4 warps, BM=64 q-rows, BN=64 k-cols, head dim 192/128.
// Warp w owns S/O rows [16w, 16w+16). QK^T and P·V via mma.m16n8k8.
// ==================================================================
#define QP 196    // Q/K pitch: bank = 4g+tl, conflict-free
#define VP 136    // V pitch: bank = 8tl+g, conflict-free
#define PP 68     // P pitch: bank = 4g+tl, conflict-free
#define FLASH_SMEM ((64*QP*2 + 64*VP + 64*PP) * 4)

__global__ __launch_bounds__(128) void flash_tf32(float scale) {
    extern __shared__ float sm[];
    float* Qs = sm;                    // [64][QP]
    float* Ks = Qs + 64 * QP;          // [64][QP]
    float* Vs = Ks + 64 * QP;          // [64][VP]
    float* Ps = Vs + 64 * VP;          // [64][PP]
    const int qb = blockIdx.x, h = blockIdx.y, b = blockIdx.z;
    const int tid = threadIdx.x;
    const int warp = tid >> 5, lane = tid & 31;
    const int g = lane >> 2, tl = lane & 3;
    const int wm = warp * 16;
    const size_t bs0 = (size_t)b * SEQ;

    // ---- stage Q (rtf-rounded), 64 rows x 192 ----
    for (int idx = tid; idx < 64 * 48; idx += 128) {
        int r = idx / 48, q4 = (idx % 48) * 4;
        float4 v = *(const float4*)&g_q[(bs0 + qb * 64 + r) * 3072 + h * QHD + q4];
        float* d = &Qs[r * QP + q4];
        d[0] = rtf(v.x); d[1] = rtf(v.y); d[2] = rtf(v.z); d[3] = rtf(v.w);
    }

    float m_i[2] = {-1e30f, -1e30f};
    float l_i[2] = {0.f, 0.f};
    float acc_o[16][4];
    #pragma unroll
    for (int nt = 0; nt < 16; nt++)
        #pragma unroll
        for (int v = 0; v < 4; v++) acc_o[nt][v] = 0.f;

    __syncthreads();

    const int row0 = qb * 64 + wm + g;       // global q row (lane rows: row0, row0+8)

    for (int kb = 0; kb <= qb; kb++) {
        __syncthreads();   // previous iteration's P·V done before restaging
        // ---- stage K (nope+rope, rtf) ----
        for (int idx = tid; idx < 64 * 48; idx += 128) {
            int r = idx / 48, q = idx % 48;
            int sk = kb * 64 + r;
            float4 v;
            if (q < 32) v = *(const float4*)&g_kv[(bs0 + sk) * 4096 + h * 256 + q * 4];
            else        v = *(const float4*)&g_kpe[(bs0 + sk) * 64 + (q - 32) * 4];
            float* d = &Ks[r * QP + q * 4];
            d[0] = rtf(v.x); d[1] = rtf(v.y); d[2] = rtf(v.z); d[3] = rtf(v.w);
        }
        // ---- stage V (rtf) ----
        for (int idx = tid; idx < 64 * 32; idx += 128) {
            int r = idx >> 5, q4 = (idx & 31) * 4;
            float4 v = *(const float4*)&g_kv[(bs0 + kb * 64 + r) * 4096 + h * 256 + NOPE + q4];
            float* d = &Vs[r * VP + q4];
            d[0] = rtf(v.x); d[1] = rtf(v.y); d[2] = rtf(v.z); d[3] = rtf(v.w);
        }
        __syncthreads();

        // ---- S = Q @ K^T  (16x64 per warp) ----
        float acc_s[8][4];
        #pragma unroll
        for (int nt = 0; nt < 8; nt++)
            #pragma unroll
            for (int v = 0; v < 4; v++) acc_s[nt][v] = 0.f;

        #pragma unroll
        for (int ks = 0; ks < 24; ks++) {
            const int kb8 = ks * 8;
            uint32_t afr[4];
            afr[0] = __float_as_uint(Qs[(wm + g) * QP + kb8 + tl]);
            afr[1] = __float_as_uint(Qs[(wm + g + 8) * QP + kb8 + tl]);
            afr[2] = __float_as_uint(Qs[(wm + g) * QP + kb8 + tl + 4]);
            afr[3] = __float_as_uint(Qs[(wm + g + 8) * QP + kb8 + tl + 4]);
            #pragma unroll
            for (int nt = 0; nt < 8; nt++) {
                uint32_t bfr[2];
                bfr[0] = __float_as_uint(Ks[(nt * 8 + g) * QP + kb8 + tl]);
                bfr[1] = __float_as_uint(Ks[(nt * 8 + g) * QP + kb8 + tl + 4]);
                mma_tf32(acc_s[nt], afr, bfr);
            }
        }

        // ---- online softmax on fragments ----
        const bool diag = (kb == qb);
        float rmax0 = -1e30f, rmax1 = -1e30f;
        #pragma unroll
        for (int nt = 0; nt < 8; nt++) {
            int c0 = kb * 64 + nt * 8 + 2 * tl, c1 = c0 + 1;
            float s0 = acc_s[nt][0] * scale, s1 = acc_s[nt][1] * scale;
            float s2 = acc_s[nt][2] * scale, s3 = acc_s[nt][3] * scale;
            if (diag) {
                if (c0 > row0) s0 = -1e30f;
                if (c1 > row0) s1 = -1e30f;
                if (c0 > row0 + 8) s2 = -1e30f;
                if (c1 > row0 + 8) s3 = -1e30f;
            }
            acc_s[nt][0] = s0; acc_s[nt][1] = s1;
            acc_s[nt][2] = s2; acc_s[nt][3] = s3;
            rmax0 = fmaxf(rmax0, fmaxf(s0, s1));
            rmax1 = fmaxf(rmax1, fmaxf(s2, s3));
        }
        #pragma unroll
        for (int off = 1; off <= 2; off <<= 1) {
            rmax0 = fmaxf(rmax0, __shfl_xor_sync(0xffffffffu, rmax0, off));
            rmax1 = fmaxf(rmax1, __shfl_xor_sync(0xffffffffu, rmax1, off));
        }
        float mn0 = fmaxf(m_i[0], rmax0), mn1 = fmaxf(m_i[1], rmax1);
        float al0 = __expf(m_i[0] - mn0), al1 = __expf(m_i[1] - mn1);
        float rs0 = 0.f, rs1 = 0.f;
        #pragma unroll
        for (int nt = 0; nt < 8; nt++) {
            float p0 = __expf(acc_s[nt][0] - mn0);
            float p1 = __expf(acc_s[nt][1] - mn0);
            float p2 = __expf(acc_s[nt][2] - mn1);
            float p3 = __expf(acc_s[nt][3] - mn1);
            rs0 += p0 + p1; rs1 += p2 + p3;
            Ps[(wm + g) * PP + nt * 8 + 2 * tl]     = rtf(p0);
            Ps[(wm + g) * PP + nt * 8 + 2 * tl + 1] = rtf(p1);
            Ps[(wm + g + 8) * PP + nt * 8 + 2 * tl]     = rtf(p2);
            Ps[(wm + g + 8) * PP + nt * 8 + 2 * tl + 1] = rtf(p3);
        }
        #pragma unroll
        for (int off = 1; off <= 2; off <<= 1) {
            rs0 += __shfl_xor_sync(0xffffffffu, rs0, off);
            rs1 += __shfl_xor_sync(0xffffffffu, rs1, off);
        }
        l_i[0] = l_i[0] * al0 + rs0;
        l_i[1] = l_i[1] * al1 + rs1;
        m_i[0] = mn0; m_i[1] = mn1;
        #pragma unroll
        for (int nt = 0; nt < 16; nt++) {
            acc_o[nt][0] *= al0; acc_o[nt][1] *= al0;
            acc_o[nt][2] *= al1; acc_o[nt][3] *= al1;
        }
        __syncwarp();   // P visible to this warp (warp-private rows)

        // ---- O += P @ V  (16x128 per warp) ----
        #pragma unroll
        for (int ks = 0; ks < 8; ks++) {
            const int kb8 = ks * 8;
            uint32_t afr[4];
            afr[0] = __float_as_uint(Ps[(wm + g) * PP + kb8 + tl]);
            afr[1] = __float_as_uint(Ps[(wm + g + 8) * PP + kb8 + tl]);
            afr[2] = __float_as_uint(Ps[(wm + g) * PP + kb8 + tl + 4]);
            afr[3] = __float_as_uint(Ps[(wm + g + 8) * PP + kb8 + tl + 4]);
            #pragma unroll
            for (int nt = 0; nt < 16; nt++) {
                uint32_t bfr[2];
                bfr[0] = __float_as_uint(Vs[(kb8 + tl) * VP + nt * 8 + g]);
                bfr[1] = __float_as_uint(Vs[(kb8 + tl + 4) * VP + nt * 8 + g]);
                mma_tf32(acc_o[nt], afr, bfr);
            }
        }
    }

    // ---- epilogue: normalize + write (rtf for wo GEMM) ----
    float inv0 = 1.0f / l_i[0], inv1 = 1.0f / l_i[1];
    size_t r0 = (bs0 + qb * 64 + wm + g) * 2048 + h * VHD;
    size_t r1 = r0 + 8 * 2048;
    #pragma unroll
    for (int nt = 0; nt < 16; nt++) {
        int cn = nt * 8 + 2 * tl;
        *(float2*)&g_attn[r0 + cn] =
            make_float2(rtf(acc_o[nt][0] * inv0), rtf(acc_o[nt][1] * inv0));
        *(float2*)&g_attn[r1 + cn] =
            make_float2(rtf(acc_o[nt][2] * inv1), rtf(acc_o[nt][3] * inv1));
    }
}

// ---------------- launch ----------------
extern "C" void kernel_launch(void* const* d_in, const int* in_sizes, int n_in,
                              void* d_out, int out_size) {
    const float* hs      = (const float*)d_in[0];
    const int*   pos     = (const int*)  d_in[1];
    const float* wq_a    = (const float*)d_in[2];
    const float* q_a_ln  = (const float*)d_in[3];
    const float* wq_b    = (const float*)d_in[4];
    const float* wkv_a   = (const float*)d_in[5];
    const float* kv_a_ln = (const float*)d_in[6];
    const float* wkv_b   = (const float*)d_in[7];
    const float* wo      = (const float*)d_in[8];
    float* out = (float*)d_out;

    float *qlora, *q, *ckv, *cnorm, *kv, *kpe, *attn;
    float *hs_t, *wqa_t, *wqb_t, *wkva_t, *wkvb_t, *wo_t;
    cudaGetSymbolAddress((void**)&qlora, g_qlora);
    cudaGetSymbolAddress((void**)&q,     g_q);
    cudaGetSymbolAddress((void**)&ckv,   g_ckv);
    cudaGetSymbolAddress((void**)&cnorm, g_cnorm);
    cudaGetSymbolAddress((void**)&kv,    g_kv);
    cudaGetSymbolAddress((void**)&kpe,   g_kpe);
    cudaGetSymbolAddress((void**)&attn,  g_attn);
    cudaGetSymbolAddress((void**)&hs_t,  g_hs_t);
    cudaGetSymbolAddress((void**)&wqa_t, g_wqa_t);
    cudaGetSymbolAddress((void**)&wqb_t, g_wqb_t);
    cudaGetSymbolAddress((void**)&wkva_t,g_wkva_t);
    cudaGetSymbolAddress((void**)&wkvb_t,g_wkvb_t);
    cudaGetSymbolAddress((void**)&wo_t,  g_wo_t);

    double m = 0.1 * log(40.0) + 1.0;
    float scale = (float)((1.0 / sqrt(192.0)) * m * m);

    cudaFuncSetAttribute(flash_tf32, cudaFuncAttributeMaxDynamicSharedMemorySize,
                         FLASH_SMEM);
    cudaFuncSetAttribute(gemm_tf32, cudaFuncAttributeMaxDynamicSharedMemorySize,
                         GEMM_SMEM);

    dim3 blk(256);
    auto cvtn = [&](const float* x, float* y, size_t n) {
        cvt_tf32_k<<<(int)((n / 4 + 255) / 256), 256>>>(x, y, (int)n);
    };
    cvtn(hs,    hs_t,   (size_t)ROWS * 2048);
    cvtn(wq_a,  wqa_t,  (size_t)1536 * 2048);
    cvtn(wq_b,  wqb_t,  (size_t)3072 * 1536);
    cvtn(wkv_a, wkva_t, (size_t)576 * 2048);
    cvtn(wkv_b, wkvb_t, (size_t)4096 * 512);
    cvtn(wo,    wo_t,   (size_t)2048 * 2048);

    gemm_tf32<<<dim3(1536 / 128, ROWS / 128), blk, GEMM_SMEM>>>(hs_t, wqa_t, qlora, ROWS, 1536, 2048);
    rmsnorm_k<<<ROWS, 256>>>(qlora, q_a_ln, qlora, 1536, 1536, 1536);
    gemm_tf32<<<dim3(3072 / 128, ROWS / 128), blk, GEMM_SMEM>>>(qlora, wqb_t, q, ROWS, 3072, 1536);
    gemm_tf32<<<dim3((576 + 127) / 128, ROWS / 128), blk, GEMM_SMEM>>>(hs_t, wkva_t, ckv, ROWS, 576, 2048);
    rmsnorm_k<<<ROWS, 256>>>(ckv, kv_a_ln, cnorm, 512, 576, 512);
    gemm_tf32<<<dim3(4096 / 128, ROWS / 128), blk, GEMM_SMEM>>>(cnorm, wkvb_t, kv, ROWS, 4096, 512);
    rope_k<<<ROWS, 544>>>(pos);
    flash_tf32<<<dim3(SEQ / 64, NHEADS, BATCH), 128, FLASH_SMEM>>>(scale);
    gemm_tf32<<<dim3(2048 / 128, ROWS / 128), blk, GEMM_SMEM>>>(attn, wo_t, out, ROWS, 2048, 2048);
}

// round 6
// speedup vs baseline: 4.9446x; 1.4480x over previous
#include <cuda_runtime.h>
#include <math.h>
#include <stdint.h>

#define SEQ 2048
#define BATCH 2
#define ROWS (BATCH*SEQ)   // 4096
#define NHEADS 16
#define QHD 192
#define NOPE 128
#define VHD 128

// ---------------- scratch (device globals; no allocation allowed) ----------------
__device__ float g_qlora[(size_t)ROWS*1536];
__device__ float g_q[(size_t)ROWS*3072];
__device__ float g_ckv[(size_t)ROWS*576];
__device__ float g_cnorm[(size_t)ROWS*512];
__device__ float g_kv[(size_t)ROWS*4096];
__device__ float g_kpe[(size_t)ROWS*64];
__device__ float g_attn[(size_t)ROWS*2048];
// tf32-rounded copies (inputs to tensor-core GEMMs)
__device__ float g_hs_t [(size_t)ROWS*2048];
__device__ float g_wqa_t[(size_t)1536*2048];
__device__ float g_wqb_t[(size_t)3072*1536];
__device__ float g_wkva_t[(size_t)576*2048];
__device__ float g_wkvb_t[(size_t)4096*512];
__device__ float g_wo_t [(size_t)2048*2048];

__device__ __forceinline__ uint32_t f2tf32(float f) {
    uint32_t u;
    asm("cvt.rna.tf32.f32 %0, %1;" : "=r"(u) : "f"(f));
    return u;
}
__device__ __forceinline__ float rtf(float f) { return __uint_as_float(f2tf32(f)); }

__device__ __forceinline__ void mma_tf32(float d[4], const uint32_t a[4],
                                         const uint32_t b[2]) {
    asm volatile(
        "mma.sync.aligned.m16n8k8.row.col.f32.tf32.tf32.f32 "
        "{%0,%1,%2,%3}, {%4,%5,%6,%7}, {%8,%9}, {%0,%1,%2,%3};"
        : "+f"(d[0]), "+f"(d[1]), "+f"(d[2]), "+f"(d[3])
        : "r"(a[0]), "r"(a[1]), "r"(a[2]), "r"(a[3]), "r"(b[0]), "r"(b[1]));
}

__device__ __forceinline__ void cp_async16(uint32_t saddr, const void* gptr, bool pred) {
    int sz = pred ? 16 : 0;
    asm volatile("cp.async.cg.shared.global [%0], [%1], 16, %2;\n"
                 :: "r"(saddr), "l"(gptr), "r"(sz));
}

// ---------------- elementwise tf32 rounding copy ----------------
__global__ __launch_bounds__(256) void cvt_tf32_k(const float* __restrict__ x,
                                                  float* __restrict__ y, int n) {
    int i = (blockIdx.x * 256 + threadIdx.x) * 4;
    if (i < n) {
        float4 v = *(const float4*)(x + i);
        v.x = rtf(v.x); v.y = rtf(v.y); v.z = rtf(v.z); v.w = rtf(v.w);
        *(float4*)(y + i) = v;
    }
}

// ==================================================================
// TF32 GEMM: C[M,N] = A[M,K] @ B[N,K]^T
// 128x128 tile, BK=32, 3-stage cp.async pipeline, 256 threads.
// roundC!=0 -> epilogue writes tf32-rounded values (for flash inputs).
// ==================================================================
#define APITCH 36
#define TILE_F (128*APITCH)
#define GEMM_SMEM (6*TILE_F*4)

__global__ __launch_bounds__(256, 2) void gemm_tf32(const float* __restrict__ A,
                                                    const float* __restrict__ B,
                                                    float* __restrict__ C,
                                                    int M, int N, int K, int roundC) {
    extern __shared__ float sm_[];
    float* As = sm_;
    float* Bs = sm_ + 3 * TILE_F;
    const int tid = threadIdx.x;
    const int warp = tid >> 5, lane = tid & 31;
    const int wm = (warp & 3) * 32, wn = (warp >> 2) * 64;
    const int g = lane >> 2, tl = lane & 3;
    const int m0 = blockIdx.y * 128, n0 = blockIdx.x * 128;

    float acc[2][8][4];
    #pragma unroll
    for (int i = 0; i < 2; i++)
        #pragma unroll
        for (int j = 0; j < 8; j++)
            #pragma unroll
            for (int v = 0; v < 4; v++) acc[i][j][v] = 0.f;

    const int T = K / 32;

    auto issue = [&](int stage, int t) {
        const int k0 = t * 32;
        uint32_t ab = (uint32_t)__cvta_generic_to_shared(As + stage * TILE_F);
        uint32_t bb = (uint32_t)__cvta_generic_to_shared(Bs + stage * TILE_F);
        #pragma unroll
        for (int u = 0; u < 4; u++) {
            int seg = tid + u * 256;
            int row = seg >> 3, kq = (seg & 7) * 4;
            cp_async16(ab + (row * APITCH + kq) * 4,
                       A + (size_t)(m0 + row) * K + k0 + kq, true);
            int nr = n0 + row;
            cp_async16(bb + (row * APITCH + kq) * 4,
                       B + (size_t)(nr < N ? nr : 0) * K + k0 + kq, nr < N);
        }
        asm volatile("cp.async.commit_group;");
    };

    issue(0, 0);
    if (T > 1) issue(1, 1); else asm volatile("cp.async.commit_group;");

    for (int t = 0; t < T; t++) {
        asm volatile("cp.async.wait_group 1;");
        __syncthreads();
        if (t + 2 < T) issue((t + 2) % 3, t + 2);
        else asm volatile("cp.async.commit_group;");

        const float* Ab = As + (t % 3) * TILE_F;
        const float* Bb = Bs + (t % 3) * TILE_F;
        #pragma unroll
        for (int ks = 0; ks < 4; ks++) {
            const int kb = ks * 8;
            uint32_t afr[2][4], bfr[8][2];
            #pragma unroll
            for (int mt = 0; mt < 2; mt++) {
                int rb = wm + mt * 16 + g;
                afr[mt][0] = __float_as_uint(Ab[rb * APITCH + kb + tl]);
                afr[mt][1] = __float_as_uint(Ab[(rb + 8) * APITCH + kb + tl]);
                afr[mt][2] = __float_as_uint(Ab[rb * APITCH + kb + tl + 4]);
                afr[mt][3] = __float_as_uint(Ab[(rb + 8) * APITCH + kb + tl + 4]);
            }
            #pragma unroll
            for (int nt = 0; nt < 8; nt++) {
                int cb = wn + nt * 8 + g;
                bfr[nt][0] = __float_as_uint(Bb[cb * APITCH + kb + tl]);
                bfr[nt][1] = __float_as_uint(Bb[cb * APITCH + kb + tl + 4]);
            }
            #pragma unroll
            for (int mt = 0; mt < 2; mt++)
                #pragma unroll
                for (int nt = 0; nt < 8; nt++)
                    mma_tf32(acc[mt][nt], afr[mt], bfr[nt]);
        }
        __syncthreads();
    }

    #pragma unroll
    for (int mt = 0; mt < 2; mt++) {
        int r0 = m0 + wm + mt * 16 + g;
        #pragma unroll
        for (int nt = 0; nt < 8; nt++) {
            int cn = n0 + wn + nt * 8 + 2 * tl;
            if (cn < N) {
                float v0 = acc[mt][nt][0], v1 = acc[mt][nt][1];
                float v2 = acc[mt][nt][2], v3 = acc[mt][nt][3];
                if (roundC) { v0 = rtf(v0); v1 = rtf(v1); v2 = rtf(v2); v3 = rtf(v3); }
                *(float2*)&C[(size_t)r0 * N + cn]       = make_float2(v0, v1);
                *(float2*)&C[(size_t)(r0 + 8) * N + cn] = make_float2(v2, v3);
            }
        }
    }
}

// ---------------- RMSNorm (writes tf32-rounded output) ----------------
__global__ __launch_bounds__(256) void rmsnorm_k(const float* __restrict__ X,
                                                 const float* __restrict__ w,
                                                 float* __restrict__ Y,
                                                 int W, int ldx, int ldy) {
    int row = blockIdx.x;
    const float* x = X + (size_t)row * ldx;
    float ss = 0.f;
    for (int i = threadIdx.x; i < W; i += 256) { float v = x[i]; ss += v * v; }
    __shared__ float red[256];
    red[threadIdx.x] = ss;
    __syncthreads();
    for (int s = 128; s > 0; s >>= 1) {
        if (threadIdx.x < s) red[threadIdx.x] += red[threadIdx.x + s];
        __syncthreads();
    }
    float inv = rsqrtf(red[0] / (float)W + 1e-6f);
    float* y = Y + (size_t)row * ldy;
    for (int i = threadIdx.x; i < W; i += 256) y[i] = rtf(w[i] * (x[i] * inv));
}

// ---------------- YaRN RoPE (writes tf32-rounded outputs) ----------------
__global__ __launch_bounds__(544) void rope_k(const int* __restrict__ pos_ids) {
    int row = blockIdx.x;
    int t = threadIdx.x;
    int h = t >> 5, j = t & 31;
    float pos = (float)pos_ids[row];
    float fe = powf(10000.0f, -(float)j / 32.0f);
    float ramp = fminf(fmaxf(((float)j - 10.0f) / 13.0f, 0.f), 1.f);
    float invf = (fe / 40.0f) * ramp + fe * (1.0f - ramp);
    float ang = pos * invf;
    float s, c;
    sincosf(ang, &s, &c);
    if (h < NHEADS) {
        float* base = g_q + (size_t)row * 3072 + h * QHD + NOPE;
        float x0 = base[2 * j], x1 = base[2 * j + 1];
        __syncwarp();
        base[j]      = rtf(x0 * c - x1 * s);
        base[32 + j] = rtf(x1 * c + x0 * s);
    } else {
        const float* src = g_ckv + (size_t)row * 576 + 512;
        float x0 = src[2 * j], x1 = src[2 * j + 1];
        float* dst = g_kpe + (size_t)row * 64;
        dst[j]      = rtf(x0 * c - x1 * s);
        dst[32 + j] = rtf(x1 * c + x0 * s);
    }
}

// ==================================================================
// Flash attention, tf32 tensor cores, cp.async double-buffered K/V.
// 128 threads / 4 warps, BM=64, BN=64. All inputs pre-rounded to tf32
// by producers, so staging is a raw async copy.
// P overlays the current K buffer (K dead after S; barrier in between).
// ==================================================================
#define QP 196
#define VP 136
#define PP 68
#define KTILE_F (64*QP)
#define VTILE_F (64*VP)
#define FLASH_SMEM ((64*QP + 2*KTILE_F + 2*VTILE_F) * 4)   // 220,160 B

__global__ __launch_bounds__(128) void flash_tf32(float scale) {
    extern __shared__ float sm[];
    float* Qs  = sm;                       // [64][QP]
    float* Kb  = sm + 64 * QP;             // [2][64][QP]  (P overlays current)
    float* Vb  = Kb + 2 * KTILE_F;         // [2][64][VP]
    const int qb = blockIdx.x, h = blockIdx.y, b = blockIdx.z;
    const int tid = threadIdx.x;
    const int warp = tid >> 5, lane = tid & 31;
    const int g = lane >> 2, tl = lane & 3;
    const int wm = warp * 16;
    const size_t bs0 = (size_t)b * SEQ;

    const uint32_t qs_s = (uint32_t)__cvta_generic_to_shared(Qs);
    const uint32_t kb_s = (uint32_t)__cvta_generic_to_shared(Kb);
    const uint32_t vb_s = (uint32_t)__cvta_generic_to_shared(Vb);

    auto stageK = [&](int buf, int kb) {
        uint32_t base = kb_s + (uint32_t)(buf * KTILE_F * 4);
        #pragma unroll
        for (int u = 0; u < 24; u++) {
            int idx = tid + u * 128;
            int r = idx / 48, q = idx % 48;
            const float* src = (q < 32)
                ? &g_kv[(bs0 + kb * 64 + r) * 4096 + h * 256 + q * 4]
                : &g_kpe[(bs0 + kb * 64 + r) * 64 + (q - 32) * 4];
            cp_async16(base + (r * QP + q * 4) * 4, src, true);
        }
    };
    auto stageV = [&](int buf, int kb) {
        uint32_t base = vb_s + (uint32_t)(buf * VTILE_F * 4);
        #pragma unroll
        for (int u = 0; u < 16; u++) {
            int idx = tid + u * 128;
            int r = idx >> 5, q4 = (idx & 31) * 4;
            cp_async16(base + (r * VP + q4) * 4,
                       &g_kv[(bs0 + kb * 64 + r) * 4096 + h * 256 + NOPE + q4], true);
        }
    };

    // ---- prologue: issue Q + K0 + V0 as one group ----
    #pragma unroll
    for (int u = 0; u < 24; u++) {
        int idx = tid + u * 128;
        int r = idx / 48, q4 = (idx % 48) * 4;
        cp_async16(qs_s + (r * QP + q4) * 4,
                   &g_q[(bs0 + qb * 64 + r) * 3072 + h * QHD + q4], true);
    }
    stageK(0, 0);
    stageV(0, 0);
    asm volatile("cp.async.commit_group;");

    float m_i[2] = {-1e30f, -1e30f};
    float l_i[2] = {0.f, 0.f};
    float acc_o[16][4];
    #pragma unroll
    for (int nt = 0; nt < 16; nt++)
        #pragma unroll
        for (int v = 0; v < 4; v++) acc_o[nt][v] = 0.f;

    const int row0 = qb * 64 + wm + g;

    for (int kb = 0; kb <= qb; kb++) {
        const int cur = kb & 1;
        asm volatile("cp.async.wait_group 0;");
        __syncthreads();                       // tile kb ready; prev P/V consumed
        if (kb < qb) {                         // prefetch next tile during compute
            stageK(cur ^ 1, kb + 1);
            stageV(cur ^ 1, kb + 1);
            asm volatile("cp.async.commit_group;");
        }
        const float* Ks = Kb + cur * KTILE_F;
        const float* Vs = Vb + cur * VTILE_F;
        float* Ps = Kb + cur * KTILE_F;        // overlay (valid after barrier below)

        // ---- S = Q @ K^T (16x64 per warp) ----
        float acc_s[8][4];
        #pragma unroll
        for (int nt = 0; nt < 8; nt++)
            #pragma unroll
            for (int v = 0; v < 4; v++) acc_s[nt][v] = 0.f;

        #pragma unroll
        for (int ks = 0; ks < 24; ks++) {
            const int kb8 = ks * 8;
            uint32_t afr[4];
            afr[0] = __float_as_uint(Qs[(wm + g) * QP + kb8 + tl]);
            afr[1] = __float_as_uint(Qs[(wm + g + 8) * QP + kb8 + tl]);
            afr[2] = __float_as_uint(Qs[(wm + g) * QP + kb8 + tl + 4]);
            afr[3] = __float_as_uint(Qs[(wm + g + 8) * QP + kb8 + tl + 4]);
            #pragma unroll
            for (int nt = 0; nt < 8; nt++) {
                uint32_t bfr[2];
                bfr[0] = __float_as_uint(Ks[(nt * 8 + g) * QP + kb8 + tl]);
                bfr[1] = __float_as_uint(Ks[(nt * 8 + g) * QP + kb8 + tl + 4]);
                mma_tf32(acc_s[nt], afr, bfr);
            }
        }

        // ---- online softmax ----
        const bool diag = (kb == qb);
        float rmax0 = -1e30f, rmax1 = -1e30f;
        #pragma unroll
        for (int nt = 0; nt < 8; nt++) {
            int c0 = kb * 64 + nt * 8 + 2 * tl, c1 = c0 + 1;
            float s0 = acc_s[nt][0] * scale, s1 = acc_s[nt][1] * scale;
            float s2 = acc_s[nt][2] * scale, s3 = acc_s[nt][3] * scale;
            if (diag) {
                if (c0 > row0) s0 = -1e30f;
                if (c1 > row0) s1 = -1e30f;
                if (c0 > row0 + 8) s2 = -1e30f;
                if (c1 > row0 + 8) s3 = -1e30f;
            }
            acc_s[nt][0] = s0; acc_s[nt][1] = s1;
            acc_s[nt][2] = s2; acc_s[nt][3] = s3;
            rmax0 = fmaxf(rmax0, fmaxf(s0, s1));
            rmax1 = fmaxf(rmax1, fmaxf(s2, s3));
        }
        #pragma unroll
        for (int off = 1; off <= 2; off <<= 1) {
            rmax0 = fmaxf(rmax0, __shfl_xor_sync(0xffffffffu, rmax0, off));
            rmax1 = fmaxf(rmax1, __shfl_xor_sync(0xffffffffu, rmax1, off));
        }
        float mn0 = fmaxf(m_i[0], rmax0), mn1 = fmaxf(m_i[1], rmax1);
        float al0 = __expf(m_i[0] - mn0), al1 = __expf(m_i[1] - mn1);
        float p_r[8][4];
        float rs0 = 0.f, rs1 = 0.f;
        #pragma unroll
        for (int nt = 0; nt < 8; nt++) {
            p_r[nt][0] = __expf(acc_s[nt][0] - mn0);
            p_r[nt][1] = __expf(acc_s[nt][1] - mn0);
            p_r[nt][2] = __expf(acc_s[nt][2] - mn1);
            p_r[nt][3] = __expf(acc_s[nt][3] - mn1);
            rs0 += p_r[nt][0] + p_r[nt][1];
            rs1 += p_r[nt][2] + p_r[nt][3];
        }
        #pragma unroll
        for (int off = 1; off <= 2; off <<= 1) {
            rs0 += __shfl_xor_sync(0xffffffffu, rs0, off);
            rs1 += __shfl_xor_sync(0xffffffffu, rs1, off);
        }
        l_i[0] = l_i[0] * al0 + rs0;
        l_i[1] = l_i[1] * al1 + rs1;
        m_i[0] = mn0; m_i[1] = mn1;
        #pragma unroll
        for (int nt = 0; nt < 16; nt++) {
            acc_o[nt][0] *= al0; acc_o[nt][1] *= al0;
            acc_o[nt][2] *= al1; acc_o[nt][3] *= al1;
        }

        __syncthreads();   // ALL warps finished reading K before P overlays it
        #pragma unroll
        for (int nt = 0; nt < 8; nt++) {
            Ps[(wm + g) * PP + nt * 8 + 2 * tl]         = rtf(p_r[nt][0]);
            Ps[(wm + g) * PP + nt * 8 + 2 * tl + 1]     = rtf(p_r[nt][1]);
            Ps[(wm + g + 8) * PP + nt * 8 + 2 * tl]     = rtf(p_r[nt][2]);
            Ps[(wm + g + 8) * PP + nt * 8 + 2 * tl + 1] = rtf(p_r[nt][3]);
        }
        __syncwarp();      // own rows only -> warp-local visibility is enough

        // ---- O += P @ V (16x128 per warp) ----
        #pragma unroll
        for (int ks = 0; ks < 8; ks++) {
            const int kb8 = ks * 8;
            uint32_t afr[4];
            afr[0] = __float_as_uint(Ps[(wm + g) * PP + kb8 + tl]);
            afr[1] = __float_as_uint(Ps[(wm + g + 8) * PP + kb8 + tl]);
            afr[2] = __float_as_uint(Ps[(wm + g) * PP + kb8 + tl + 4]);
            afr[3] = __float_as_uint(Ps[(wm + g + 8) * PP + kb8 + tl + 4]);
            #pragma unroll
            for (int nt = 0; nt < 16; nt++) {
                uint32_t bfr[2];
                bfr[0] = __float_as_uint(Vs[(kb8 + tl) * VP + nt * 8 + g]);
                bfr[1] = __float_as_uint(Vs[(kb8 + tl + 4) * VP + nt * 8 + g]);
                mma_tf32(acc_o[nt], afr, bfr);
            }
        }
    }

    // ---- epilogue ----
    float inv0 = 1.0f / l_i[0], inv1 = 1.0f / l_i[1];
    size_t r0 = (bs0 + qb * 64 + wm + g) * 2048 + h * VHD;
    size_t r1 = r0 + 8 * 2048;
    #pragma unroll
    for (int nt = 0; nt < 16; nt++) {
        int cn = nt * 8 + 2 * tl;
        *(float2*)&g_attn[r0 + cn] =
            make_float2(rtf(acc_o[nt][0] * inv0), rtf(acc_o[nt][1] * inv0));
        *(float2*)&g_attn[r1 + cn] =
            make_float2(rtf(acc_o[nt][2] * inv1), rtf(acc_o[nt][3] * inv1));
    }
}

// ---------------- launch ----------------
extern "C" void kernel_launch(void* const* d_in, const int* in_sizes, int n_in,
                              void* d_out, int out_size) {
    const float* hs      = (const float*)d_in[0];
    const int*   pos     = (const int*)  d_in[1];
    const float* wq_a    = (const float*)d_in[2];
    const float* q_a_ln  = (const float*)d_in[3];
    const float* wq_b    = (const float*)d_in[4];
    const float* wkv_a   = (const float*)d_in[5];
    const float* kv_a_ln = (const float*)d_in[6];
    const float* wkv_b   = (const float*)d_in[7];
    const float* wo      = (const float*)d_in[8];
    float* out = (float*)d_out;

    float *qlora, *q, *ckv, *cnorm, *kv, *kpe, *attn;
    float *hs_t, *wqa_t, *wqb_t, *wkva_t, *wkvb_t, *wo_t;
    cudaGetSymbolAddress((void**)&qlora, g_qlora);
    cudaGetSymbolAddress((void**)&q,     g_q);
    cudaGetSymbolAddress((void**)&ckv,   g_ckv);
    cudaGetSymbolAddress((void**)&cnorm, g_cnorm);
    cudaGetSymbolAddress((void**)&kv,    g_kv);
    cudaGetSymbolAddress((void**)&kpe,   g_kpe);
    cudaGetSymbolAddress((void**)&attn,  g_attn);
    cudaGetSymbolAddress((void**)&hs_t,  g_hs_t);
    cudaGetSymbolAddress((void**)&wqa_t, g_wqa_t);
    cudaGetSymbolAddress((void**)&wqb_t, g_wqb_t);
    cudaGetSymbolAddress((void**)&wkva_t,g_wkva_t);
    cudaGetSymbolAddress((void**)&wkvb_t,g_wkvb_t);
    cudaGetSymbolAddress((void**)&wo_t,  g_wo_t);

    double m = 0.1 * log(40.0) + 1.0;
    float scale = (float)((1.0 / sqrt(192.0)) * m * m);

    cudaFuncSetAttribute(flash_tf32, cudaFuncAttributeMaxDynamicSharedMemorySize,
                         FLASH_SMEM);
    cudaFuncSetAttribute(gemm_tf32, cudaFuncAttributeMaxDynamicSharedMemorySize,
                         GEMM_SMEM);

    dim3 blk(256);
    auto cvtn = [&](const float* x, float* y, size_t n) {
        cvt_tf32_k<<<(int)((n / 4 + 255) / 256), 256>>>(x, y, (int)n);
    };
    cvtn(hs,    hs_t,   (size_t)ROWS * 2048);
    cvtn(wq_a,  wqa_t,  (size_t)1536 * 2048);
    cvtn(wq_b,  wqb_t,  (size_t)3072 * 1536);
    cvtn(wkv_a, wkva_t, (size_t)576 * 2048);
    cvtn(wkv_b, wkvb_t, (size_t)4096 * 512);
    cvtn(wo,    wo_t,   (size_t)2048 * 2048);

    // q path
    gemm_tf32<<<dim3(1536 / 128, ROWS / 128), blk, GEMM_SMEM>>>(hs_t, wqa_t, qlora, ROWS, 1536, 2048, 0);
    rmsnorm_k<<<ROWS, 256>>>(qlora, q_a_ln, qlora, 1536, 1536, 1536);
    gemm_tf32<<<dim3(3072 / 128, ROWS / 128), blk, GEMM_SMEM>>>(qlora, wqb_t, q, ROWS, 3072, 1536, 1);
    // kv path
    gemm_tf32<<<dim3((576 + 127) / 128, ROWS / 128), blk, GEMM_SMEM>>>(hs_t, wkva_t, ckv, ROWS, 576, 2048, 0);
    rmsnorm_k<<<ROWS, 256>>>(ckv, kv_a_ln, cnorm, 512, 576, 512);
    gemm_tf32<<<dim3(4096 / 128, ROWS / 128), blk, GEMM_SMEM>>>(cnorm, wkvb_t, kv, ROWS, 4096, 512, 1);
    // rope (rounds q_pe in place + k_pe)
    rope_k<<<ROWS, 544>>>(pos);
    // attention
    flash_tf32<<<dim3(SEQ / 64, NHEADS, BATCH), 128, FLASH_SMEM>>>(scale);
    // output projection
    gemm_tf32<<<dim3(2048 / 128, ROWS / 128), blk, GEMM_SMEM>>>(attn, wo_t, out, ROWS, 2048, 2048, 0);
}

// round 8
// speedup vs baseline: 5.1566x; 1.0429x over previous
#include <cuda_runtime.h>
#include <math.h>
#include <stdint.h>

#define SEQ 2048
#define BATCH 2
#define ROWS (BATCH*SEQ)   // 4096
#define NHEADS 16
#define QHD 192
#define NOPE 128
#define VHD 128

// ---------------- scratch (device globals; no allocation allowed) ----------------
__device__ float g_qab [(size_t)ROWS*2112];    // combined [qlora(1536) | ckv(512) | kpe(64)]
__device__ float g_qlora[(size_t)ROWS*1536];
__device__ float g_q[(size_t)ROWS*3072];
__device__ float g_cnorm[(size_t)ROWS*512];
__device__ float g_kv[(size_t)ROWS*4096];
__device__ float g_kpe[(size_t)ROWS*64];
__device__ float g_attn[(size_t)ROWS*2048];
// tf32-rounded copies
__device__ float g_hs_t [(size_t)ROWS*2048];
__device__ float g_wab_t[(size_t)2112*2048];   // [wq_a(1536) ; wkv_a(576)]
__device__ float g_wqb_t[(size_t)3072*1536];
__device__ float g_wkvb_t[(size_t)4096*512];
__device__ float g_wo_t [(size_t)2048*2048];

__device__ __forceinline__ uint32_t f2tf32(float f) {
    uint32_t u;
    asm("cvt.rna.tf32.f32 %0, %1;" : "=r"(u) : "f"(f));
    return u;
}
__device__ __forceinline__ float rtf(float f) { return __uint_as_float(f2tf32(f)); }

__device__ __forceinline__ void mma_tf32(float d[4], const uint32_t a[4],
                                         const uint32_t b[2]) {
    asm volatile(
        "mma.sync.aligned.m16n8k8.row.col.f32.tf32.tf32.f32 "
        "{%0,%1,%2,%3}, {%4,%5,%6,%7}, {%8,%9}, {%0,%1,%2,%3};"
        : "+f"(d[0]), "+f"(d[1]), "+f"(d[2]), "+f"(d[3])
        : "r"(a[0]), "r"(a[1]), "r"(a[2]), "r"(a[3]), "r"(b[0]), "r"(b[1]));
}

__device__ __forceinline__ void cp_async16(uint32_t saddr, const void* gptr, bool pred) {
    int sz = pred ? 16 : 0;
    asm volatile("cp.async.cg.shared.global [%0], [%1], 16, %2;\n"
                 :: "r"(saddr), "l"(gptr), "r"(sz));
}

// ---------------- elementwise tf32 rounding copy ----------------
__global__ __launch_bounds__(256) void cvt_tf32_k(const float* __restrict__ x,
                                                  float* __restrict__ y, int n) {
    int i = (blockIdx.x * 256 + threadIdx.x) * 4;
    if (i < n) {
        float4 v = *(const float4*)(x + i);
        v.x = rtf(v.x); v.y = rtf(v.y); v.z = rtf(v.z); v.w = rtf(v.w);
        *(float4*)(y + i) = v;
    }
}

// ==================================================================
// TF32 GEMM: C[M,N] = A[M,K] @ B[N,K]^T
// 128x128 block tile, BK=32, 3-stage cp.async ring, 128 threads
// (4 warps, 2x2), warp tile 64x64 (4 m16 x 8 n8). One barrier/chunk.
// ==================================================================
#define APITCH 36
#define TILE_F (128*APITCH)
#define GEMM_SMEM (6*TILE_F*4)   // 110,592 B

__global__ __launch_bounds__(128, 2) void gemm_tf32(const float* __restrict__ A,
                                                    const float* __restrict__ B,
                                                    float* __restrict__ C,
                                                    int M, int N, int K, int roundC) {
    extern __shared__ float sm_[];
    float* As = sm_;
    float* Bs = sm_ + 3 * TILE_F;
    const int tid = threadIdx.x;
    const int warp = tid >> 5, lane = tid & 31;
    const int wm = (warp & 1) * 64, wn = (warp >> 1) * 64;
    const int g = lane >> 2, tl = lane & 3;
    const int m0 = blockIdx.y * 128, n0 = blockIdx.x * 128;

    float acc[4][8][4];
    #pragma unroll
    for (int i = 0; i < 4; i++)
        #pragma unroll
        for (int j = 0; j < 8; j++)
            #pragma unroll
            for (int v = 0; v < 4; v++) acc[i][j][v] = 0.f;

    const int T = K / 32;

    auto issue = [&](int stage, int t) {
        const int k0 = t * 32;
        uint32_t ab = (uint32_t)__cvta_generic_to_shared(As + stage * TILE_F);
        uint32_t bb = (uint32_t)__cvta_generic_to_shared(Bs + stage * TILE_F);
        #pragma unroll
        for (int u = 0; u < 8; u++) {
            int seg = tid + u * 128;
            int row = seg >> 3, kq = (seg & 7) * 4;
            cp_async16(ab + (row * APITCH + kq) * 4,
                       A + (size_t)(m0 + row) * K + k0 + kq, true);
            int nr = n0 + row;
            cp_async16(bb + (row * APITCH + kq) * 4,
                       B + (size_t)(nr < N ? nr : 0) * K + k0 + kq, nr < N);
        }
        asm volatile("cp.async.commit_group;");
    };

    issue(0, 0);
    if (T > 1) issue(1, 1); else asm volatile("cp.async.commit_group;");

    for (int t = 0; t < T; t++) {
        asm volatile("cp.async.wait_group 1;");
        __syncthreads();            // tile t ready AND all warps done with t-1
        if (t + 2 < T) issue((t + 2) % 3, t + 2);
        else asm volatile("cp.async.commit_group;");

        const float* Ab = As + (t % 3) * TILE_F;
        const float* Bb = Bs + (t % 3) * TILE_F;
        #pragma unroll
        for (int ks = 0; ks < 4; ks++) {
            const int kb = ks * 8;
            uint32_t afr[4][4], bfr[8][2];
            #pragma unroll
            for (int mt = 0; mt < 4; mt++) {
                int rb = wm + mt * 16 + g;
                afr[mt][0] = __float_as_uint(Ab[rb * APITCH + kb + tl]);
                afr[mt][1] = __float_as_uint(Ab[(rb + 8) * APITCH + kb + tl]);
                afr[mt][2] = __float_as_uint(Ab[rb * APITCH + kb + tl + 4]);
                afr[mt][3] = __float_as_uint(Ab[(rb + 8) * APITCH + kb + tl + 4]);
            }
            #pragma unroll
            for (int nt = 0; nt < 8; nt++) {
                int cb = wn + nt * 8 + g;
                bfr[nt][0] = __float_as_uint(Bb[cb * APITCH + kb + tl]);
                bfr[nt][1] = __float_as_uint(Bb[cb * APITCH + kb + tl + 4]);
            }
            #pragma unroll
            for (int mt = 0; mt < 4; mt++)
                #pragma unroll
                for (int nt = 0; nt < 8; nt++)
                    mma_tf32(acc[mt][nt], afr[mt], bfr[nt]);
        }
        // no bottom barrier: next-iter top barrier orders reuse (ring distance 3)
    }

    #pragma unroll
    for (int mt = 0; mt < 4; mt++) {
        int r0 = m0 + wm + mt * 16 + g;
        #pragma unroll
        for (int nt = 0; nt < 8; nt++) {
            int cn = n0 + wn + nt * 8 + 2 * tl;
            if (cn < N) {
                float v0 = acc[mt][nt][0], v1 = acc[mt][nt][1];
                float v2 = acc[mt][nt][2], v3 = acc[mt][nt][3];
                if (roundC) { v0 = rtf(v0); v1 = rtf(v1); v2 = rtf(v2); v3 = rtf(v3); }
                *(float2*)&C[(size_t)r0 * N + cn]       = make_float2(v0, v1);
                *(float2*)&C[(size_t)(r0 + 8) * N + cn] = make_float2(v2, v3);
            }
        }
    }
}

// ---------------- RMSNorm (writes tf32-rounded output) ----------------
__global__ __launch_bounds__(256) void rmsnorm_k(const float* __restrict__ X,
                                                 const float* __restrict__ w,
                                                 float* __restrict__ Y,
                                                 int W, int ldx, int ldy) {
    int row = blockIdx.x;
    const float* x = X + (size_t)row * ldx;
    float ss = 0.f;
    for (int i = threadIdx.x; i < W; i += 256) { float v = x[i]; ss += v * v; }
    __shared__ float red[256];
    red[threadIdx.x] = ss;
    __syncthreads();
    for (int s = 128; s > 0; s >>= 1) {
        if (threadIdx.x < s) red[threadIdx.x] += red[threadIdx.x + s];
        __syncthreads();
    }
    float inv = rsqrtf(red[0] / (float)W + 1e-6f);
    float* y = Y + (size_t)row * ldy;
    for (int i = threadIdx.x; i < W; i += 256) y[i] = rtf(w[i] * (x[i] * inv));
}

// ---------------- YaRN RoPE (reads combined buffer; tf32-rounded out) ----------------
__global__ __launch_bounds__(544) void rope_k(const int* __restrict__ pos_ids) {
    int row = blockIdx.x;
    int t = threadIdx.x;
    int h = t >> 5, j = t & 31;
    float pos = (float)pos_ids[row];
    float fe = powf(10000.0f, -(float)j / 32.0f);
    float ramp = fminf(fmaxf(((float)j - 10.0f) / 13.0f, 0.f), 1.f);
    float invf = (fe / 40.0f) * ramp + fe * (1.0f - ramp);
    float ang = pos * invf;
    float s, c;
    sincosf(ang, &s, &c);
    if (h < NHEADS) {
        float* base = g_q + (size_t)row * 3072 + h * QHD + NOPE;
        float x0 = base[2 * j], x1 = base[2 * j + 1];
        __syncwarp();
        base[j]      = rtf(x0 * c - x1 * s);
        base[32 + j] = rtf(x1 * c + x0 * s);
    } else {
        const float* src = g_qab + (size_t)row * 2112 + 2048;   // k_pe slice
        float x0 = src[2 * j], x1 = src[2 * j + 1];
        float* dst = g_kpe + (size_t)row * 64;
        dst[j]      = rtf(x0 * c - x1 * s);
        dst[32 + j] = rtf(x1 * c + x0 * s);
    }
}

// ==================================================================
// Flash attention, tf32 tensor cores, cp.async double-buffered K/V.
// ==================================================================
#define QP 196
#define VP 136
#define PP 68
#define KTILE_F (64*QP)
#define VTILE_F (64*VP)
#define FLASH_SMEM ((64*QP + 2*KTILE_F + 2*VTILE_F) * 4)   // 220,160 B

__global__ __launch_bounds__(128) void flash_tf32(float scale) {
    extern __shared__ float sm[];
    float* Qs  = sm;                       // [64][QP]
    float* Kb  = sm + 64 * QP;             // [2][64][QP]  (P overlays current)
    float* Vb  = Kb + 2 * KTILE_F;         // [2][64][VP]
    const int qb = blockIdx.x, h = blockIdx.y, b = blockIdx.z;
    const int tid = threadIdx.x;
    const int warp = tid >> 5, lane = tid & 31;
    const int g = lane >> 2, tl = lane & 3;
    const int wm = warp * 16;
    const size_t bs0 = (size_t)b * SEQ;

    const uint32_t qs_s = (uint32_t)__cvta_generic_to_shared(Qs);
    const uint32_t kb_s = (uint32_t)__cvta_generic_to_shared(Kb);
    const uint32_t vb_s = (uint32_t)__cvta_generic_to_shared(Vb);

    auto stageK = [&](int buf, int kb) {
        uint32_t base = kb_s + (uint32_t)(buf * KTILE_F * 4);
        #pragma unroll
        for (int u = 0; u < 24; u++) {
            int idx = tid + u * 128;
            int r = idx / 48, q = idx % 48;
            const float* src = (q < 32)
                ? &g_kv[(bs0 + kb * 64 + r) * 4096 + h * 256 + q * 4]
                : &g_kpe[(bs0 + kb * 64 + r) * 64 + (q - 32) * 4];
            cp_async16(base + (r * QP + q * 4) * 4, src, true);
        }
    };
    auto stageV = [&](int buf, int kb) {
        uint32_t base = vb_s + (uint32_t)(buf * VTILE_F * 4);
        #pragma unroll
        for (int u = 0; u < 16; u++) {
            int idx = tid + u * 128;
            int r = idx >> 5, q4 = (idx & 31) * 4;
            cp_async16(base + (r * VP + q4) * 4,
                       &g_kv[(bs0 + kb * 64 + r) * 4096 + h * 256 + NOPE + q4], true);
        }
    };

    #pragma unroll
    for (int u = 0; u < 24; u++) {
        int idx = tid + u * 128;
        int r = idx / 48, q4 = (idx % 48) * 4;
        cp_async16(qs_s + (r * QP + q4) * 4,
                   &g_q[(bs0 + qb * 64 + r) * 3072 + h * QHD + q4], true);
    }
    stageK(0, 0);
    stageV(0, 0);
    asm volatile("cp.async.commit_group;");

    float m_i[2] = {-1e30f, -1e30f};
    float l_i[2] = {0.f, 0.f};
    float acc_o[16][4];
    #pragma unroll
    for (int nt = 0; nt < 16; nt++)
        #pragma unroll
        for (int v = 0; v < 4; v++) acc_o[nt][v] = 0.f;

    const int row0 = qb * 64 + wm + g;

    for (int kb = 0; kb <= qb; kb++) {
        const int cur = kb & 1;
        asm volatile("cp.async.wait_group 0;");
        __syncthreads();
        if (kb < qb) {
            stageK(cur ^ 1, kb + 1);
            stageV(cur ^ 1, kb + 1);
            asm volatile("cp.async.commit_group;");
        }
        const float* Ks = Kb + cur * KTILE_F;
        const float* Vs = Vb + cur * VTILE_F;
        float* Ps = Kb + cur * KTILE_F;

        float acc_s[8][4];
        #pragma unroll
        for (int nt = 0; nt < 8; nt++)
            #pragma unroll
            for (int v = 0; v < 4; v++) acc_s[nt][v] = 0.f;

        #pragma unroll
        for (int ks = 0; ks < 24; ks++) {
            const int kb8 = ks * 8;
            uint32_t afr[4];
            afr[0] = __float_as_uint(Qs[(wm + g) * QP + kb8 + tl]);
            afr[1] = __float_as_uint(Qs[(wm + g + 8) * QP + kb8 + tl]);
            afr[2] = __float_as_uint(Qs[(wm + g) * QP + kb8 + tl + 4]);
            afr[3] = __float_as_uint(Qs[(wm + g + 8) * QP + kb8 + tl + 4]);
            #pragma unroll
            for (int nt = 0; nt < 8; nt++) {
                uint32_t bfr[2];
                bfr[0] = __float_as_uint(Ks[(nt * 8 + g) * QP + kb8 + tl]);
                bfr[1] = __float_as_uint(Ks[(nt * 8 + g) * QP + kb8 + tl + 4]);
                mma_tf32(acc_s[nt], afr, bfr);
            }
        }

        const bool diag = (kb == qb);
        float rmax0 = -1e30f, rmax1 = -1e30f;
        #pragma unroll
        for (int nt = 0; nt < 8; nt++) {
            int c0 = kb * 64 + nt * 8 + 2 * tl, c1 = c0 + 1;
            float s0 = acc_s[nt][0] * scale, s1 = acc_s[nt][1] * scale;
            float s2 = acc_s[nt][2] * scale, s3 = acc_s[nt][3] * scale;
            if (diag) {
                if (c0 > row0) s0 = -1e30f;
                if (c1 > row0) s1 = -1e30f;
                if (c0 > row0 + 8) s2 = -1e30f;
                if (c1 > row0 + 8) s3 = -1e30f;
            }
            acc_s[nt][0] = s0; acc_s[nt][1] = s1;
            acc_s[nt][2] = s2; acc_s[nt][3] = s3;
            rmax0 = fmaxf(rmax0, fmaxf(s0, s1));
            rmax1 = fmaxf(rmax1, fmaxf(s2, s3));
        }
        #pragma unroll
        for (int off = 1; off <= 2; off <<= 1) {
            rmax0 = fmaxf(rmax0, __shfl_xor_sync(0xffffffffu, rmax0, off));
            rmax1 = fmaxf(rmax1, __shfl_xor_sync(0xffffffffu, rmax1, off));
        }
        float mn0 = fmaxf(m_i[0], rmax0), mn1 = fmaxf(m_i[1], rmax1);
        float al0 = __expf(m_i[0] - mn0), al1 = __expf(m_i[1] - mn1);
        float p_r[8][4];
        float rs0 = 0.f, rs1 = 0.f;
        #pragma unroll
        for (int nt = 0; nt < 8; nt++) {
            p_r[nt][0] = __expf(acc_s[nt][0] - mn0);
            p_r[nt][1] = __expf(acc_s[nt][1] - mn0);
            p_r[nt][2] = __expf(acc_s[nt][2] - mn1);
            p_r[nt][3] = __expf(acc_s[nt][3] - mn1);
            rs0 += p_r[nt][0] + p_r[nt][1];
            rs1 += p_r[nt][2] + p_r[nt][3];
        }
        #pragma unroll
        for (int off = 1; off <= 2; off <<= 1) {
            rs0 += __shfl_xor_sync(0xffffffffu, rs0, off);
            rs1 += __shfl_xor_sync(0xffffffffu, rs1, off);
        }
        l_i[0] = l_i[0] * al0 + rs0;
        l_i[1] = l_i[1] * al1 + rs1;
        m_i[0] = mn0; m_i[1] = mn1;
        #pragma unroll
        for (int nt = 0; nt < 16; nt++) {
            acc_o[nt][0] *= al0; acc_o[nt][1] *= al0;
            acc_o[nt][2] *= al1; acc_o[nt][3] *= al1;
        }

        __syncthreads();
        #pragma unroll
        for (int nt = 0; nt < 8; nt++) {
            Ps[(wm + g) * PP + nt * 8 + 2 * tl]         = rtf(p_r[nt][0]);
            Ps[(wm + g) * PP + nt * 8 + 2 * tl + 1]     = rtf(p_r[nt][1]);
            Ps[(wm + g + 8) * PP + nt * 8 + 2 * tl]     = rtf(p_r[nt][2]);
            Ps[(wm + g + 8) * PP + nt * 8 + 2 * tl + 1] = rtf(p_r[nt][3]);
        }
        __syncwarp();

        #pragma unroll
        for (int ks = 0; ks < 8; ks++) {
            const int kb8 = ks * 8;
            uint32_t afr[4];
            afr[0] = __float_as_uint(Ps[(wm + g) * PP + kb8 + tl]);
            afr[1] = __float_as_uint(Ps[(wm + g + 8) * PP + kb8 + tl]);
            afr[2] = __float_as_uint(Ps[(wm + g) * PP + kb8 + tl + 4]);
            afr[3] = __float_as_uint(Ps[(wm + g + 8) * PP + kb8 + tl + 4]);
            #pragma unroll
            for (int nt = 0; nt < 16; nt++) {
                uint32_t bfr[2];
                bfr[0] = __float_as_uint(Vs[(kb8 + tl) * VP + nt * 8 + g]);
                bfr[1] = __float_as_uint(Vs[(kb8 + tl + 4) * VP + nt * 8 + g]);
                mma_tf32(acc_o[nt], afr, bfr);
            }
        }
    }

    float inv0 = 1.0f / l_i[0], inv1 = 1.0f / l_i[1];
    size_t r0 = (bs0 + qb * 64 + wm + g) * 2048 + h * VHD;
    size_t r1 = r0 + 8 * 2048;
    #pragma unroll
    for (int nt = 0; nt < 16; nt++) {
        int cn = nt * 8 + 2 * tl;
        *(float2*)&g_attn[r0 + cn] =
            make_float2(rtf(acc_o[nt][0] * inv0), rtf(acc_o[nt][1] * inv0));
        *(float2*)&g_attn[r1 + cn] =
            make_float2(rtf(acc_o[nt][2] * inv1), rtf(acc_o[nt][3] * inv1));
    }
}

// ---------------- launch ----------------
extern "C" void kernel_launch(void* const* d_in, const int* in_sizes, int n_in,
                              void* d_out, int out_size) {
    const float* hs      = (const float*)d_in[0];
    const int*   pos     = (const int*)  d_in[1];
    const float* wq_a    = (const float*)d_in[2];
    const float* q_a_ln  = (const float*)d_in[3];
    const float* wq_b    = (const float*)d_in[4];
    const float* wkv_a   = (const float*)d_in[5];
    const float* kv_a_ln = (const float*)d_in[6];
    const float* wkv_b   = (const float*)d_in[7];
    const float* wo      = (const float*)d_in[8];
    float* out = (float*)d_out;

    float *qab, *qlora, *q, *cnorm, *kv, *kpe, *attn;
    float *hs_t, *wab_t, *wqb_t, *wkvb_t, *wo_t;
    cudaGetSymbolAddress((void**)&qab,   g_qab);
    cudaGetSymbolAddress((void**)&qlora, g_qlora);
    cudaGetSymbolAddress((void**)&q,     g_q);
    cudaGetSymbolAddress((void**)&cnorm, g_cnorm);
    cudaGetSymbolAddress((void**)&kv,    g_kv);
    cudaGetSymbolAddress((void**)&kpe,   g_kpe);
    cudaGetSymbolAddress((void**)&attn,  g_attn);
    cudaGetSymbolAddress((void**)&hs_t,  g_hs_t);
    cudaGetSymbolAddress((void**)&wab_t, g_wab_t);
    cudaGetSymbolAddress((void**)&wqb_t, g_wqb_t);
    cudaGetSymbolAddress((void**)&wkvb_t,g_wkvb_t);
    cudaGetSymbolAddress((void**)&wo_t,  g_wo_t);

    double m = 0.1 * log(40.0) + 1.0;
    float scale = (float)((1.0 / sqrt(192.0)) * m * m);

    cudaFuncSetAttribute(flash_tf32, cudaFuncAttributeMaxDynamicSharedMemorySize,
                         FLASH_SMEM);
    cudaFuncSetAttribute(gemm_tf32, cudaFuncAttributeMaxDynamicSharedMemorySize,
                         GEMM_SMEM);

    auto cvtn = [&](const float* x, float* y, size_t n) {
        cvt_tf32_k<<<(int)((n / 4 + 255) / 256), 256>>>(x, y, (int)n);
    };
    cvtn(hs,    hs_t,   (size_t)ROWS * 2048);
    cvtn(wq_a,  wab_t,               (size_t)1536 * 2048);
    cvtn(wkv_a, wab_t + (size_t)1536 * 2048, (size_t)576 * 2048);
    cvtn(wq_b,  wqb_t,  (size_t)3072 * 1536);
    cvtn(wkv_b, wkvb_t, (size_t)4096 * 512);
    cvtn(wo,    wo_t,   (size_t)2048 * 2048);

    dim3 blk(128);
    // combined: [qlora | ckv] = hs @ [wq_a ; wkv_a]^T   (N=2112)
    gemm_tf32<<<dim3((2112 + 127) / 128, ROWS / 128), blk, GEMM_SMEM>>>(
        hs_t, wab_t, qab, ROWS, 2112, 2048, 0);
    // rmsnorm q_lora (cols 0..1535) and compressed kv (cols 1536..2047)
    rmsnorm_k<<<ROWS, 256>>>(qab,        q_a_ln,  qlora, 1536, 2112, 1536);
    rmsnorm_k<<<ROWS, 256>>>(qab + 1536, kv_a_ln, cnorm, 512,  2112, 512);
    // q = qlora_n @ wq_b^T
    gemm_tf32<<<dim3(3072 / 128, ROWS / 128), blk, GEMM_SMEM>>>(
        qlora, wqb_t, q, ROWS, 3072, 1536, 1);
    // kv = cnorm @ wkv_b^T
    gemm_tf32<<<dim3(4096 / 128, ROWS / 128), blk, GEMM_SMEM>>>(
        cnorm, wkvb_t, kv, ROWS, 4096, 512, 1);
    // rope (q_pe in place on g_q; k_pe from combined buffer -> g_kpe)
    rope_k<<<ROWS, 544>>>(pos);
    // attention
    flash_tf32<<<dim3(SEQ / 64, NHEADS, BATCH), 128, FLASH_SMEM>>>(scale);
    // out = attn @ wo^T
    gemm_tf32<<<dim3(2048 / 128, ROWS / 128), blk, GEMM_SMEM>>>(
        attn, wo_t, out, ROWS, 2048, 2048, 0);
}

// round 10
// speedup vs baseline: 5.1639x; 1.0014x over previous
#include <cuda_runtime.h>
#include <math.h>
#include <stdint.h>

#define SEQ 2048
#define BATCH 2
#define ROWS (BATCH*SEQ)   // 4096
#define NHEADS 16
#define QHD 192
#define NOPE 128
#define VHD 128

// ---------------- scratch (device globals; no allocation allowed) ----------------
__device__ float g_qab [(size_t)ROWS*2112];    // [qlora(1536) | ckv(512) | kpe(64)]
__device__ float g_qlora[(size_t)ROWS*1536];
__device__ float g_q[(size_t)ROWS*3072];
__device__ float g_cnorm[(size_t)ROWS*512];
__device__ float g_kv[(size_t)ROWS*4096];
__device__ float g_kpe[(size_t)ROWS*64];
__device__ float g_attn[(size_t)ROWS*2048];
// tf32-rounded copies
__device__ float g_hs_t [(size_t)ROWS*2048];
__device__ float g_wab_t[(size_t)2112*2048];   // [wq_a(1536) ; wkv_a(576)]
__device__ float g_wqb_t[(size_t)3072*1536];
__device__ float g_wkvb_t[(size_t)4096*512];
__device__ float g_wo_t [(size_t)2048*2048];

__device__ __forceinline__ uint32_t f2tf32(float f) {
    uint32_t u;
    asm("cvt.rna.tf32.f32 %0, %1;" : "=r"(u) : "f"(f));
    return u;
}
__device__ __forceinline__ float rtf(float f) { return __uint_as_float(f2tf32(f)); }

__device__ __forceinline__ void mma_tf32(float d[4], const uint32_t a[4],
                                         const uint32_t b[2]) {
    asm volatile(
        "mma.sync.aligned.m16n8k8.row.col.f32.tf32.tf32.f32 "
        "{%0,%1,%2,%3}, {%4,%5,%6,%7}, {%8,%9}, {%0,%1,%2,%3};"
        : "+f"(d[0]), "+f"(d[1]), "+f"(d[2]), "+f"(d[3])
        : "r"(a[0]), "r"(a[1]), "r"(a[2]), "r"(a[3]), "r"(b[0]), "r"(b[1]));
}

__device__ __forceinline__ void cp_async16(uint32_t saddr, const void* gptr, bool pred) {
    int sz = pred ? 16 : 0;
    asm volatile("cp.async.cg.shared.global [%0], [%1], 16, %2;\n"
                 :: "r"(saddr), "l"(gptr), "r"(sz));
}

// ---------------- elementwise tf32 rounding copy ----------------
__global__ __launch_bounds__(256) void cvt_tf32_k(const float* __restrict__ x,
                                                  float* __restrict__ y, int n) {
    int i = (blockIdx.x * 256 + threadIdx.x) * 4;
    if (i < n) {
        float4 v = *(const float4*)(x + i);
        v.x = rtf(v.x); v.y = rtf(v.y); v.z = rtf(v.z); v.w = rtf(v.w);
        *(float4*)(y + i) = v;
    }
}

// ==================================================================
// TF32 GEMM: C[M,N] = A[M,K] @ B[N,K]^T
// 256x128 block tile, BK=32, 3-stage cp.async ring, 256 threads
// (8 warps as 4m x 2n, each 64x64). Halves smem LDS bytes per MAC
// vs a 128x128 tile. M % 256 == 0, K % 32 == 0; N guarded.
// ==================================================================
#define APITCH 36
#define AT_F (256*APITCH)
#define BT_F (128*APITCH)
#define ST_F (AT_F + BT_F)
#define GEMM_SMEM (3*ST_F*4)   // 165,888 B

__global__ __launch_bounds__(256, 1) void gemm_tf32(const float* __restrict__ A,
                                                    const float* __restrict__ B,
                                                    float* __restrict__ C,
                                                    int M, int N, int K, int roundC) {
    extern __shared__ float sm_[];
    const int tid = threadIdx.x;
    const int warp = tid >> 5, lane = tid & 31;
    const int wm = (warp & 3) * 64, wn = (warp >> 2) * 64;
    const int g = lane >> 2, tl = lane & 3;
    const int m0 = blockIdx.y * 256, n0 = blockIdx.x * 128;

    float acc[4][8][4];
    #pragma unroll
    for (int i = 0; i < 4; i++)
        #pragma unroll
        for (int j = 0; j < 8; j++)
            #pragma unroll
            for (int v = 0; v < 4; v++) acc[i][j][v] = 0.f;

    const int T = K / 32;

    auto issue = [&](int stage, int t) {
        const int k0 = t * 32;
        uint32_t ab = (uint32_t)__cvta_generic_to_shared(sm_ + stage * ST_F);
        uint32_t bb = ab + AT_F * 4;
        #pragma unroll
        for (int u = 0; u < 8; u++) {          // A: 256 rows x 8 granules
            int seg = tid + u * 256;
            int row = seg >> 3, kq = (seg & 7) * 4;
            cp_async16(ab + (row * APITCH + kq) * 4,
                       A + (size_t)(m0 + row) * K + k0 + kq, true);
        }
        #pragma unroll
        for (int u = 0; u < 4; u++) {          // B: 128 rows x 8 granules
            int seg = tid + u * 256;
            int row = seg >> 3, kq = (seg & 7) * 4;
            int nr = n0 + row;
            cp_async16(bb + (row * APITCH + kq) * 4,
                       B + (size_t)(nr < N ? nr : 0) * K + k0 + kq, nr < N);
        }
        asm volatile("cp.async.commit_group;");
    };

    issue(0, 0);
    if (T > 1) issue(1, 1); else asm volatile("cp.async.commit_group;");

    for (int t = 0; t < T; t++) {
        asm volatile("cp.async.wait_group 1;");
        __syncthreads();            // tile t ready AND all warps done with t-1
        if (t + 2 < T) issue((t + 2) % 3, t + 2);
        else asm volatile("cp.async.commit_group;");

        const float* Ab = sm_ + (t % 3) * ST_F;
        const float* Bb = Ab + AT_F;
        #pragma unroll
        for (int ks = 0; ks < 4; ks++) {
            const int kb = ks * 8;
            uint32_t afr[4][4], bfr[8][2];
            #pragma unroll
            for (int mt = 0; mt < 4; mt++) {
                int rb = wm + mt * 16 + g;
                afr[mt][0] = __float_as_uint(Ab[rb * APITCH + kb + tl]);
                afr[mt][1] = __float_as_uint(Ab[(rb + 8) * APITCH + kb + tl]);
                afr[mt][2] = __float_as_uint(Ab[rb * APITCH + kb + tl + 4]);
                afr[mt][3] = __float_as_uint(Ab[(rb + 8) * APITCH + kb + tl + 4]);
            }
            #pragma unroll
            for (int nt = 0; nt < 8; nt++) {
                int cb = wn + nt * 8 + g;
                bfr[nt][0] = __float_as_uint(Bb[cb * APITCH + kb + tl]);
                bfr[nt][1] = __float_as_uint(Bb[cb * APITCH + kb + tl + 4]);
            }
            #pragma unroll
            for (int mt = 0; mt < 4; mt++)
                #pragma unroll
                for (int nt = 0; nt < 8; nt++)
                    mma_tf32(acc[mt][nt], afr[mt], bfr[nt]);
        }
        // no bottom barrier: next-iter top barrier orders reuse (ring distance 3)
    }

    #pragma unroll
    for (int mt = 0; mt < 4; mt++) {
        int r0 = m0 + wm + mt * 16 + g;
        #pragma unroll
        for (int nt = 0; nt < 8; nt++) {
            int cn = n0 + wn + nt * 8 + 2 * tl;
            if (cn < N) {
                float v0 = acc[mt][nt][0], v1 = acc[mt][nt][1];
                float v2 = acc[mt][nt][2], v3 = acc[mt][nt][3];
                if (roundC) { v0 = rtf(v0); v1 = rtf(v1); v2 = rtf(v2); v3 = rtf(v3); }
                *(float2*)&C[(size_t)r0 * N + cn]       = make_float2(v0, v1);
                *(float2*)&C[(size_t)(r0 + 8) * N + cn] = make_float2(v2, v3);
            }
        }
    }
}

// ---------------- RMSNorm (writes tf32-rounded output) ----------------
__global__ __launch_bounds__(256) void rmsnorm_k(const float* __restrict__ X,
                                                 const float* __restrict__ w,
                                                 float* __restrict__ Y,
                                                 int W, int ldx, int ldy) {
    int row = blockIdx.x;
    const float* x = X + (size_t)row * ldx;
    float ss = 0.f;
    for (int i = threadIdx.x; i < W; i += 256) { float v = x[i]; ss += v * v; }
    __shared__ float red[256];
    red[threadIdx.x] = ss;
    __syncthreads();
    for (int s = 128; s > 0; s >>= 1) {
        if (threadIdx.x < s) red[threadIdx.x] += red[threadIdx.x + s];
        __syncthreads();
    }
    float inv = rsqrtf(red[0] / (float)W + 1e-6f);
    float* y = Y + (size_t)row * ldy;
    for (int i = threadIdx.x; i < W; i += 256) y[i] = rtf(w[i] * (x[i] * inv));
}

// ---------------- YaRN RoPE (reads combined buffer; tf32-rounded out) ----------------
__global__ __launch_bounds__(544) void rope_k(const int* __restrict__ pos_ids) {
    int row = blockIdx.x;
    int t = threadIdx.x;
    int h = t >> 5, j = t & 31;
    float pos = (float)pos_ids[row];
    float fe = powf(10000.0f, -(float)j / 32.0f);
    float ramp = fminf(fmaxf(((float)j - 10.0f) / 13.0f, 0.f), 1.f);
    float invf = (fe / 40.0f) * ramp + fe * (1.0f - ramp);
    float ang = pos * invf;
    float s, c;
    sincosf(ang, &s, &c);
    if (h < NHEADS) {
        float* base = g_q + (size_t)row * 3072 + h * QHD + NOPE;
        float x0 = base[2 * j], x1 = base[2 * j + 1];
        __syncwarp();
        base[j]      = rtf(x0 * c - x1 * s);
        base[32 + j] = rtf(x1 * c + x0 * s);
    } else {
        const float* src = g_qab + (size_t)row * 2112 + 2048;   // k_pe slice
        float x0 = src[2 * j], x1 = src[2 * j + 1];
        float* dst = g_kpe + (size_t)row * 64;
        dst[j]      = rtf(x0 * c - x1 * s);
        dst[32 + j] = rtf(x1 * c + x0 * s);
    }
}

// ==================================================================
// Flash attention, tf32 tensor cores, cp.async double-buffered K/V.
// ==================================================================
#define QP 196
#define VP 136
#define PP 68
#define KTILE_F (64*QP)
#define VTILE_F (64*VP)
#define FLASH_SMEM ((64*QP + 2*KTILE_F + 2*VTILE_F) * 4)   // 220,160 B

__global__ __launch_bounds__(128) void flash_tf32(float scale) {
    extern __shared__ float sm[];
    float* Qs  = sm;
    float* Kb  = sm + 64 * QP;
    float* Vb  = Kb + 2 * KTILE_F;
    const int qb = blockIdx.x, h = blockIdx.y, b = blockIdx.z;
    const int tid = threadIdx.x;
    const int warp = tid >> 5, lane = tid & 31;
    const int g = lane >> 2, tl = lane & 3;
    const int wm = warp * 16;
    const size_t bs0 = (size_t)b * SEQ;

    const uint32_t qs_s = (uint32_t)__cvta_generic_to_shared(Qs);
    const uint32_t kb_s = (uint32_t)__cvta_generic_to_shared(Kb);
    const uint32_t vb_s = (uint32_t)__cvta_generic_to_shared(Vb);

    auto stageK = [&](int buf, int kb) {
        uint32_t base = kb_s + (uint32_t)(buf * KTILE_F * 4);
        #pragma unroll
        for (int u = 0; u < 24; u++) {
            int idx = tid + u * 128;
            int r = idx / 48, q = idx % 48;
            const float* src = (q < 32)
                ? &g_kv[(bs0 + kb * 64 + r) * 4096 + h * 256 + q * 4]
                : &g_kpe[(bs0 + kb * 64 + r) * 64 + (q - 32) * 4];
            cp_async16(base + (r * QP + q * 4) * 4, src, true);
        }
    };
    auto stageV = [&](int buf, int kb) {
        uint32_t base = vb_s + (uint32_t)(buf * VTILE_F * 4);
        #pragma unroll
        for (int u = 0; u < 16; u++) {
            int idx = tid + u * 128;
            int r = idx >> 5, q4 = (idx & 31) * 4;
            cp_async16(base + (r * VP + q4) * 4,
                       &g_kv[(bs0 + kb * 64 + r) * 4096 + h * 256 + NOPE + q4], true);
        }
    };

    #pragma unroll
    for (int u = 0; u < 24; u++) {
        int idx = tid + u * 128;
        int r = idx / 48, q4 = (idx % 48) * 4;
        cp_async16(qs_s + (r * QP + q4) * 4,
                   &g_q[(bs0 + qb * 64 + r) * 3072 + h * QHD + q4], true);
    }
    stageK(0, 0);
    stageV(0, 0);
    asm volatile("cp.async.commit_group;");

    float m_i[2] = {-1e30f, -1e30f};
    float l_i[2] = {0.f, 0.f};
    float acc_o[16][4];
    #pragma unroll
    for (int nt = 0; nt < 16; nt++)
        #pragma unroll
        for (int v = 0; v < 4; v++) acc_o[nt][v] = 0.f;

    const int row0 = qb * 64 + wm + g;

    for (int kb = 0; kb <= qb; kb++) {
        const int cur = kb & 1;
        asm volatile("cp.async.wait_group 0;");
        __syncthreads();
        if (kb < qb) {
            stageK(cur ^ 1, kb + 1);
            stageV(cur ^ 1, kb + 1);
            asm volatile("cp.async.commit_group;");
        }
        const float* Ks = Kb + cur * KTILE_F;
        const float* Vs = Vb + cur * VTILE_F;
        float* Ps = Kb + cur * KTILE_F;

        float acc_s[8][4];
        #pragma unroll
        for (int nt = 0; nt < 8; nt++)
            #pragma unroll
            for (int v = 0; v < 4; v++) acc_s[nt][v] = 0.f;

        #pragma unroll
        for (int ks = 0; ks < 24; ks++) {
            const int kb8 = ks * 8;
            uint32_t afr[4];
            afr[0] = __float_as_uint(Qs[(wm + g) * QP + kb8 + tl]);
            afr[1] = __float_as_uint(Qs[(wm + g + 8) * QP + kb8 + tl]);
            afr[2] = __float_as_uint(Qs[(wm + g) * QP + kb8 + tl + 4]);
            afr[3] = __float_as_uint(Qs[(wm + g + 8) * QP + kb8 + tl + 4]);
            #pragma unroll
            for (int nt = 0; nt < 8; nt++) {
                uint32_t bfr[2];
                bfr[0] = __float_as_uint(Ks[(nt * 8 + g) * QP + kb8 + tl]);
                bfr[1] = __float_as_uint(Ks[(nt * 8 + g) * QP + kb8 + tl + 4]);
                mma_tf32(acc_s[nt], afr, bfr);
            }
        }

        const bool diag = (kb == qb);
        float rmax0 = -1e30f, rmax1 = -1e30f;
        #pragma unroll
        for (int nt = 0; nt < 8; nt++) {
            int c0 = kb * 64 + nt * 8 + 2 * tl, c1 = c0 + 1;
            float s0 = acc_s[nt][0] * scale, s1 = acc_s[nt][1] * scale;
            float s2 = acc_s[nt][2] * scale, s3 = acc_s[nt][3] * scale;
            if (diag) {
                if (c0 > row0) s0 = -1e30f;
                if (c1 > row0) s1 = -1e30f;
                if (c0 > row0 + 8) s2 = -1e30f;
                if (c1 > row0 + 8) s3 = -1e30f;
            }
            acc_s[nt][0] = s0; acc_s[nt][1] = s1;
            acc_s[nt][2] = s2; acc_s[nt][3] = s3;
            rmax0 = fmaxf(rmax0, fmaxf(s0, s1));
            rmax1 = fmaxf(rmax1, fmaxf(s2, s3));
        }
        #pragma unroll
        for (int off = 1; off <= 2; off <<= 1) {
            rmax0 = fmaxf(rmax0, __shfl_xor_sync(0xffffffffu, rmax0, off));
            rmax1 = fmaxf(rmax1, __shfl_xor_sync(0xffffffffu, rmax1, off));
        }
        float mn0 = fmaxf(m_i[0], rmax0), mn1 = fmaxf(m_i[1], rmax1);
        float al0 = __expf(m_i[0] - mn0), al1 = __expf(m_i[1] - mn1);
        float p_r[8][4];
        float rs0 = 0.f, rs1 = 0.f;
        #pragma unroll
        for (int nt = 0; nt < 8; nt++) {
            p_r[nt][0] = __expf(acc_s[nt][0] - mn0);
            p_r[nt][1] = __expf(acc_s[nt][1] - mn0);
            p_r[nt][2] = __expf(acc_s[nt][2] - mn1);
            p_r[nt][3] = __expf(acc_s[nt][3] - mn1);
            rs0 += p_r[nt][0] + p_r[nt][1];
            rs1 += p_r[nt][2] + p_r[nt][3];
        }
        #pragma unroll
        for (int off = 1; off <= 2; off <<= 1) {
            rs0 += __shfl_xor_sync(0xffffffffu, rs0, off);
            rs1 += __shfl_xor_sync(0xffffffffu, rs1, off);
        }
        l_i[0] = l_i[0] * al0 + rs0;
        l_i[1] = l_i[1] * al1 + rs1;
        m_i[0] = mn0; m_i[1] = mn1;
        #pragma unroll
        for (int nt = 0; nt < 16; nt++) {
            acc_o[nt][0] *= al0; acc_o[nt][1] *= al0;
            acc_o[nt][2] *= al1; acc_o[nt][3] *= al1;
        }

        __syncthreads();
        #pragma unroll
        for (int nt = 0; nt < 8; nt++) {
            Ps[(wm + g) * PP + nt * 8 + 2 * tl]         = rtf(p_r[nt][0]);
            Ps[(wm + g) * PP + nt * 8 + 2 * tl + 1]     = rtf(p_r[nt][1]);
            Ps[(wm + g + 8) * PP + nt * 8 + 2 * tl]     = rtf(p_r[nt][2]);
            Ps[(wm + g + 8) * PP + nt * 8 + 2 * tl + 1] = rtf(p_r[nt][3]);
        }
        __syncwarp();

        #pragma unroll
        for (int ks = 0; ks < 8; ks++) {
            const int kb8 = ks * 8;
            uint32_t afr[4];
            afr[0] = __float_as_uint(Ps[(wm + g) * PP + kb8 + tl]);
            afr[1] = __float_as_uint(Ps[(wm + g + 8) * PP + kb8 + tl]);
            afr[2] = __float_as_uint(Ps[(wm + g) * PP + kb8 + tl + 4]);
            afr[3] = __float_as_uint(Ps[(wm + g + 8) * PP + kb8 + tl + 4]);
            #pragma unroll
            for (int nt = 0; nt < 16; nt++) {
                uint32_t bfr[2];
                bfr[0] = __float_as_uint(Vs[(kb8 + tl) * VP + nt * 8 + g]);
                bfr[1] = __float_as_uint(Vs[(kb8 + tl + 4) * VP + nt * 8 + g]);
                mma_tf32(acc_o[nt], afr, bfr);
            }
        }
    }

    float inv0 = 1.0f / l_i[0], inv1 = 1.0f / l_i[1];
    size_t r0 = (bs0 + qb * 64 + wm + g) * 2048 + h * VHD;
    size_t r1 = r0 + 8 * 2048;
    #pragma unroll
    for (int nt = 0; nt < 16; nt++) {
        int cn = nt * 8 + 2 * tl;
        *(float2*)&g_attn[r0 + cn] =
            make_float2(rtf(acc_o[nt][0] * inv0), rtf(acc_o[nt][1] * inv0));
        *(float2*)&g_attn[r1 + cn] =
            make_float2(rtf(acc_o[nt][2] * inv1), rtf(acc_o[nt][3] * inv1));
    }
}

// ---------------- launch ----------------
extern "C" void kernel_launch(void* const* d_in, const int* in_sizes, int n_in,
                              void* d_out, int out_size) {
    const float* hs      = (const float*)d_in[0];
    const int*   pos     = (const int*)  d_in[1];
    const float* wq_a    = (const float*)d_in[2];
    const float* q_a_ln  = (const float*)d_in[3];
    const float* wq_b    = (const float*)d_in[4];
    const float* wkv_a   = (const float*)d_in[5];
    const float* kv_a_ln = (const float*)d_in[6];
    const float* wkv_b   = (const float*)d_in[7];
    const float* wo      = (const float*)d_in[8];
    float* out = (float*)d_out;

    float *qab, *qlora, *q, *cnorm, *kv, *kpe, *attn;
    float *hs_t, *wab_t, *wqb_t, *wkvb_t, *wo_t;
    cudaGetSymbolAddress((void**)&qab,   g_qab);
    cudaGetSymbolAddress((void**)&qlora, g_qlora);
    cudaGetSymbolAddress((void**)&q,     g_q);
    cudaGetSymbolAddress((void**)&cnorm, g_cnorm);
    cudaGetSymbolAddress((void**)&kv,    g_kv);
    cudaGetSymbolAddress((void**)&kpe,   g_kpe);
    cudaGetSymbolAddress((void**)&attn,  g_attn);
    cudaGetSymbolAddress((void**)&hs_t,  g_hs_t);
    cudaGetSymbolAddress((void**)&wab_t, g_wab_t);
    cudaGetSymbolAddress((void**)&wqb_t, g_wqb_t);
    cudaGetSymbolAddress((void**)&wkvb_t,g_wkvb_t);
    cudaGetSymbolAddress((void**)&wo_t,  g_wo_t);

    double m = 0.1 * log(40.0) + 1.0;
    float scale = (float)((1.0 / sqrt(192.0)) * m * m);

    cudaFuncSetAttribute(flash_tf32, cudaFuncAttributeMaxDynamicSharedMemorySize,
                         FLASH_SMEM);
    cudaFuncSetAttribute(gemm_tf32, cudaFuncAttributeMaxDynamicSharedMemorySize,
                         GEMM_SMEM);

    auto cvtn = [&](const float* x, float* y, size_t n) {
        cvt_tf32_k<<<(int)((n / 4 + 255) / 256), 256>>>(x, y, (int)n);
    };
    // Launch indices 0-4: cvt pre-passes. Index 5 = the big GEMM, so the
    // ncu capture (-s 5 -c 1) profiles the GEMM instead of a cvt.
    cvtn(hs,    hs_t,   (size_t)ROWS * 2048);                         // 0
    cvtn(wq_a,  wab_t,               (size_t)1536 * 2048);            // 1
    cvtn(wkv_a, wab_t + (size_t)1536 * 2048, (size_t)576 * 2048);     // 2
    cvtn(wq_b,  wqb_t,  (size_t)3072 * 1536);                         // 3
    cvtn(wkv_b, wkvb_t, (size_t)4096 * 512);                          // 4

    dim3 blk(256);
    // [5] combined: [qlora | ckv | kpe] = hs @ [wq_a ; wkv_a]^T   (N=2112)
    gemm_tf32<<<dim3((2112 + 127) / 128, ROWS / 256), blk, GEMM_SMEM>>>(
        hs_t, wab_t, qab, ROWS, 2112, 2048, 0);
    cvtn(wo, wo_t, (size_t)2048 * 2048);                              // 6
    rmsnorm_k<<<ROWS, 256>>>(qab,        q_a_ln,  qlora, 1536, 2112, 1536);
    rmsnorm_k<<<ROWS, 256>>>(qab + 1536, kv_a_ln, cnorm, 512,  2112, 512);
    gemm_tf32<<<dim3(3072 / 128, ROWS / 256), blk, GEMM_SMEM>>>(
        qlora, wqb_t, q, ROWS, 3072, 1536, 1);
    gemm_tf32<<<dim3(4096 / 128, ROWS / 256), blk, GEMM_SMEM>>>(
        cnorm, wkvb_t, kv, ROWS, 4096, 512, 1);
    rope_k<<<ROWS, 544>>>(pos);
    flash_tf32<<<dim3(SEQ / 64, NHEADS, BATCH), 128, FLASH_SMEM>>>(scale);
    gemm_tf32<<<dim3(2048 / 128, ROWS / 256), blk, GEMM_SMEM>>>(
        attn, wo_t, out, ROWS, 2048, 2048, 0);
}

// round 11
// speedup vs baseline: 7.4036x; 1.4337x over previous
#include <cuda_runtime.h>
#include <cuda_fp16.h>
#include <math.h>
#include <stdint.h>

#define SEQ 2048
#define BATCH 2
#define ROWS (BATCH*SEQ)   // 4096
#define NHEADS 16
#define QHD 192
#define NOPE 128
#define VHD 128

// ---------------- scratch (device globals; no allocation allowed) ----------------
__device__ float g_qab [(size_t)ROWS*2112];    // [qlora(1536) | ckv(512) | kpe(64)]
__device__ float g_q[(size_t)ROWS*3072];
__device__ float g_kv[(size_t)ROWS*4096];
__device__ float g_kpe[(size_t)ROWS*64];
// fp16 GEMM operands
__device__ __half g_hs16 [(size_t)ROWS*2048];
__device__ __half g_wab16[(size_t)2112*2048];   // [wq_a(1536) ; wkv_a(576)]
__device__ __half g_wqb16[(size_t)3072*1536];
__device__ __half g_wkvb16[(size_t)4096*512];
__device__ __half g_wo16 [(size_t)2048*2048];
__device__ __half g_qlora16[(size_t)ROWS*1536];
__device__ __half g_cnorm16[(size_t)ROWS*512];
__device__ __half g_attn16[(size_t)ROWS*2048];

__device__ __forceinline__ uint32_t f2tf32(float f) {
    uint32_t u;
    asm("cvt.rna.tf32.f32 %0, %1;" : "=r"(u) : "f"(f));
    return u;
}
__device__ __forceinline__ float rtf(float f) { return __uint_as_float(f2tf32(f)); }

__device__ __forceinline__ void mma_tf32(float d[4], const uint32_t a[4],
                                         const uint32_t b[2]) {
    asm volatile(
        "mma.sync.aligned.m16n8k8.row.col.f32.tf32.tf32.f32 "
        "{%0,%1,%2,%3}, {%4,%5,%6,%7}, {%8,%9}, {%0,%1,%2,%3};"
        : "+f"(d[0]), "+f"(d[1]), "+f"(d[2]), "+f"(d[3])
        : "r"(a[0]), "r"(a[1]), "r"(a[2]), "r"(a[3]), "r"(b[0]), "r"(b[1]));
}

__device__ __forceinline__ void mma_f16(float d[4], const uint32_t a[4],
                                        const uint32_t b[2]) {
    asm volatile(
        "mma.sync.aligned.m16n8k16.row.col.f32.f16.f16.f32 "
        "{%0,%1,%2,%3}, {%4,%5,%6,%7}, {%8,%9}, {%0,%1,%2,%3};"
        : "+f"(d[0]), "+f"(d[1]), "+f"(d[2]), "+f"(d[3])
        : "r"(a[0]), "r"(a[1]), "r"(a[2]), "r"(a[3]), "r"(b[0]), "r"(b[1]));
}

__device__ __forceinline__ void cp_async16(uint32_t saddr, const void* gptr, bool pred) {
    int sz = pred ? 16 : 0;
    asm volatile("cp.async.cg.shared.global [%0], [%1], 16, %2;\n"
                 :: "r"(saddr), "l"(gptr), "r"(sz));
}

// ---------------- fp32 -> fp16 copy ----------------
__global__ __launch_bounds__(256) void cvt_f16_k(const float* __restrict__ x,
                                                 __half* __restrict__ y, int n) {
    int i = (blockIdx.x * 256 + threadIdx.x) * 4;
    if (i < n) {
        float4 v = *(const float4*)(x + i);
        half2* y2 = (half2*)(y + i);
        y2[0] = __floats2half2_rn(v.x, v.y);
        y2[1] = __floats2half2_rn(v.z, v.w);
    }
}

// ==================================================================
// FP16 GEMM: C[M,N] = A[M,K] @ B[N,K]^T, fp32 accumulate.
// 256x128 block tile, BK=64, 3-stage cp.async ring, 256 threads
// (8 warps as 4m x 2n, each 64x64), mma.m16n8k16.
// Pitch 72 halves (word-pitch 36 == 4 mod 32 -> conflict-free).
// M % 256 == 0, K % 64 == 0; N guarded.
// ==================================================================
#define HP 72
#define AT_H (256*HP)
#define BT_H (128*HP)
#define ST_H (AT_H + BT_H)
#define GEMM_SMEM (3*ST_H*2)   // 165,888 B

__global__ __launch_bounds__(256, 1) void gemm_f16(const __half* __restrict__ A,
                                                   const __half* __restrict__ B,
                                                   float* __restrict__ C,
                                                   int M, int N, int K, int roundC) {
    extern __shared__ __half smh[];
    const int tid = threadIdx.x;
    const int warp = tid >> 5, lane = tid & 31;
    const int wm = (warp & 3) * 64, wn = (warp >> 2) * 64;
    const int g = lane >> 2, tl = lane & 3;
    const int m0 = blockIdx.y * 256, n0 = blockIdx.x * 128;

    float acc[4][8][4];
    #pragma unroll
    for (int i = 0; i < 4; i++)
        #pragma unroll
        for (int j = 0; j < 8; j++)
            #pragma unroll
            for (int v = 0; v < 4; v++) acc[i][j][v] = 0.f;

    const int T = K / 64;

    auto issue = [&](int stage, int t) {
        const int k0 = t * 64;
        uint32_t ab = (uint32_t)__cvta_generic_to_shared(smh + stage * ST_H);
        uint32_t bb = ab + AT_H * 2;
        #pragma unroll
        for (int u = 0; u < 8; u++) {          // A: 256 rows x 8 granules(8h)
            int seg = tid + u * 256;
            int row = seg >> 3, gq = (seg & 7) * 8;
            cp_async16(ab + (row * HP + gq) * 2,
                       A + (size_t)(m0 + row) * K + k0 + gq, true);
        }
        #pragma unroll
        for (int u = 0; u < 4; u++) {          // B: 128 rows x 8 granules
            int seg = tid + u * 256;
            int row = seg >> 3, gq = (seg & 7) * 8;
            int nr = n0 + row;
            cp_async16(bb + (row * HP + gq) * 2,
                       B + (size_t)(nr < N ? nr : 0) * K + k0 + gq, nr < N);
        }
        asm volatile("cp.async.commit_group;");
    };

    issue(0, 0);
    if (T > 1) issue(1, 1); else asm volatile("cp.async.commit_group;");

    for (int t = 0; t < T; t++) {
        asm volatile("cp.async.wait_group 1;");
        __syncthreads();            // tile t ready AND all warps done with t-1
        if (t + 2 < T) issue((t + 2) % 3, t + 2);
        else asm volatile("cp.async.commit_group;");

        const __half* Ab = smh + (t % 3) * ST_H;
        const __half* Bb = Ab + AT_H;
        #pragma unroll
        for (int ks = 0; ks < 4; ks++) {
            const int kb = ks * 16;
            uint32_t afr[4][4], bfr[8][2];
            #pragma unroll
            for (int mt = 0; mt < 4; mt++) {
                int rb = wm + mt * 16 + g;
                afr[mt][0] = *(const uint32_t*)&Ab[rb * HP + kb + 2 * tl];
                afr[mt][1] = *(const uint32_t*)&Ab[(rb + 8) * HP + kb + 2 * tl];
                afr[mt][2] = *(const uint32_t*)&Ab[rb * HP + kb + 8 + 2 * tl];
                afr[mt][3] = *(const uint32_t*)&Ab[(rb + 8) * HP + kb + 8 + 2 * tl];
            }
            #pragma unroll
            for (int nt = 0; nt < 8; nt++) {
                int cb = wn + nt * 8 + g;
                bfr[nt][0] = *(const uint32_t*)&Bb[cb * HP + kb + 2 * tl];
                bfr[nt][1] = *(const uint32_t*)&Bb[cb * HP + kb + 8 + 2 * tl];
            }
            #pragma unroll
            for (int mt = 0; mt < 4; mt++)
                #pragma unroll
                for (int nt = 0; nt < 8; nt++)
                    mma_f16(acc[mt][nt], afr[mt], bfr[nt]);
        }
        // no bottom barrier: next-iter top barrier orders reuse (ring distance 3)
    }

    #pragma unroll
    for (int mt = 0; mt < 4; mt++) {
        int r0 = m0 + wm + mt * 16 + g;
        #pragma unroll
        for (int nt = 0; nt < 8; nt++) {
            int cn = n0 + wn + nt * 8 + 2 * tl;
            if (cn < N) {
                float v0 = acc[mt][nt][0], v1 = acc[mt][nt][1];
                float v2 = acc[mt][nt][2], v3 = acc[mt][nt][3];
                if (roundC) { v0 = rtf(v0); v1 = rtf(v1); v2 = rtf(v2); v3 = rtf(v3); }
                *(float2*)&C[(size_t)r0 * N + cn]       = make_float2(v0, v1);
                *(float2*)&C[(size_t)(r0 + 8) * N + cn] = make_float2(v2, v3);
            }
        }
    }
}

// ---------------- RMSNorm (fp32 in -> fp16 out) ----------------
__global__ __launch_bounds__(256) void rmsnorm_k(const float* __restrict__ X,
                                                 const float* __restrict__ w,
                                                 __half* __restrict__ Y,
                                                 int W, int ldx) {
    int row = blockIdx.x;
    const float* x = X + (size_t)row * ldx;
    float ss = 0.f;
    for (int i = threadIdx.x; i < W; i += 256) { float v = x[i]; ss += v * v; }
    __shared__ float red[256];
    red[threadIdx.x] = ss;
    __syncthreads();
    for (int s = 128; s > 0; s >>= 1) {
        if (threadIdx.x < s) red[threadIdx.x] += red[threadIdx.x + s];
        __syncthreads();
    }
    float inv = rsqrtf(red[0] / (float)W + 1e-6f);
    __half* y = Y + (size_t)row * W;
    for (int i = threadIdx.x; i < W; i += 256)
        y[i] = __float2half_rn(w[i] * (x[i] * inv));
}

// ---------------- YaRN RoPE (reads combined buffer; tf32-rounded out) ----------------
__global__ __launch_bounds__(544) void rope_k(const int* __restrict__ pos_ids) {
    int row = blockIdx.x;
    int t = threadIdx.x;
    int h = t >> 5, j = t & 31;
    float pos = (float)pos_ids[row];
    float fe = powf(10000.0f, -(float)j / 32.0f);
    float ramp = fminf(fmaxf(((float)j - 10.0f) / 13.0f, 0.f), 1.f);
    float invf = (fe / 40.0f) * ramp + fe * (1.0f - ramp);
    float ang = pos * invf;
    float s, c;
    sincosf(ang, &s, &c);
    if (h < NHEADS) {
        float* base = g_q + (size_t)row * 3072 + h * QHD + NOPE;
        float x0 = base[2 * j], x1 = base[2 * j + 1];
        __syncwarp();
        base[j]      = rtf(x0 * c - x1 * s);
        base[32 + j] = rtf(x1 * c + x0 * s);
    } else {
        const float* src = g_qab + (size_t)row * 2112 + 2048;   // k_pe slice
        float x0 = src[2 * j], x1 = src[2 * j + 1];
        float* dst = g_kpe + (size_t)row * 64;
        dst[j]      = rtf(x0 * c - x1 * s);
        dst[32 + j] = rtf(x1 * c + x0 * s);
    }
}

// ==================================================================
// Flash attention, tf32 tensor cores, cp.async double-buffered K/V.
// Epilogue writes fp16 attn (input to wo fp16 GEMM).
// ==================================================================
#define QP 196
#define VP 136
#define PP 68
#define KTILE_F (64*QP)
#define VTILE_F (64*VP)
#define FLASH_SMEM ((64*QP + 2*KTILE_F + 2*VTILE_F) * 4)   // 220,160 B

__global__ __launch_bounds__(128) void flash_tf32(float scale) {
    extern __shared__ float sm[];
    float* Qs  = sm;
    float* Kb  = sm + 64 * QP;
    float* Vb  = Kb + 2 * KTILE_F;
    const int qb = blockIdx.x, h = blockIdx.y, b = blockIdx.z;
    const int tid = threadIdx.x;
    const int warp = tid >> 5, lane = tid & 31;
    const int g = lane >> 2, tl = lane & 3;
    const int wm = warp * 16;
    const size_t bs0 = (size_t)b * SEQ;

    const uint32_t qs_s = (uint32_t)__cvta_generic_to_shared(Qs);
    const uint32_t kb_s = (uint32_t)__cvta_generic_to_shared(Kb);
    const uint32_t vb_s = (uint32_t)__cvta_generic_to_shared(Vb);

    auto stageK = [&](int buf, int kb) {
        uint32_t base = kb_s + (uint32_t)(buf * KTILE_F * 4);
        #pragma unroll
        for (int u = 0; u < 24; u++) {
            int idx = tid + u * 128;
            int r = idx / 48, q = idx % 48;
            const float* src = (q < 32)
                ? &g_kv[(bs0 + kb * 64 + r) * 4096 + h * 256 + q * 4]
                : &g_kpe[(bs0 + kb * 64 + r) * 64 + (q - 32) * 4];
            cp_async16(base + (r * QP + q * 4) * 4, src, true);
        }
    };
    auto stageV = [&](int buf, int kb) {
        uint32_t base = vb_s + (uint32_t)(buf * VTILE_F * 4);
        #pragma unroll
        for (int u = 0; u < 16; u++) {
            int idx = tid + u * 128;
            int r = idx >> 5, q4 = (idx & 31) * 4;
            cp_async16(base + (r * VP + q4) * 4,
                       &g_kv[(bs0 + kb * 64 + r) * 4096 + h * 256 + NOPE + q4], true);
        }
    };

    #pragma unroll
    for (int u = 0; u < 24; u++) {
        int idx = tid + u * 128;
        int r = idx / 48, q4 = (idx % 48) * 4;
        cp_async16(qs_s + (r * QP + q4) * 4,
                   &g_q[(bs0 + qb * 64 + r) * 3072 + h * QHD + q4], true);
    }
    stageK(0, 0);
    stageV(0, 0);
    asm volatile("cp.async.commit_group;");

    float m_i[2] = {-1e30f, -1e30f};
    float l_i[2] = {0.f, 0.f};
    float acc_o[16][4];
    #pragma unroll
    for (int nt = 0; nt < 16; nt++)
        #pragma unroll
        for (int v = 0; v < 4; v++) acc_o[nt][v] = 0.f;

    const int row0 = qb * 64 + wm + g;

    for (int kb = 0; kb <= qb; kb++) {
        const int cur = kb & 1;
        asm volatile("cp.async.wait_group 0;");
        __syncthreads();
        if (kb < qb) {
            stageK(cur ^ 1, kb + 1);
            stageV(cur ^ 1, kb + 1);
            asm volatile("cp.async.commit_group;");
        }
        const float* Ks = Kb + cur * KTILE_F;
        const float* Vs = Vb + cur * VTILE_F;
        float* Ps = Kb + cur * KTILE_F;

        float acc_s[8][4];
        #pragma unroll
        for (int nt = 0; nt < 8; nt++)
            #pragma unroll
            for (int v = 0; v < 4; v++) acc_s[nt][v] = 0.f;

        #pragma unroll
        for (int ks = 0; ks < 24; ks++) {
            const int kb8 = ks * 8;
            uint32_t afr[4];
            afr[0] = __float_as_uint(Qs[(wm + g) * QP + kb8 + tl]);
            afr[1] = __float_as_uint(Qs[(wm + g + 8) * QP + kb8 + tl]);
            afr[2] = __float_as_uint(Qs[(wm + g) * QP + kb8 + tl + 4]);
            afr[3] = __float_as_uint(Qs[(wm + g + 8) * QP + kb8 + tl + 4]);
            #pragma unroll
            for (int nt = 0; nt < 8; nt++) {
                uint32_t bfr[2];
                bfr[0] = __float_as_uint(Ks[(nt * 8 + g) * QP + kb8 + tl]);
                bfr[1] = __float_as_uint(Ks[(nt * 8 + g) * QP + kb8 + tl + 4]);
                mma_tf32(acc_s[nt], afr, bfr);
            }
        }

        const bool diag = (kb == qb);
        float rmax0 = -1e30f, rmax1 = -1e30f;
        #pragma unroll
        for (int nt = 0; nt < 8; nt++) {
            int c0 = kb * 64 + nt * 8 + 2 * tl, c1 = c0 + 1;
            float s0 = acc_s[nt][0] * scale, s1 = acc_s[nt][1] * scale;
            float s2 = acc_s[nt][2] * scale, s3 = acc_s[nt][3] * scale;
            if (diag) {
                if (c0 > row0) s0 = -1e30f;
                if (c1 > row0) s1 = -1e30f;
                if (c0 > row0 + 8) s2 = -1e30f;
                if (c1 > row0 + 8) s3 = -1e30f;
            }
            acc_s[nt][0] = s0; acc_s[nt][1] = s1;
            acc_s[nt][2] = s2; acc_s[nt][3] = s3;
            rmax0 = fmaxf(rmax0, fmaxf(s0, s1));
            rmax1 = fmaxf(rmax1, fmaxf(s2, s3));
        }
        #pragma unroll
        for (int off = 1; off <= 2; off <<= 1) {
            rmax0 = fmaxf(rmax0, __shfl_xor_sync(0xffffffffu, rmax0, off));
            rmax1 = fmaxf(rmax1, __shfl_xor_sync(0xffffffffu, rmax1, off));
        }
        float mn0 = fmaxf(m_i[0], rmax0), mn1 = fmaxf(m_i[1], rmax1);
        float al0 = __expf(m_i[0] - mn0), al1 = __expf(m_i[1] - mn1);
        float p_r[8][4];
        float rs0 = 0.f, rs1 = 0.f;
        #pragma unroll
        for (int nt = 0; nt < 8; nt++) {
            p_r[nt][0] = __expf(acc_s[nt][0] - mn0);
            p_r[nt][1] = __expf(acc_s[nt][1] - mn0);
            p_r[nt][2] = __expf(acc_s[nt][2] - mn1);
            p_r[nt][3] = __expf(acc_s[nt][3] - mn1);
            rs0 += p_r[nt][0] + p_r[nt][1];
            rs1 += p_r[nt][2] + p_r[nt][3];
        }
        #pragma unroll
        for (int off = 1; off <= 2; off <<= 1) {
            rs0 += __shfl_xor_sync(0xffffffffu, rs0, off);
            rs1 += __shfl_xor_sync(0xffffffffu, rs1, off);
        }
        l_i[0] = l_i[0] * al0 + rs0;
        l_i[1] = l_i[1] * al1 + rs1;
        m_i[0] = mn0; m_i[1] = mn1;
        #pragma unroll
        for (int nt = 0; nt < 16; nt++) {
            acc_o[nt][0] *= al0; acc_o[nt][1] *= al0;
            acc_o[nt][2] *= al1; acc_o[nt][3] *= al1;
        }

        __syncthreads();
        #pragma unroll
        for (int nt = 0; nt < 8; nt++) {
            Ps[(wm + g) * PP + nt * 8 + 2 * tl]         = rtf(p_r[nt][0]);
            Ps[(wm + g) * PP + nt * 8 + 2 * tl + 1]     = rtf(p_r[nt][1]);
            Ps[(wm + g + 8) * PP + nt * 8 + 2 * tl]     = rtf(p_r[nt][2]);
            Ps[(wm + g + 8) * PP + nt * 8 + 2 * tl + 1] = rtf(p_r[nt][3]);
        }
        __syncwarp();

        #pragma unroll
        for (int ks = 0; ks < 8; ks++) {
            const int kb8 = ks * 8;
            uint32_t afr[4];
            afr[0] = __float_as_uint(Ps[(wm + g) * PP + kb8 + tl]);
            afr[1] = __float_as_uint(Ps[(wm + g + 8) * PP + kb8 + tl]);
            afr[2] = __float_as_uint(Ps[(wm + g) * PP + kb8 + tl + 4]);
            afr[3] = __float_as_uint(Ps[(wm + g + 8) * PP + kb8 + tl + 4]);
            #pragma unroll
            for (int nt = 0; nt < 16; nt++) {
                uint32_t bfr[2];
                bfr[0] = __float_as_uint(Vs[(kb8 + tl) * VP + nt * 8 + g]);
                bfr[1] = __float_as_uint(Vs[(kb8 + tl + 4) * VP + nt * 8 + g]);
                mma_tf32(acc_o[nt], afr, bfr);
            }
        }
    }

    // epilogue: normalize + write fp16 attn (wo GEMM input)
    float inv0 = 1.0f / l_i[0], inv1 = 1.0f / l_i[1];
    size_t r0 = (bs0 + qb * 64 + wm + g) * 2048 + h * VHD;
    size_t r1 = r0 + 8 * 2048;
    #pragma unroll
    for (int nt = 0; nt < 16; nt++) {
        int cn = nt * 8 + 2 * tl;
        *(half2*)&g_attn16[r0 + cn] =
            __floats2half2_rn(acc_o[nt][0] * inv0, acc_o[nt][1] * inv0);
        *(half2*)&g_attn16[r1 + cn] =
            __floats2half2_rn(acc_o[nt][2] * inv1, acc_o[nt][3] * inv1);
    }
}

// ---------------- launch ----------------
extern "C" void kernel_launch(void* const* d_in, const int* in_sizes, int n_in,
                              void* d_out, int out_size) {
    const float* hs      = (const float*)d_in[0];
    const int*   pos     = (const int*)  d_in[1];
    const float* wq_a    = (const float*)d_in[2];
    const float* q_a_ln  = (const float*)d_in[3];
    const float* wq_b    = (const float*)d_in[4];
    const float* wkv_a   = (const float*)d_in[5];
    const float* kv_a_ln = (const float*)d_in[6];
    const float* wkv_b   = (const float*)d_in[7];
    const float* wo      = (const float*)d_in[8];
    float* out = (float*)d_out;

    float *qab, *q, *kv, *kpe;
    __half *hs16, *wab16, *wqb16, *wkvb16, *wo16, *qlo16, *cn16, *at16;
    cudaGetSymbolAddress((void**)&qab, g_qab);
    cudaGetSymbolAddress((void**)&q,   g_q);
    cudaGetSymbolAddress((void**)&kv,  g_kv);
    cudaGetSymbolAddress((void**)&kpe, g_kpe);
    cudaGetSymbolAddress((void**)&hs16,  g_hs16);
    cudaGetSymbolAddress((void**)&wab16, g_wab16);
    cudaGetSymbolAddress((void**)&wqb16, g_wqb16);
    cudaGetSymbolAddress((void**)&wkvb16,g_wkvb16);
    cudaGetSymbolAddress((void**)&wo16,  g_wo16);
    cudaGetSymbolAddress((void**)&qlo16, g_qlora16);
    cudaGetSymbolAddress((void**)&cn16,  g_cnorm16);
    cudaGetSymbolAddress((void**)&at16,  g_attn16);

    double m = 0.1 * log(40.0) + 1.0;
    float scale = (float)((1.0 / sqrt(192.0)) * m * m);

    cudaFuncSetAttribute(flash_tf32, cudaFuncAttributeMaxDynamicSharedMemorySize,
                         FLASH_SMEM);
    cudaFuncSetAttribute(gemm_f16, cudaFuncAttributeMaxDynamicSharedMemorySize,
                         GEMM_SMEM);

    auto cvtn = [&](const float* x, __half* y, size_t n) {
        cvt_f16_k<<<(int)((n / 4 + 255) / 256), 256>>>(x, y, (int)n);
    };
    cvtn(hs,    hs16,   (size_t)ROWS * 2048);
    cvtn(wq_a,  wab16,               (size_t)1536 * 2048);
    cvtn(wkv_a, wab16 + (size_t)1536 * 2048, (size_t)576 * 2048);
    cvtn(wq_b,  wqb16,  (size_t)3072 * 1536);
    cvtn(wkv_b, wkvb16, (size_t)4096 * 512);

    dim3 blk(256);
    // combined: [qlora | ckv | kpe] = hs @ [wq_a ; wkv_a]^T   (N=2112)
    gemm_f16<<<dim3((2112 + 127) / 128, ROWS / 256), blk, GEMM_SMEM>>>(
        hs16, wab16, qab, ROWS, 2112, 2048, 0);
    cvtn(wo, wo16, (size_t)2048 * 2048);
    rmsnorm_k<<<ROWS, 256>>>(qab,        q_a_ln,  qlo16, 1536, 2112);
    rmsnorm_k<<<ROWS, 256>>>(qab + 1536, kv_a_ln, cn16,  512,  2112);
    // q = qlora_n @ wq_b^T  (fp32 out, rtf for flash)
    gemm_f16<<<dim3(3072 / 128, ROWS / 256), blk, GEMM_SMEM>>>(
        qlo16, wqb16, q, ROWS, 3072, 1536, 1);
    // kv = cnorm @ wkv_b^T  (fp32 out, rtf for flash)
    gemm_f16<<<dim3(4096 / 128, ROWS / 256), blk, GEMM_SMEM>>>(
        cn16, wkvb16, kv, ROWS, 4096, 512, 1);
    rope_k<<<ROWS, 544>>>(pos);
    flash_tf32<<<dim3(SEQ / 64, NHEADS, BATCH), 128, FLASH_SMEM>>>(scale);
    // out = attn @ wo^T
    gemm_f16<<<dim3(2048 / 128, ROWS / 256), blk, GEMM_SMEM>>>(
        at16, wo16, out, ROWS, 2048, 2048, 0);
}

// round 12
// speedup vs baseline: 9.7609x; 1.3184x over previous
#include <cuda_runtime.h>
#include <cuda_fp16.h>
#include <math.h>
#include <stdint.h>

#define SEQ 2048
#define BATCH 2
#define ROWS (BATCH*SEQ)   // 4096
#define NHEADS 16
#define QHD 192
#define NOPE 128
#define VHD 128

// ---------------- scratch (device globals; no allocation allowed) ----------------
__device__ float g_qab [(size_t)ROWS*2112];    // [qlora(1536) | ckv(512) | kpe(64)] fp32
// fp16 operands
__device__ __half g_hs16 [(size_t)ROWS*2048];
__device__ __half g_wab16[(size_t)2112*2048];
__device__ __half g_wqb16[(size_t)3072*1536];
__device__ __half g_wkvb16[(size_t)4096*512];
__device__ __half g_wo16 [(size_t)2048*2048];
__device__ __half g_qlora16[(size_t)ROWS*1536];
__device__ __half g_cnorm16[(size_t)ROWS*512];
__device__ __half g_q16 [(size_t)ROWS*3072];
__device__ __half g_kv16[(size_t)ROWS*4096];
__device__ __half g_kpe16[(size_t)ROWS*64];
__device__ __half g_attn16[(size_t)ROWS*2048];

__device__ __forceinline__ void mma_f16(float d[4], const uint32_t a[4],
                                        const uint32_t b[2]) {
    asm volatile(
        "mma.sync.aligned.m16n8k16.row.col.f32.f16.f16.f32 "
        "{%0,%1,%2,%3}, {%4,%5,%6,%7}, {%8,%9}, {%0,%1,%2,%3};"
        : "+f"(d[0]), "+f"(d[1]), "+f"(d[2]), "+f"(d[3])
        : "r"(a[0]), "r"(a[1]), "r"(a[2]), "r"(a[3]), "r"(b[0]), "r"(b[1]));
}

__device__ __forceinline__ void cp_async16(uint32_t saddr, const void* gptr, bool pred) {
    int sz = pred ? 16 : 0;
    asm volatile("cp.async.cg.shared.global [%0], [%1], 16, %2;\n"
                 :: "r"(saddr), "l"(gptr), "r"(sz));
}

// ---------------- fp32 -> fp16 copy ----------------
__global__ __launch_bounds__(256) void cvt_f16_k(const float* __restrict__ x,
                                                 __half* __restrict__ y, int n) {
    int i = (blockIdx.x * 256 + threadIdx.x) * 4;
    if (i < n) {
        float4 v = *(const float4*)(x + i);
        half2* y2 = (half2*)(y + i);
        y2[0] = __floats2half2_rn(v.x, v.y);
        y2[1] = __floats2half2_rn(v.z, v.w);
    }
}

// ==================================================================
// FP16 GEMM: C[M,N] = A[M,K] @ B[N,K]^T, fp32 accumulate.
// 256x128 tile, BK=64, 3-stage cp.async, 256 threads (8 warps 4x2).
// mode: 0 = fp32 out, 2 = fp16 out (same layout).
// ==================================================================
#define HP 72
#define AT_H (256*HP)
#define BT_H (128*HP)
#define ST_H (AT_H + BT_H)
#define GEMM_SMEM (3*ST_H*2)   // 165,888 B

__global__ __launch_bounds__(256, 1) void gemm_f16(const __half* __restrict__ A,
                                                   const __half* __restrict__ B,
                                                   void* __restrict__ C,
                                                   int M, int N, int K, int mode) {
    extern __shared__ __half smh[];
    const int tid = threadIdx.x;
    const int warp = tid >> 5, lane = tid & 31;
    const int wm = (warp & 3) * 64, wn = (warp >> 2) * 64;
    const int g = lane >> 2, tl = lane & 3;
    const int m0 = blockIdx.y * 256, n0 = blockIdx.x * 128;

    float acc[4][8][4];
    #pragma unroll
    for (int i = 0; i < 4; i++)
        #pragma unroll
        for (int j = 0; j < 8; j++)
            #pragma unroll
            for (int v = 0; v < 4; v++) acc[i][j][v] = 0.f;

    const int T = K / 64;

    auto issue = [&](int stage, int t) {
        const int k0 = t * 64;
        uint32_t ab = (uint32_t)__cvta_generic_to_shared(smh + stage * ST_H);
        uint32_t bb = ab + AT_H * 2;
        #pragma unroll
        for (int u = 0; u < 8; u++) {
            int seg = tid + u * 256;
            int row = seg >> 3, gq = (seg & 7) * 8;
            cp_async16(ab + (row * HP + gq) * 2,
                       A + (size_t)(m0 + row) * K + k0 + gq, true);
        }
        #pragma unroll
        for (int u = 0; u < 4; u++) {
            int seg = tid + u * 256;
            int row = seg >> 3, gq = (seg & 7) * 8;
            int nr = n0 + row;
            cp_async16(bb + (row * HP + gq) * 2,
                       B + (size_t)(nr < N ? nr : 0) * K + k0 + gq, nr < N);
        }
        asm volatile("cp.async.commit_group;");
    };

    issue(0, 0);
    if (T > 1) issue(1, 1); else asm volatile("cp.async.commit_group;");

    for (int t = 0; t < T; t++) {
        asm volatile("cp.async.wait_group 1;");
        __syncthreads();
        if (t + 2 < T) issue((t + 2) % 3, t + 2);
        else asm volatile("cp.async.commit_group;");

        const __half* Ab = smh + (t % 3) * ST_H;
        const __half* Bb = Ab + AT_H;
        #pragma unroll
        for (int ks = 0; ks < 4; ks++) {
            const int kb = ks * 16;
            uint32_t afr[4][4], bfr[8][2];
            #pragma unroll
            for (int mt = 0; mt < 4; mt++) {
                int rb = wm + mt * 16 + g;
                afr[mt][0] = *(const uint32_t*)&Ab[rb * HP + kb + 2 * tl];
                afr[mt][1] = *(const uint32_t*)&Ab[(rb + 8) * HP + kb + 2 * tl];
                afr[mt][2] = *(const uint32_t*)&Ab[rb * HP + kb + 8 + 2 * tl];
                afr[mt][3] = *(const uint32_t*)&Ab[(rb + 8) * HP + kb + 8 + 2 * tl];
            }
            #pragma unroll
            for (int nt = 0; nt < 8; nt++) {
                int cb = wn + nt * 8 + g;
                bfr[nt][0] = *(const uint32_t*)&Bb[cb * HP + kb + 2 * tl];
                bfr[nt][1] = *(const uint32_t*)&Bb[cb * HP + kb + 8 + 2 * tl];
            }
            #pragma unroll
            for (int mt = 0; mt < 4; mt++)
                #pragma unroll
                for (int nt = 0; nt < 8; nt++)
                    mma_f16(acc[mt][nt], afr[mt], bfr[nt]);
        }
    }

    #pragma unroll
    for (int mt = 0; mt < 4; mt++) {
        int r0 = m0 + wm + mt * 16 + g;
        #pragma unroll
        for (int nt = 0; nt < 8; nt++) {
            int cn = n0 + wn + nt * 8 + 2 * tl;
            if (cn < N) {
                float v0 = acc[mt][nt][0], v1 = acc[mt][nt][1];
                float v2 = acc[mt][nt][2], v3 = acc[mt][nt][3];
                if (mode == 2) {
                    __half* Ch = (__half*)C;
                    *(half2*)&Ch[(size_t)r0 * N + cn]       = __floats2half2_rn(v0, v1);
                    *(half2*)&Ch[(size_t)(r0 + 8) * N + cn] = __floats2half2_rn(v2, v3);
                } else {
                    float* Cf = (float*)C;
                    *(float2*)&Cf[(size_t)r0 * N + cn]       = make_float2(v0, v1);
                    *(float2*)&Cf[(size_t)(r0 + 8) * N + cn] = make_float2(v2, v3);
                }
            }
        }
    }
}

// ---------------- RMSNorm (fp32 in -> fp16 out) ----------------
__global__ __launch_bounds__(256) void rmsnorm_k(const float* __restrict__ X,
                                                 const float* __restrict__ w,
                                                 __half* __restrict__ Y,
                                                 int W, int ldx) {
    int row = blockIdx.x;
    const float* x = X + (size_t)row * ldx;
    float ss = 0.f;
    for (int i = threadIdx.x; i < W; i += 256) { float v = x[i]; ss += v * v; }
    __shared__ float red[256];
    red[threadIdx.x] = ss;
    __syncthreads();
    for (int s = 128; s > 0; s >>= 1) {
        if (threadIdx.x < s) red[threadIdx.x] += red[threadIdx.x + s];
        __syncthreads();
    }
    float inv = rsqrtf(red[0] / (float)W + 1e-6f);
    __half* y = Y + (size_t)row * W;
    for (int i = threadIdx.x; i < W; i += 256)
        y[i] = __float2half_rn(w[i] * (x[i] * inv));
}

// ---------------- YaRN RoPE (fp16 q in place; kpe fp32->fp16) ----------------
__global__ __launch_bounds__(544) void rope_k(const int* __restrict__ pos_ids) {
    int row = blockIdx.x;
    int t = threadIdx.x;
    int h = t >> 5, j = t & 31;
    float pos = (float)pos_ids[row];
    float fe = powf(10000.0f, -(float)j / 32.0f);
    float ramp = fminf(fmaxf(((float)j - 10.0f) / 13.0f, 0.f), 1.f);
    float invf = (fe / 40.0f) * ramp + fe * (1.0f - ramp);
    float ang = pos * invf;
    float s, c;
    sincosf(ang, &s, &c);
    if (h < NHEADS) {
        __half* base = g_q16 + (size_t)row * 3072 + h * QHD + NOPE;
        float x0 = __half2float(base[2 * j]), x1 = __half2float(base[2 * j + 1]);
        __syncwarp();
        base[j]      = __float2half_rn(x0 * c - x1 * s);
        base[32 + j] = __float2half_rn(x1 * c + x0 * s);
    } else {
        const float* src = g_qab + (size_t)row * 2112 + 2048;
        float x0 = src[2 * j], x1 = src[2 * j + 1];
        __half* dst = g_kpe16 + (size_t)row * 64;
        dst[j]      = __float2half_rn(x0 * c - x1 * s);
        dst[32 + j] = __float2half_rn(x1 * c + x0 * s);
    }
}

// ==================================================================
// Flash attention, fp16 tensor cores, cp.async double-buffered K/V.
// 128 threads / 4 warps, BM=64, BN=64, 2 CTAs/SM (smem 111.6 KB).
// QK^T and P·V via mma.m16n8k16.f16; V B-frags via ldmatrix.trans.
// P overlays current K buffer (barrier-separated).
// ==================================================================
#define QPH 200   // Q/K pitch in halves (word pitch 100 == 4 mod 32)
#define VPH 136   // V pitch in halves (272 B rows; ldmatrix rows hit all banks)
#define PPH 72    // P pitch in halves
#define KT_H (64*QPH)
#define VT_H (64*VPH)
#define FLASH_SMEM ((64*QPH + 2*KT_H + 2*VT_H) * 2)   // 111,616 B

__global__ __launch_bounds__(128, 2) void flash_f16(float scale) {
    extern __shared__ __half smf[];
    __half* Qs = smf;                    // [64][QPH]
    __half* Kb = smf + 64 * QPH;         // [2][64][QPH]  (P overlays current)
    __half* Vb = Kb + 2 * KT_H;          // [2][64][VPH]
    const int qb = blockIdx.x, h = blockIdx.y, b = blockIdx.z;
    const int tid = threadIdx.x;
    const int warp = tid >> 5, lane = tid & 31;
    const int g = lane >> 2, tl = lane & 3;
    const int wm = warp * 16;
    const size_t bs0 = (size_t)b * SEQ;

    const uint32_t qs_s = (uint32_t)__cvta_generic_to_shared(Qs);
    const uint32_t kb_s = (uint32_t)__cvta_generic_to_shared(Kb);
    const uint32_t vb_s = (uint32_t)__cvta_generic_to_shared(Vb);

    auto stageK = [&](int buf, int kb) {
        uint32_t base = kb_s + (uint32_t)(buf * KT_H * 2);
        #pragma unroll
        for (int u = 0; u < 12; u++) {
            int idx = tid + u * 128;
            int r = idx / 24, q8 = idx % 24;
            const __half* src = (q8 < 16)
                ? &g_kv16[(bs0 + kb * 64 + r) * 4096 + h * 256 + q8 * 8]
                : &g_kpe16[(bs0 + kb * 64 + r) * 64 + (q8 - 16) * 8];
            cp_async16(base + (r * QPH + q8 * 8) * 2, src, true);
        }
    };
    auto stageV = [&](int buf, int kb) {
        uint32_t base = vb_s + (uint32_t)(buf * VT_H * 2);
        #pragma unroll
        for (int u = 0; u < 8; u++) {
            int idx = tid + u * 128;
            int r = idx >> 4, c8 = (idx & 15) * 8;
            cp_async16(base + (r * VPH + c8) * 2,
                       &g_kv16[(bs0 + kb * 64 + r) * 4096 + h * 256 + NOPE + c8], true);
        }
    };

    #pragma unroll
    for (int u = 0; u < 12; u++) {
        int idx = tid + u * 128;
        int r = idx / 24, q8 = (idx % 24) * 8;
        cp_async16(qs_s + (r * QPH + q8) * 2,
                   &g_q16[(bs0 + qb * 64 + r) * 3072 + h * QHD + q8], true);
    }
    stageK(0, 0);
    stageV(0, 0);
    asm volatile("cp.async.commit_group;");

    float m_i[2] = {-1e30f, -1e30f};
    float l_i[2] = {0.f, 0.f};
    float acc_o[16][4];
    #pragma unroll
    for (int nt = 0; nt < 16; nt++)
        #pragma unroll
        for (int v = 0; v < 4; v++) acc_o[nt][v] = 0.f;

    const int row0 = qb * 64 + wm + g;
    // ldmatrix lane decomposition
    const int lq = lane >> 3, lrl = lane & 7;

    for (int kb = 0; kb <= qb; kb++) {
        const int cur = kb & 1;
        asm volatile("cp.async.wait_group 0;");
        __syncthreads();
        if (kb < qb) {
            stageK(cur ^ 1, kb + 1);
            stageV(cur ^ 1, kb + 1);
            asm volatile("cp.async.commit_group;");
        }
        const __half* Ks = Kb + cur * KT_H;
        const uint32_t vcur = vb_s + (uint32_t)(cur * VT_H * 2);
        __half* Ps = Kb + cur * KT_H;

        // ---- S = Q @ K^T (16x64 per warp), 12 k16-steps ----
        float acc_s[8][4];
        #pragma unroll
        for (int nt = 0; nt < 8; nt++)
            #pragma unroll
            for (int v = 0; v < 4; v++) acc_s[nt][v] = 0.f;

        #pragma unroll
        for (int ks = 0; ks < 12; ks++) {
            const int kbh = ks * 16;
            uint32_t afr[4];
            afr[0] = *(const uint32_t*)&Qs[(wm + g) * QPH + kbh + 2 * tl];
            afr[1] = *(const uint32_t*)&Qs[(wm + g + 8) * QPH + kbh + 2 * tl];
            afr[2] = *(const uint32_t*)&Qs[(wm + g) * QPH + kbh + 8 + 2 * tl];
            afr[3] = *(const uint32_t*)&Qs[(wm + g + 8) * QPH + kbh + 8 + 2 * tl];
            #pragma unroll
            for (int nt = 0; nt < 8; nt++) {
                uint32_t bfr[2];
                bfr[0] = *(const uint32_t*)&Ks[(nt * 8 + g) * QPH + kbh + 2 * tl];
                bfr[1] = *(const uint32_t*)&Ks[(nt * 8 + g) * QPH + kbh + 8 + 2 * tl];
                mma_f16(acc_s[nt], afr, bfr);
            }
        }

        // ---- online softmax ----
        const bool diag = (kb == qb);
        float rmax0 = -1e30f, rmax1 = -1e30f;
        #pragma unroll
        for (int nt = 0; nt < 8; nt++) {
            int c0 = kb * 64 + nt * 8 + 2 * tl, c1 = c0 + 1;
            float s0 = acc_s[nt][0] * scale, s1 = acc_s[nt][1] * scale;
            float s2 = acc_s[nt][2] * scale, s3 = acc_s[nt][3] * scale;
            if (diag) {
                if (c0 > row0) s0 = -1e30f;
                if (c1 > row0) s1 = -1e30f;
                if (c0 > row0 + 8) s2 = -1e30f;
                if (c1 > row0 + 8) s3 = -1e30f;
            }
            acc_s[nt][0] = s0; acc_s[nt][1] = s1;
            acc_s[nt][2] = s2; acc_s[nt][3] = s3;
            rmax0 = fmaxf(rmax0, fmaxf(s0, s1));
            rmax1 = fmaxf(rmax1, fmaxf(s2, s3));
        }
        #pragma unroll
        for (int off = 1; off <= 2; off <<= 1) {
            rmax0 = fmaxf(rmax0, __shfl_xor_sync(0xffffffffu, rmax0, off));
            rmax1 = fmaxf(rmax1, __shfl_xor_sync(0xffffffffu, rmax1, off));
        }
        float mn0 = fmaxf(m_i[0], rmax0), mn1 = fmaxf(m_i[1], rmax1);
        float al0 = __expf(m_i[0] - mn0), al1 = __expf(m_i[1] - mn1);
        float p_r[8][4];
        float rs0 = 0.f, rs1 = 0.f;
        #pragma unroll
        for (int nt = 0; nt < 8; nt++) {
            p_r[nt][0] = __expf(acc_s[nt][0] - mn0);
            p_r[nt][1] = __expf(acc_s[nt][1] - mn0);
            p_r[nt][2] = __expf(acc_s[nt][2] - mn1);
            p_r[nt][3] = __expf(acc_s[nt][3] - mn1);
            rs0 += p_r[nt][0] + p_r[nt][1];
            rs1 += p_r[nt][2] + p_r[nt][3];
        }
        #pragma unroll
        for (int off = 1; off <= 2; off <<= 1) {
            rs0 += __shfl_xor_sync(0xffffffffu, rs0, off);
            rs1 += __shfl_xor_sync(0xffffffffu, rs1, off);
        }
        l_i[0] = l_i[0] * al0 + rs0;
        l_i[1] = l_i[1] * al1 + rs1;
        m_i[0] = mn0; m_i[1] = mn1;
        #pragma unroll
        for (int nt = 0; nt < 16; nt++) {
            acc_o[nt][0] *= al0; acc_o[nt][1] *= al0;
            acc_o[nt][2] *= al1; acc_o[nt][3] *= al1;
        }

        __syncthreads();   // ALL warps done reading K before P overlays it
        #pragma unroll
        for (int nt = 0; nt < 8; nt++) {
            *(half2*)&Ps[(wm + g) * PPH + nt * 8 + 2 * tl] =
                __floats2half2_rn(p_r[nt][0], p_r[nt][1]);
            *(half2*)&Ps[(wm + g + 8) * PPH + nt * 8 + 2 * tl] =
                __floats2half2_rn(p_r[nt][2], p_r[nt][3]);
        }
        __syncwarp();      // warp-private rows

        // ---- O += P @ V (16x128 per warp), 4 k16-steps ----
        #pragma unroll
        for (int ks = 0; ks < 4; ks++) {
            const int kbh = ks * 16;
            uint32_t afr[4];
            afr[0] = *(const uint32_t*)&Ps[(wm + g) * PPH + kbh + 2 * tl];
            afr[1] = *(const uint32_t*)&Ps[(wm + g + 8) * PPH + kbh + 2 * tl];
            afr[2] = *(const uint32_t*)&Ps[(wm + g) * PPH + kbh + 8 + 2 * tl];
            afr[3] = *(const uint32_t*)&Ps[(wm + g + 8) * PPH + kbh + 8 + 2 * tl];
            #pragma unroll
            for (int p = 0; p < 8; p++) {
                // ldmatrix x4 trans: 4 8x8 tiles of V -> B frags for 2 n-tiles
                uint32_t maddr = vcur +
                    (uint32_t)(((kbh + (lq & 1) * 8 + lrl) * VPH +
                                (p * 2 + (lq >> 1)) * 8) * 2);
                uint32_t b0, b1, b2, b3;
                asm volatile(
                    "ldmatrix.sync.aligned.m8n8.x4.trans.shared.b16 "
                    "{%0,%1,%2,%3}, [%4];"
                    : "=r"(b0), "=r"(b1), "=r"(b2), "=r"(b3) : "r"(maddr));
                uint32_t bfr0[2] = {b0, b1};
                uint32_t bfr1[2] = {b2, b3};
                mma_f16(acc_o[2 * p],     afr, bfr0);
                mma_f16(acc_o[2 * p + 1], afr, bfr1);
            }
        }
    }

    // ---- epilogue: normalize + fp16 attn (wo GEMM input) ----
    float inv0 = 1.0f / l_i[0], inv1 = 1.0f / l_i[1];
    size_t r0 = (bs0 + qb * 64 + wm + g) * 2048 + h * VHD;
    size_t r1 = r0 + 8 * 2048;
    #pragma unroll
    for (int nt = 0; nt < 16; nt++) {
        int cn = nt * 8 + 2 * tl;
        *(half2*)&g_attn16[r0 + cn] =
            __floats2half2_rn(acc_o[nt][0] * inv0, acc_o[nt][1] * inv0);
        *(half2*)&g_attn16[r1 + cn] =
            __floats2half2_rn(acc_o[nt][2] * inv1, acc_o[nt][3] * inv1);
    }
}

// ---------------- launch ----------------
extern "C" void kernel_launch(void* const* d_in, const int* in_sizes, int n_in,
                              void* d_out, int out_size) {
    const float* hs      = (const float*)d_in[0];
    const int*   pos     = (const int*)  d_in[1];
    const float* wq_a    = (const float*)d_in[2];
    const float* q_a_ln  = (const float*)d_in[3];
    const float* wq_b    = (const float*)d_in[4];
    const float* wkv_a   = (const float*)d_in[5];
    const float* kv_a_ln = (const float*)d_in[6];
    const float* wkv_b   = (const float*)d_in[7];
    const float* wo      = (const float*)d_in[8];
    float* out = (float*)d_out;

    float *qab;
    __half *hs16, *wab16, *wqb16, *wkvb16, *wo16, *qlo16, *cn16, *q16, *kv16, *at16;
    cudaGetSymbolAddress((void**)&qab, g_qab);
    cudaGetSymbolAddress((void**)&hs16,  g_hs16);
    cudaGetSymbolAddress((void**)&wab16, g_wab16);
    cudaGetSymbolAddress((void**)&wqb16, g_wqb16);
    cudaGetSymbolAddress((void**)&wkvb16,g_wkvb16);
    cudaGetSymbolAddress((void**)&wo16,  g_wo16);
    cudaGetSymbolAddress((void**)&qlo16, g_qlora16);
    cudaGetSymbolAddress((void**)&cn16,  g_cnorm16);
    cudaGetSymbolAddress((void**)&q16,   g_q16);
    cudaGetSymbolAddress((void**)&kv16,  g_kv16);
    cudaGetSymbolAddress((void**)&at16,  g_attn16);

    double m = 0.1 * log(40.0) + 1.0;
    float scale = (float)((1.0 / sqrt(192.0)) * m * m);

    cudaFuncSetAttribute(flash_f16, cudaFuncAttributeMaxDynamicSharedMemorySize,
                         FLASH_SMEM);
    cudaFuncSetAttribute(gemm_f16, cudaFuncAttributeMaxDynamicSharedMemorySize,
                         GEMM_SMEM);

    auto cvtn = [&](const float* x, __half* y, size_t n) {
        cvt_f16_k<<<(int)((n / 4 + 255) / 256), 256>>>(x, y, (int)n);
    };
    cvtn(hs,    hs16,   (size_t)ROWS * 2048);
    cvtn(wq_a,  wab16,               (size_t)1536 * 2048);
    cvtn(wkv_a, wab16 + (size_t)1536 * 2048, (size_t)576 * 2048);
    cvtn(wq_b,  wqb16,  (size_t)3072 * 1536);
    cvtn(wkv_b, wkvb16, (size_t)4096 * 512);

    dim3 blk(256);
    // combined: [qlora | ckv | kpe] = hs @ [wq_a ; wkv_a]^T   (N=2112, fp32 out)
    gemm_f16<<<dim3((2112 + 127) / 128, ROWS / 256), blk, GEMM_SMEM>>>(
        hs16, wab16, qab, ROWS, 2112, 2048, 0);
    cvtn(wo, wo16, (size_t)2048 * 2048);
    rmsnorm_k<<<ROWS, 256>>>(qab,        q_a_ln,  qlo16, 1536, 2112);
    rmsnorm_k<<<ROWS, 256>>>(qab + 1536, kv_a_ln, cn16,  512,  2112);
    // q = qlora_n @ wq_b^T   (fp16 out)
    gemm_f16<<<dim3(3072 / 128, ROWS / 256), blk, GEMM_SMEM>>>(
        qlo16, wqb16, q16, ROWS, 3072, 1536, 2);
    // kv = cnorm @ wkv_b^T   (fp16 out)
    gemm_f16<<<dim3(4096 / 128, ROWS / 256), blk, GEMM_SMEM>>>(
        cn16, wkvb16, kv16, ROWS, 4096, 512, 2);
    rope_k<<<ROWS, 544>>>(pos);
    flash_f16<<<dim3(SEQ / 64, NHEADS, BATCH), 128, FLASH_SMEM>>>(scale);
    // out = attn @ wo^T   (fp32 out)
    gemm_f16<<<dim3(2048 / 128, ROWS / 256), blk, GEMM_SMEM>>>(
        at16, wo16, out, ROWS, 2048, 2048, 0);
}

// round 13
// speedup vs baseline: 10.2202x; 1.0471x over previous
#include <cuda_runtime.h>
#include <cuda_fp16.h>
#include <math.h>
#include <stdint.h>

#define SEQ 2048
#define BATCH 2
#define ROWS (BATCH*SEQ)   // 4096
#define NHEADS 16
#define QHD 192
#define NOPE 128
#define VHD 128

// ---------------- scratch (device globals; no allocation allowed) ----------------
__device__ float g_qab [(size_t)ROWS*2112];    // [qlora(1536) | ckv(512) | kpe(64)] fp32
__device__ __half g_hs16 [(size_t)ROWS*2048];
__device__ __half g_wab16[(size_t)2112*2048];
__device__ __half g_wqb16[(size_t)3072*1536];
__device__ __half g_wkvb16[(size_t)4096*512];
__device__ __half g_wo16 [(size_t)2048*2048];
__device__ __half g_qlora16[(size_t)ROWS*1536];
__device__ __half g_cnorm16[(size_t)ROWS*512];
__device__ __half g_q16 [(size_t)ROWS*3072];
__device__ __half g_kv16[(size_t)ROWS*4096];
__device__ __half g_kpe16[(size_t)ROWS*64];
__device__ __half g_attn16[(size_t)ROWS*2048];

__device__ __forceinline__ void mma_f16(float d[4], const uint32_t a[4],
                                        const uint32_t b[2]) {
    asm volatile(
        "mma.sync.aligned.m16n8k16.row.col.f32.f16.f16.f32 "
        "{%0,%1,%2,%3}, {%4,%5,%6,%7}, {%8,%9}, {%0,%1,%2,%3};"
        : "+f"(d[0]), "+f"(d[1]), "+f"(d[2]), "+f"(d[3])
        : "r"(a[0]), "r"(a[1]), "r"(a[2]), "r"(a[3]), "r"(b[0]), "r"(b[1]));
}

__device__ __forceinline__ void cp_async16(uint32_t saddr, const void* gptr, bool pred) {
    int sz = pred ? 16 : 0;
    asm volatile("cp.async.cg.shared.global [%0], [%1], 16, %2;\n"
                 :: "r"(saddr), "l"(gptr), "r"(sz));
}

// ---------------- single merged fp32->fp16 conversion over all 6 buffers ----------------
#define CVT_E0 ((size_t)ROWS*2048)                    //  8,388,608  hs
#define CVT_E1 (CVT_E0 + (size_t)1536*2048)           // 11,534,336  wq_a
#define CVT_E2 (CVT_E1 + (size_t)576*2048)            // 12,713,984  wkv_a
#define CVT_E3 (CVT_E2 + (size_t)3072*1536)           // 17,432,576  wq_b
#define CVT_E4 (CVT_E3 + (size_t)4096*512)            // 19,529,728  wkv_b
#define CVT_E5 (CVT_E4 + (size_t)2048*2048)           // 23,724,032  wo
#define CVT_BLOCKS ((int)(CVT_E5 / 4 / 256))          // 23168 exact

__global__ __launch_bounds__(256) void cvt_all_k(const float* __restrict__ hs,
                                                 const float* __restrict__ wqa,
                                                 const float* __restrict__ wkva,
                                                 const float* __restrict__ wqb,
                                                 const float* __restrict__ wkvb,
                                                 const float* __restrict__ wo) {
    size_t i = ((size_t)blockIdx.x * 256 + threadIdx.x) * 4;
    const float* src; __half* dst; size_t off;
    if (i < CVT_E0)      { src = hs;   dst = g_hs16;   off = i; }
    else if (i < CVT_E1) { src = wqa;  dst = g_wab16;  off = i - CVT_E0; }
    else if (i < CVT_E2) { src = wkva; dst = g_wab16 + (size_t)1536*2048; off = i - CVT_E1; }
    else if (i < CVT_E3) { src = wqb;  dst = g_wqb16;  off = i - CVT_E2; }
    else if (i < CVT_E4) { src = wkvb; dst = g_wkvb16; off = i - CVT_E3; }
    else                 { src = wo;   dst = g_wo16;   off = i - CVT_E4; }
    float4 v = *(const float4*)(src + off);
    half2* y2 = (half2*)(dst + off);
    y2[0] = __floats2half2_rn(v.x, v.y);
    y2[1] = __floats2half2_rn(v.z, v.w);
}

// ==================================================================
// FP16 dual-GEMM: up to two independent C = A @ B^T in ONE launch.
// Flat x-index: blocks [0,nx0) -> GEMM 0, rest -> GEMM 1 (merged
// tails; heavy-K GEMM first = LPT). M=4096 for all. mode: 0=fp32
// out, 2=fp16 out. 256x128 tile, BK=64, 3-stage cp.async, 8 warps.
// ==================================================================
#define HP 72
#define AT_H (256*HP)
#define BT_H (128*HP)
#define ST_H (AT_H + BT_H)
#define GEMM_SMEM (3*ST_H*2)   // 165,888 B

__global__ __launch_bounds__(256, 1) void gemm_dual(
    const __half* __restrict__ A0, const __half* __restrict__ B0,
    void* __restrict__ C0, int N0, int K0, int mode0, int nx0,
    const __half* __restrict__ A1, const __half* __restrict__ B1,
    void* __restrict__ C1, int N1, int K1, int mode1)
{
    extern __shared__ __half smh[];
    const int tid = threadIdx.x;
    const int warp = tid >> 5, lane = tid & 31;
    const int wm = (warp & 3) * 64, wn = (warp >> 2) * 64;
    const int g = lane >> 2, tl = lane & 3;

    const bool second = ((int)blockIdx.x >= nx0);
    const __half* A = second ? A1 : A0;
    const __half* B = second ? B1 : B0;
    void* C   = second ? C1 : C0;
    const int N    = second ? N1 : N0;
    const int K    = second ? K1 : K0;
    const int mode = second ? mode1 : mode0;
    const int m0 = blockIdx.y * 256;
    const int n0 = (second ? (int)blockIdx.x - nx0 : (int)blockIdx.x) * 128;

    float acc[4][8][4];
    #pragma unroll
    for (int i = 0; i < 4; i++)
        #pragma unroll
        for (int j = 0; j < 8; j++)
            #pragma unroll
            for (int v = 0; v < 4; v++) acc[i][j][v] = 0.f;

    const int T = K / 64;

    auto issue = [&](int stage, int t) {
        const int k0 = t * 64;
        uint32_t ab = (uint32_t)__cvta_generic_to_shared(smh + stage * ST_H);
        uint32_t bb = ab + AT_H * 2;
        #pragma unroll
        for (int u = 0; u < 8; u++) {
            int seg = tid + u * 256;
            int row = seg >> 3, gq = (seg & 7) * 8;
            cp_async16(ab + (row * HP + gq) * 2,
                       A + (size_t)(m0 + row) * K + k0 + gq, true);
        }
        #pragma unroll
        for (int u = 0; u < 4; u++) {
            int seg = tid + u * 256;
            int row = seg >> 3, gq = (seg & 7) * 8;
            int nr = n0 + row;
            cp_async16(bb + (row * HP + gq) * 2,
                       B + (size_t)(nr < N ? nr : 0) * K + k0 + gq, nr < N);
        }
        asm volatile("cp.async.commit_group;");
    };

    issue(0, 0);
    if (T > 1) issue(1, 1); else asm volatile("cp.async.commit_group;");

    for (int t = 0; t < T; t++) {
        asm volatile("cp.async.wait_group 1;");
        __syncthreads();
        if (t + 2 < T) issue((t + 2) % 3, t + 2);
        else asm volatile("cp.async.commit_group;");

        const __half* Ab = smh + (t % 3) * ST_H;
        const __half* Bb = Ab + AT_H;
        #pragma unroll
        for (int ks = 0; ks < 4; ks++) {
            const int kb = ks * 16;
            uint32_t afr[4][4], bfr[8][2];
            #pragma unroll
            for (int mt = 0; mt < 4; mt++) {
                int rb = wm + mt * 16 + g;
                afr[mt][0] = *(const uint32_t*)&Ab[rb * HP + kb + 2 * tl];
                afr[mt][1] = *(const uint32_t*)&Ab[(rb + 8) * HP + kb + 2 * tl];
                afr[mt][2] = *(const uint32_t*)&Ab[rb * HP + kb + 8 + 2 * tl];
                afr[mt][3] = *(const uint32_t*)&Ab[(rb + 8) * HP + kb + 8 + 2 * tl];
            }
            #pragma unroll
            for (int nt = 0; nt < 8; nt++) {
                int cb = wn + nt * 8 + g;
                bfr[nt][0] = *(const uint32_t*)&Bb[cb * HP + kb + 2 * tl];
                bfr[nt][1] = *(const uint32_t*)&Bb[cb * HP + kb + 8 + 2 * tl];
            }
            #pragma unroll
            for (int mt = 0; mt < 4; mt++)
                #pragma unroll
                for (int nt = 0; nt < 8; nt++)
                    mma_f16(acc[mt][nt], afr[mt], bfr[nt]);
        }
    }

    #pragma unroll
    for (int mt = 0; mt < 4; mt++) {
        int r0 = m0 + wm + mt * 16 + g;
        #pragma unroll
        for (int nt = 0; nt < 8; nt++) {
            int cn = n0 + wn + nt * 8 + 2 * tl;
            if (cn < N) {
                float v0 = acc[mt][nt][0], v1 = acc[mt][nt][1];
                float v2 = acc[mt][nt][2], v3 = acc[mt][nt][3];
                if (mode == 2) {
                    __half* Ch = (__half*)C;
                    *(half2*)&Ch[(size_t)r0 * N + cn]       = __floats2half2_rn(v0, v1);
                    *(half2*)&Ch[(size_t)(r0 + 8) * N + cn] = __floats2half2_rn(v2, v3);
                } else {
                    float* Cf = (float*)C;
                    *(float2*)&Cf[(size_t)r0 * N + cn]       = make_float2(v0, v1);
                    *(float2*)&Cf[(size_t)(r0 + 8) * N + cn] = make_float2(v2, v3);
                }
            }
        }
    }
}

// ---------------- merged RMSNorm: y=0 -> qlora(1536), y=1 -> ckv(512) ----------------
__global__ __launch_bounds__(256) void rmsnorm2_k(const float* __restrict__ qab,
                                                  const float* __restrict__ w0,
                                                  const float* __restrict__ w1) {
    int row = blockIdx.x;
    int which = blockIdx.y;
    const float* x = qab + (size_t)row * 2112 + (which ? 1536 : 0);
    const float* w = which ? w1 : w0;
    int W = which ? 512 : 1536;
    __half* Y = which ? (g_cnorm16 + (size_t)row * 512)
                      : (g_qlora16 + (size_t)row * 1536);
    float ss = 0.f;
    for (int i = threadIdx.x; i < W; i += 256) { float v = x[i]; ss += v * v; }
    __shared__ float red[256];
    red[threadIdx.x] = ss;
    __syncthreads();
    for (int s = 128; s > 0; s >>= 1) {
        if (threadIdx.x < s) red[threadIdx.x] += red[threadIdx.x + s];
        __syncthreads();
    }
    float inv = rsqrtf(red[0] / (float)W + 1e-6f);
    for (int i = threadIdx.x; i < W; i += 256)
        Y[i] = __float2half_rn(w[i] * (x[i] * inv));
}

// ---------------- YaRN RoPE (fp16 q in place; kpe fp32->fp16) ----------------
__global__ __launch_bounds__(544) void rope_k(const int* __restrict__ pos_ids) {
    int row = blockIdx.x;
    int t = threadIdx.x;
    int h = t >> 5, j = t & 31;
    float pos = (float)pos_ids[row];
    float fe = powf(10000.0f, -(float)j / 32.0f);
    float ramp = fminf(fmaxf(((float)j - 10.0f) / 13.0f, 0.f), 1.f);
    float invf = (fe / 40.0f) * ramp + fe * (1.0f - ramp);
    float ang = pos * invf;
    float s, c;
    sincosf(ang, &s, &c);
    if (h < NHEADS) {
        __half* base = g_q16 + (size_t)row * 3072 + h * QHD + NOPE;
        float x0 = __half2float(base[2 * j]), x1 = __half2float(base[2 * j + 1]);
        __syncwarp();
        base[j]      = __float2half_rn(x0 * c - x1 * s);
        base[32 + j] = __float2half_rn(x1 * c + x0 * s);
    } else {
        const float* src = g_qab + (size_t)row * 2112 + 2048;
        float x0 = src[2 * j], x1 = src[2 * j + 1];
        __half* dst = g_kpe16 + (size_t)row * 64;
        dst[j]      = __float2half_rn(x0 * c - x1 * s);
        dst[32 + j] = __float2half_rn(x1 * c + x0 * s);
    }
}

// ==================================================================
// Flash attention, fp16 tensor cores, cp.async double-buffered K/V.
// LPT: heaviest q-tiles (largest qb) scheduled first via x-reversal.
// ==================================================================
#define QPH 200
#define VPH 136
#define PPH 72
#define KT_H (64*QPH)
#define VT_H (64*VPH)
#define FLASH_SMEM ((64*QPH + 2*KT_H + 2*VT_H) * 2)   // 111,616 B

__global__ __launch_bounds__(128, 2) void flash_f16(float scale) {
    extern __shared__ __half smf[];
    __half* Qs = smf;
    __half* Kb = smf + 64 * QPH;
    __half* Vb = Kb + 2 * KT_H;
    const int qb = gridDim.x - 1 - blockIdx.x;   // LPT: heavy first
    const int h = blockIdx.y, b = blockIdx.z;
    const int tid = threadIdx.x;
    const int warp = tid >> 5, lane = tid & 31;
    const int g = lane >> 2, tl = lane & 3;
    const int wm = warp * 16;
    const size_t bs0 = (size_t)b * SEQ;

    const uint32_t qs_s = (uint32_t)__cvta_generic_to_shared(Qs);
    const uint32_t kb_s = (uint32_t)__cvta_generic_to_shared(Kb);
    const uint32_t vb_s = (uint32_t)__cvta_generic_to_shared(Vb);

    auto stageK = [&](int buf, int kb) {
        uint32_t base = kb_s + (uint32_t)(buf * KT_H * 2);
        #pragma unroll
        for (int u = 0; u < 12; u++) {
            int idx = tid + u * 128;
            int r = idx / 24, q8 = idx % 24;
            const __half* src = (q8 < 16)
                ? &g_kv16[(bs0 + kb * 64 + r) * 4096 + h * 256 + q8 * 8]
                : &g_kpe16[(bs0 + kb * 64 + r) * 64 + (q8 - 16) * 8];
            cp_async16(base + (r * QPH + q8 * 8) * 2, src, true);
        }
    };
    auto stageV = [&](int buf, int kb) {
        uint32_t base = vb_s + (uint32_t)(buf * VT_H * 2);
        #pragma unroll
        for (int u = 0; u < 8; u++) {
            int idx = tid + u * 128;
            int r = idx >> 4, c8 = (idx & 15) * 8;
            cp_async16(base + (r * VPH + c8) * 2,
                       &g_kv16[(bs0 + kb * 64 + r) * 4096 + h * 256 + NOPE + c8], true);
        }
    };

    #pragma unroll
    for (int u = 0; u < 12; u++) {
        int idx = tid + u * 128;
        int r = idx / 24, q8 = (idx % 24) * 8;
        cp_async16(qs_s + (r * QPH + q8) * 2,
                   &g_q16[(bs0 + qb * 64 + r) * 3072 + h * QHD + q8], true);
    }
    stageK(0, 0);
    stageV(0, 0);
    asm volatile("cp.async.commit_group;");

    float m_i[2] = {-1e30f, -1e30f};
    float l_i[2] = {0.f, 0.f};
    float acc_o[16][4];
    #pragma unroll
    for (int nt = 0; nt < 16; nt++)
        #pragma unroll
        for (int v = 0; v < 4; v++) acc_o[nt][v] = 0.f;

    const int row0 = qb * 64 + wm + g;
    const int lq = lane >> 3, lrl = lane & 7;

    for (int kb = 0; kb <= qb; kb++) {
        const int cur = kb & 1;
        asm volatile("cp.async.wait_group 0;");
        __syncthreads();
        if (kb < qb) {
            stageK(cur ^ 1, kb + 1);
            stageV(cur ^ 1, kb + 1);
            asm volatile("cp.async.commit_group;");
        }
        const __half* Ks = Kb + cur * KT_H;
        const uint32_t vcur = vb_s + (uint32_t)(cur * VT_H * 2);
        __half* Ps = Kb + cur * KT_H;

        float acc_s[8][4];
        #pragma unroll
        for (int nt = 0; nt < 8; nt++)
            #pragma unroll
            for (int v = 0; v < 4; v++) acc_s[nt][v] = 0.f;

        #pragma unroll
        for (int ks = 0; ks < 12; ks++) {
            const int kbh = ks * 16;
            uint32_t afr[4];
            afr[0] = *(const uint32_t*)&Qs[(wm + g) * QPH + kbh + 2 * tl];
            afr[1] = *(const uint32_t*)&Qs[(wm + g + 8) * QPH + kbh + 2 * tl];
            afr[2] = *(const uint32_t*)&Qs[(wm + g) * QPH + kbh + 8 + 2 * tl];
            afr[3] = *(const uint32_t*)&Qs[(wm + g + 8) * QPH + kbh + 8 + 2 * tl];
            #pragma unroll
            for (int nt = 0; nt < 8; nt++) {
                uint32_t bfr[2];
                bfr[0] = *(const uint32_t*)&Ks[(nt * 8 + g) * QPH + kbh + 2 * tl];
                bfr[1] = *(const uint32_t*)&Ks[(nt * 8 + g) * QPH + kbh + 8 + 2 * tl];
                mma_f16(acc_s[nt], afr, bfr);
            }
        }

        const bool diag = (kb == qb);
        float rmax0 = -1e30f, rmax1 = -1e30f;
        #pragma unroll
        for (int nt = 0; nt < 8; nt++) {
            int c0 = kb * 64 + nt * 8 + 2 * tl, c1 = c0 + 1;
            float s0 = acc_s[nt][0] * scale, s1 = acc_s[nt][1] * scale;
            float s2 = acc_s[nt][2] * scale, s3 = acc_s[nt][3] * scale;
            if (diag) {
                if (c0 > row0) s0 = -1e30f;
                if (c1 > row0) s1 = -1e30f;
                if (c0 > row0 + 8) s2 = -1e30f;
                if (c1 > row0 + 8) s3 = -1e30f;
            }
            acc_s[nt][0] = s0; acc_s[nt][1] = s1;
            acc_s[nt][2] = s2; acc_s[nt][3] = s3;
            rmax0 = fmaxf(rmax0, fmaxf(s0, s1));
            rmax1 = fmaxf(rmax1, fmaxf(s2, s3));
        }
        #pragma unroll
        for (int off = 1; off <= 2; off <<= 1) {
            rmax0 = fmaxf(rmax0, __shfl_xor_sync(0xffffffffu, rmax0, off));
            rmax1 = fmaxf(rmax1, __shfl_xor_sync(0xffffffffu, rmax1, off));
        }
        float mn0 = fmaxf(m_i[0], rmax0), mn1 = fmaxf(m_i[1], rmax1);
        float al0 = __expf(m_i[0] - mn0), al1 = __expf(m_i[1] - mn1);
        float p_r[8][4];
        float rs0 = 0.f, rs1 = 0.f;
        #pragma unroll
        for (int nt = 0; nt < 8; nt++) {
            p_r[nt][0] = __expf(acc_s[nt][0] - mn0);
            p_r[nt][1] = __expf(acc_s[nt][1] - mn0);
            p_r[nt][2] = __expf(acc_s[nt][2] - mn1);
            p_r[nt][3] = __expf(acc_s[nt][3] - mn1);
            rs0 += p_r[nt][0] + p_r[nt][1];
            rs1 += p_r[nt][2] + p_r[nt][3];
        }
        #pragma unroll
        for (int off = 1; off <= 2; off <<= 1) {
            rs0 += __shfl_xor_sync(0xffffffffu, rs0, off);
            rs1 += __shfl_xor_sync(0xffffffffu, rs1, off);
        }
        l_i[0] = l_i[0] * al0 + rs0;
        l_i[1] = l_i[1] * al1 + rs1;
        m_i[0] = mn0; m_i[1] = mn1;
        #pragma unroll
        for (int nt = 0; nt < 16; nt++) {
            acc_o[nt][0] *= al0; acc_o[nt][1] *= al0;
            acc_o[nt][2] *= al1; acc_o[nt][3] *= al1;
        }

        __syncthreads();
        #pragma unroll
        for (int nt = 0; nt < 8; nt++) {
            *(half2*)&Ps[(wm + g) * PPH + nt * 8 + 2 * tl] =
                __floats2half2_rn(p_r[nt][0], p_r[nt][1]);
            *(half2*)&Ps[(wm + g + 8) * PPH + nt * 8 + 2 * tl] =
                __floats2half2_rn(p_r[nt][2], p_r[nt][3]);
        }
        __syncwarp();

        #pragma unroll
        for (int ks = 0; ks < 4; ks++) {
            const int kbh = ks * 16;
            uint32_t afr[4];
            afr[0] = *(const uint32_t*)&Ps[(wm + g) * PPH + kbh + 2 * tl];
            afr[1] = *(const uint32_t*)&Ps[(wm + g + 8) * PPH + kbh + 2 * tl];
            afr[2] = *(const uint32_t*)&Ps[(wm + g) * PPH + kbh + 8 + 2 * tl];
            afr[3] = *(const uint32_t*)&Ps[(wm + g + 8) * PPH + kbh + 8 + 2 * tl];
            #pragma unroll
            for (int p = 0; p < 8; p++) {
                uint32_t maddr = vcur +
                    (uint32_t)(((kbh + (lq & 1) * 8 + lrl) * VPH +
                                (p * 2 + (lq >> 1)) * 8) * 2);
                uint32_t b0, b1, b2, b3;
                asm volatile(
                    "ldmatrix.sync.aligned.m8n8.x4.trans.shared.b16 "
                    "{%0,%1,%2,%3}, [%4];"
                    : "=r"(b0), "=r"(b1), "=r"(b2), "=r"(b3) : "r"(maddr));
                uint32_t bfr0[2] = {b0, b1};
                uint32_t bfr1[2] = {b2, b3};
                mma_f16(acc_o[2 * p],     afr, bfr0);
                mma_f16(acc_o[2 * p + 1], afr, bfr1);
            }
        }
    }

    float inv0 = 1.0f / l_i[0], inv1 = 1.0f / l_i[1];
    size_t r0 = (bs0 + qb * 64 + wm + g) * 2048 + h * VHD;
    size_t r1 = r0 + 8 * 2048;
    #pragma unroll
    for (int nt = 0; nt < 16; nt++) {
        int cn = nt * 8 + 2 * tl;
        *(half2*)&g_attn16[r0 + cn] =
            __floats2half2_rn(acc_o[nt][0] * inv0, acc_o[nt][1] * inv0);
        *(half2*)&g_attn16[r1 + cn] =
            __floats2half2_rn(acc_o[nt][2] * inv1, acc_o[nt][3] * inv1);
    }
}

// ---------------- launch ----------------
extern "C" void kernel_launch(void* const* d_in, const int* in_sizes, int n_in,
                              void* d_out, int out_size) {
    const float* hs      = (const float*)d_in[0];
    const int*   pos     = (const int*)  d_in[1];
    const float* wq_a    = (const float*)d_in[2];
    const float* q_a_ln  = (const float*)d_in[3];
    const float* wq_b    = (const float*)d_in[4];
    const float* wkv_a   = (const float*)d_in[5];
    const float* kv_a_ln = (const float*)d_in[6];
    const float* wkv_b   = (const float*)d_in[7];
    const float* wo      = (const float*)d_in[8];
    float* out = (float*)d_out;

    float *qab;
    __half *hs16, *wab16, *wqb16, *wkvb16, *wo16, *qlo16, *cn16, *q16, *kv16, *at16;
    cudaGetSymbolAddress((void**)&qab, g_qab);
    cudaGetSymbolAddress((void**)&hs16,  g_hs16);
    cudaGetSymbolAddress((void**)&wab16, g_wab16);
    cudaGetSymbolAddress((void**)&wqb16, g_wqb16);
    cudaGetSymbolAddress((void**)&wkvb16,g_wkvb16);
    cudaGetSymbolAddress((void**)&wo16,  g_wo16);
    cudaGetSymbolAddress((void**)&qlo16, g_qlora16);
    cudaGetSymbolAddress((void**)&cn16,  g_cnorm16);
    cudaGetSymbolAddress((void**)&q16,   g_q16);
    cudaGetSymbolAddress((void**)&kv16,  g_kv16);
    cudaGetSymbolAddress((void**)&at16,  g_attn16);

    double m = 0.1 * log(40.0) + 1.0;
    float scale = (float)((1.0 / sqrt(192.0)) * m * m);

    cudaFuncSetAttribute(flash_f16, cudaFuncAttributeMaxDynamicSharedMemorySize,
                         FLASH_SMEM);
    cudaFuncSetAttribute(gemm_dual, cudaFuncAttributeMaxDynamicSharedMemorySize,
                         GEMM_SMEM);

    // [0] all fp32->fp16 conversions in one launch
    cvt_all_k<<<CVT_BLOCKS, 256>>>(hs, wq_a, wkv_a, wq_b, wkv_b, wo);

    dim3 blk(256);
    // [1] combined: [qlora | ckv | kpe] = hs @ [wq_a ; wkv_a]^T   (N=2112, fp32 out)
    gemm_dual<<<dim3(17, 16), blk, GEMM_SMEM>>>(
        hs16, wab16, qab, 2112, 2048, 0, 17,
        hs16, wab16, qab, 2112, 2048, 0);
    // [2] both rmsnorms in one launch
    rmsnorm2_k<<<dim3(ROWS, 2), 256>>>(qab, q_a_ln, kv_a_ln);
    // [3] q-GEMM (24 x-tiles, K=1536) + kv-GEMM (32 x-tiles, K=512) merged
    gemm_dual<<<dim3(24 + 32, 16), blk, GEMM_SMEM>>>(
        qlo16, wqb16, q16, 3072, 1536, 2, 24,
        cn16, wkvb16, kv16, 4096, 512, 2);
    // [4] rope (q_pe in place; k_pe -> fp16)
    rope_k<<<ROWS, 544>>>(pos);
    // [5] flash attention (LPT order)
    flash_f16<<<dim3(SEQ / 64, NHEADS, BATCH), 128, FLASH_SMEM>>>(scale);
    // [6] out = attn @ wo^T (fp32 out)
    gemm_dual<<<dim3(16, 16), blk, GEMM_SMEM>>>(
        at16, wo16, out, 2048, 2048, 0, 16,
        at16, wo16, out, 2048, 2048, 0);
}